// round 1
// baseline (speedup 1.0000x reference)
#include <cuda_runtime.h>
#include <math.h>

#define PP 3136
#define CC 256
#define BB 2
#define WX 56
#define EPS 1e-5f
#define SLOPE 0.01f

// 7 scratch buffers of [B, C, HW] floats: Q, K, V, QKs, VS, Y, Y2
#define BUFN ((long)BB * CC * PP)
__device__ float g_buf[7 * BB * CC * PP];

// ---------------------------------------------------------------------------
// Tiled fp32 GEMM: out[b, o, p] = sum_c W[o,c] * X[b,c,p]  (+ fused epilogue)
// BM=64, BN=64, BK=16, 256 threads, 4x4 per thread.
// MODE 0: out = acc + bias[o]
// MODE 1: out = aux[b,o,p] * sigmoid(acc + bias[o])
// MODE 2: out = leaky( (acc - mn[o]) * g[o]/sqrt(v[o]+eps) + bt[o] )
// ---------------------------------------------------------------------------
template <int MODE>
__global__ void __launch_bounds__(256)
gemm_k(const float* __restrict__ W, const float* __restrict__ X,
       float* __restrict__ out,
       const float* __restrict__ bias, const float* __restrict__ aux,
       const float* __restrict__ g, const float* __restrict__ bt,
       const float* __restrict__ mn, const float* __restrict__ vr,
       long outB)
{
    __shared__ float As[16][64];
    __shared__ float Bs[16][64];
    const int b  = blockIdx.z;
    const int o0 = blockIdx.y * 64;
    const int p0 = blockIdx.x * 64;
    const float* Xb = X + (long)b * CC * PP;
    const int tid = threadIdx.x;
    const int tm = tid >> 4, tn = tid & 15;

    float acc[4][4];
#pragma unroll
    for (int i = 0; i < 4; i++)
#pragma unroll
        for (int j = 0; j < 4; j++) acc[i][j] = 0.f;

    for (int k0 = 0; k0 < CC; k0 += 16) {
        // A tile: 64(m) x 16(k); 4 consecutive k per thread
        {
            int i = tid * 4;
            int m = i >> 4, k = i & 15;
            float4 w4 = *(const float4*)(W + (long)(o0 + m) * CC + k0 + k);
            As[k + 0][m] = w4.x; As[k + 1][m] = w4.y;
            As[k + 2][m] = w4.z; As[k + 3][m] = w4.w;
        }
        // B tile: 16(k) x 64(n); 4 consecutive n per thread
        {
            int i = tid * 4;
            int k = i >> 6, n = i & 63;
            float4 x4 = *(const float4*)(Xb + (long)(k0 + k) * PP + p0 + n);
            *(float4*)&Bs[k][n] = x4;
        }
        __syncthreads();
#pragma unroll
        for (int k = 0; k < 16; k++) {
            float4 a4 = *(const float4*)&As[k][tm * 4];
            float4 b4 = *(const float4*)&Bs[k][tn * 4];
            float a[4] = {a4.x, a4.y, a4.z, a4.w};
            float bb[4] = {b4.x, b4.y, b4.z, b4.w};
#pragma unroll
            for (int i = 0; i < 4; i++)
#pragma unroll
                for (int j = 0; j < 4; j++) acc[i][j] += a[i] * bb[j];
        }
        __syncthreads();
    }

#pragma unroll
    for (int i = 0; i < 4; i++) {
        int o = o0 + tm * 4 + i;
        float bi = 0.f, sc = 0.f, sb = 0.f;
        if (MODE == 0 || MODE == 1) bi = bias[o];
        if (MODE == 2) { sc = g[o] * rsqrtf(vr[o] + EPS); sb = bt[o] - mn[o] * sc; }
#pragma unroll
        for (int j = 0; j < 4; j++) {
            int p = p0 + tn * 4 + j;
            long oi = (long)b * outB + (long)o * PP + p;
            float a = acc[i][j];
            if (MODE == 0) {
                out[oi] = a + bi;
            } else if (MODE == 1) {
                float gg = 1.f / (1.f + __expf(-(a + bi)));
                long ai = (long)b * CC * PP + (long)o * PP + p;
                out[oi] = aux[ai] * gg;
            } else {
                float t = a * sc + sb;
                out[oi] = t > 0.f ? t : SLOPE * t;
            }
        }
    }
}

// ---------------------------------------------------------------------------
// Implicit-GEMM 3x3 conv (SAME padding), K-dim = C*9 = 2304.
// Fused epilogue: outQKs = (acc + ksb[o]) * Qbuf[b,o,p]
// ---------------------------------------------------------------------------
__global__ void __launch_bounds__(256)
convgemm_k(const float* __restrict__ Wk, const float* __restrict__ X,
           const float* __restrict__ ksb, const float* __restrict__ Qb,
           float* __restrict__ outQKs)
{
    __shared__ float As[16][64];
    __shared__ float Bs[16][64];
    const int b  = blockIdx.z;
    const int o0 = blockIdx.y * 64;
    const int p0 = blockIdx.x * 64;
    const float* Xb = X + (long)b * CC * PP;
    const int tid = threadIdx.x;
    const int tm = tid >> 4, tn = tid & 15;
    const int KK = CC * 9;

    float acc[4][4];
#pragma unroll
    for (int i = 0; i < 4; i++)
#pragma unroll
        for (int j = 0; j < 4; j++) acc[i][j] = 0.f;

    for (int k0 = 0; k0 < KK; k0 += 16) {
        {
            int i = tid * 4;
            int m = i >> 4, k = i & 15;
            float4 w4 = *(const float4*)(Wk + (long)(o0 + m) * KK + k0 + k);
            As[k + 0][m] = w4.x; As[k + 1][m] = w4.y;
            As[k + 2][m] = w4.z; As[k + 3][m] = w4.w;
        }
        {
            int i = tid * 4;
            int k = i >> 6, n0 = i & 63;
            int kk = k0 + k;
            int c = kk / 9, t = kk - c * 9;
            int dy = t / 3 - 1, dx = t - (t / 3) * 3 - 1;
            const float* Xc = Xb + (long)c * PP;
#pragma unroll
            for (int q = 0; q < 4; q++) {
                int p = p0 + n0 + q;
                int y = p / WX, x = p - y * WX;
                int yy = y + dy, xx = x + dx;
                float v = 0.f;
                if ((unsigned)yy < WX && (unsigned)xx < WX)
                    v = Xc[yy * WX + xx];
                Bs[k][n0 + q] = v;
            }
        }
        __syncthreads();
#pragma unroll
        for (int k = 0; k < 16; k++) {
            float4 a4 = *(const float4*)&As[k][tm * 4];
            float4 b4 = *(const float4*)&Bs[k][tn * 4];
            float a[4] = {a4.x, a4.y, a4.z, a4.w};
            float bb[4] = {b4.x, b4.y, b4.z, b4.w};
#pragma unroll
            for (int i = 0; i < 4; i++)
#pragma unroll
                for (int j = 0; j < 4; j++) acc[i][j] += a[i] * bb[j];
        }
        __syncthreads();
    }

#pragma unroll
    for (int i = 0; i < 4; i++) {
        int o = o0 + tm * 4 + i;
        float bi = ksb[o];
#pragma unroll
        for (int j = 0; j < 4; j++) {
            int p = p0 + tn * 4 + j;
            long oi = (long)b * CC * PP + (long)o * PP + p;
            outQKs[oi] = (acc[i][j] + bi) * Qb[oi];
        }
    }
}

// ---------------------------------------------------------------------------
// Flash attention (fp32). grid=(25, 16): x = query tile of 128, y = b*8+h.
// 128 threads, 1 query per thread, K/V tiles of 128 keys in smem (pitch 36).
// Writes sa directly into d_out channels [0,256).
// ---------------------------------------------------------------------------
__global__ void __launch_bounds__(128)
attn_k(const float* __restrict__ Q, const float* __restrict__ K,
       const float* __restrict__ V, float* __restrict__ out)
{
    __shared__ float ksm[128 * 36];
    __shared__ float vsm[128 * 36];
    const int tid = threadIdx.x;
    const int bh = blockIdx.y;
    const int b = bh >> 3, h = bh & 7;
    const long base = ((long)b * CC + h * 32) * PP;
    const float* qp = Q + base;
    const float* kp = K + base;
    const float* vp = V + base;

    const int qpos = blockIdx.x * 128 + tid;
    const bool active = qpos < PP;

    float qr[32];
    const float scale = 0.17677669529663687f;  // 1/sqrt(32)
#pragma unroll
    for (int d = 0; d < 32; d++)
        qr[d] = active ? qp[(long)d * PP + qpos] * scale : 0.f;

    float m = -1e30f, l = 0.f;
    float acc[32];
#pragma unroll
    for (int d = 0; d < 32; d++) acc[d] = 0.f;

    for (int kt = 0; kt < 25; kt++) {
        const int kbase = kt * 128;
        const int kn = min(128, PP - kbase);
        __syncthreads();
        // cooperative float4 load of K and V tiles, smem layout [j][d] pitch 36
        for (int i = tid; i < 32 * 32; i += 128) {
            int d = i >> 5;
            int j4 = (i & 31) * 4;
            if (j4 < kn) {
                float4 kv = *(const float4*)(kp + (long)d * PP + kbase + j4);
                ksm[(j4 + 0) * 36 + d] = kv.x; ksm[(j4 + 1) * 36 + d] = kv.y;
                ksm[(j4 + 2) * 36 + d] = kv.z; ksm[(j4 + 3) * 36 + d] = kv.w;
                float4 vv = *(const float4*)(vp + (long)d * PP + kbase + j4);
                vsm[(j4 + 0) * 36 + d] = vv.x; vsm[(j4 + 1) * 36 + d] = vv.y;
                vsm[(j4 + 2) * 36 + d] = vv.z; vsm[(j4 + 3) * 36 + d] = vv.w;
            }
        }
        __syncthreads();

        for (int j = 0; j < kn; j++) {
            const float* kr = ksm + j * 36;
            float s0 = 0.f, s1 = 0.f, s2 = 0.f, s3 = 0.f;
#pragma unroll
            for (int d = 0; d < 32; d += 4) {
                float4 kv = *(const float4*)(kr + d);
                s0 += qr[d + 0] * kv.x; s1 += qr[d + 1] * kv.y;
                s2 += qr[d + 2] * kv.z; s3 += qr[d + 3] * kv.w;
            }
            float s = (s0 + s1) + (s2 + s3);
            float p;
            if (s > m) {
                float alpha = __expf(m - s);
#pragma unroll
                for (int d = 0; d < 32; d++) acc[d] *= alpha;
                l *= alpha; m = s; p = 1.f;
            } else {
                p = __expf(s - m);
            }
            l += p;
            const float* vrw = vsm + j * 36;
#pragma unroll
            for (int d = 0; d < 32; d += 4) {
                float4 vv = *(const float4*)(vrw + d);
                acc[d + 0] += p * vv.x; acc[d + 1] += p * vv.y;
                acc[d + 2] += p * vv.z; acc[d + 3] += p * vv.w;
            }
        }
    }

    if (active) {
        float inv = 1.f / l;
        float* op = out + (long)b * (2 * CC * PP) + (long)(h * 32) * PP + qpos;
#pragma unroll
        for (int d = 0; d < 32; d++) op[(long)d * PP] = acc[d] * inv;
    }
}

// ---------------------------------------------------------------------------
// Depthwise 3x3 conv + BN1 + leaky ReLU (elementwise, L2-fed).
// ---------------------------------------------------------------------------
__global__ void __launch_bounds__(256)
dw_bn_lrelu_k(const float* __restrict__ in, const float* __restrict__ w9,
              const float* __restrict__ g, const float* __restrict__ bt,
              const float* __restrict__ mn, const float* __restrict__ vv,
              float* __restrict__ out)
{
    long idx = (long)blockIdx.x * 256 + threadIdx.x;
    if (idx >= (long)BB * CC * PP) return;
    int p = (int)(idx % PP);
    int c = (int)((idx / PP) % CC);
    int y = p / WX, x = p - y * WX;
    const float* ip = in + (idx - p);
    const float* wc = w9 + c * 9;
    float s = 0.f;
#pragma unroll
    for (int dy = -1; dy <= 1; dy++) {
        int yy = y + dy;
        if ((unsigned)yy >= WX) continue;
#pragma unroll
        for (int dx = -1; dx <= 1; dx++) {
            int xx = x + dx;
            if ((unsigned)xx >= WX) continue;
            s += wc[(dy + 1) * 3 + (dx + 1)] * ip[yy * WX + xx];
        }
    }
    float sc = g[c] * rsqrtf(vv[c] + EPS);
    float t = (s - mn[c]) * sc + bt[c];
    out[idx] = t > 0.f ? t : SLOPE * t;
}

// ---------------------------------------------------------------------------
extern "C" void kernel_launch(void* const* d_in, const int* in_sizes, int n_in,
                              void* d_out, int out_size)
{
    (void)in_sizes; (void)n_in; (void)out_size;
    const float* x    = (const float*)d_in[0];
    const float* qw   = (const float*)d_in[1];
    const float* qb   = (const float*)d_in[2];
    const float* kw   = (const float*)d_in[3];
    const float* kb   = (const float*)d_in[4];
    const float* vw   = (const float*)d_in[5];
    const float* vb   = (const float*)d_in[6];
    const float* ksw  = (const float*)d_in[7];
    const float* ksb  = (const float*)d_in[8];
    const float* sd1w = (const float*)d_in[9];
    const float* sd1b = (const float*)d_in[10];
    const float* sd2w = (const float*)d_in[11];
    const float* sd2b = (const float*)d_in[12];
    const float* dww  = (const float*)d_in[13];
    const float* bn1g = (const float*)d_in[14];
    const float* bn1b = (const float*)d_in[15];
    const float* bn1m = (const float*)d_in[16];
    const float* bn1v = (const float*)d_in[17];
    const float* pww  = (const float*)d_in[18];
    const float* bn2g = (const float*)d_in[19];
    const float* bn2b = (const float*)d_in[20];
    const float* bn2m = (const float*)d_in[21];
    const float* bn2v = (const float*)d_in[22];
    float* out = (float*)d_out;

    float* buf = nullptr;
    cudaGetSymbolAddress((void**)&buf, g_buf);
    float* Q   = buf + 0 * BUFN;
    float* Kb  = buf + 1 * BUFN;
    float* Vb  = buf + 2 * BUFN;
    float* QKs = buf + 3 * BUFN;
    float* VS  = buf + 4 * BUFN;
    float* Y   = buf + 5 * BUFN;
    float* Y2  = buf + 6 * BUFN;

    dim3 gg(PP / 64, CC / 64, BB);  // (49, 4, 2)
    const long bs = (long)CC * PP;

    // Q, K, V projections
    gemm_k<0><<<gg, 256>>>(qw, x, Q,  qb, nullptr, nullptr, nullptr, nullptr, nullptr, bs);
    gemm_k<0><<<gg, 256>>>(kw, x, Kb, kb, nullptr, nullptr, nullptr, nullptr, nullptr, bs);
    gemm_k<0><<<gg, 256>>>(vw, x, Vb, vb, nullptr, nullptr, nullptr, nullptr, nullptr, bs);

    // Ks 3x3 conv, fused *Q  -> QKs
    convgemm_k<<<gg, 256>>>(ksw, x, ksb, Q, QKs);

    // flash attention -> out channels [0,256)
    attn_k<<<dim3(25, 16), 128>>>(Q, Kb, Vb, out);

    // gate = sigmoid(sd1(QKs)); VS = V * gate
    gemm_k<1><<<gg, 256>>>(sd1w, QKs, VS, sd1b, Vb, nullptr, nullptr, nullptr, nullptr, bs);

    // depthwise 3x3 + BN1 + leaky -> Y
    long total = (long)BB * CC * PP;
    dw_bn_lrelu_k<<<(int)((total + 255) / 256), 256>>>(VS, dww, bn1g, bn1b, bn1m, bn1v, Y);

    // pointwise pww + BN2 + leaky -> Y2
    gemm_k<2><<<gg, 256>>>(pww, Y, Y2, nullptr, nullptr, bn2g, bn2b, bn2m, bn2v, bs);

    // sd2 projection -> out channels [256,512)
    gemm_k<0><<<gg, 256>>>(sd2w, Y2, out + (long)CC * PP, sd2b,
                           nullptr, nullptr, nullptr, nullptr, nullptr, (long)2 * CC * PP);
}

// round 2
// speedup vs baseline: 1.7768x; 1.7768x over previous
#include <cuda_runtime.h>
#include <math.h>

#define PP 3136
#define CC 256
#define BB 2
#define WX 56
#define EPS 1e-5f
#define SLOPE 0.01f

// 7 scratch buffers of [B, C, HW] floats: Q, K, V, QKs, VS, Y, Y2
#define BUFN ((long)BB * CC * PP)
__device__ float g_buf[7 * BB * CC * PP];

__device__ __forceinline__ unsigned f2tf(float f) {
    unsigned u;
    asm("cvt.rna.tf32.f32 %0, %1;" : "=r"(u) : "f"(f));
    return u;
}
__device__ __forceinline__ float f2tff(float f) { return __uint_as_float(f2tf(f)); }

__device__ __forceinline__ void mma8(float* c, const unsigned* a, unsigned b0, unsigned b1) {
    asm volatile(
        "mma.sync.aligned.m16n8k8.row.col.f32.tf32.tf32.f32 "
        "{%0,%1,%2,%3}, {%4,%5,%6,%7}, {%8,%9}, {%0,%1,%2,%3};"
        : "+f"(c[0]), "+f"(c[1]), "+f"(c[2]), "+f"(c[3])
        : "r"(a[0]), "r"(a[1]), "r"(a[2]), "r"(a[3]), "r"(b0), "r"(b1));
}

// ---------------------------------------------------------------------------
// Tiled fp32 GEMM: out[b, o, p] = sum_c W[o,c] * X[b,c,p]  (+ fused epilogue)
// BM=128, BN=64, BK=16, 256 threads, 8x4 per thread.
// MODE 0: out = acc + bias[o]
// MODE 1: out = aux[b,o,p] * sigmoid(acc + bias[o])
// MODE 2: out = leaky( (acc - mn[o]) * g[o]/sqrt(v[o]+eps) + bt[o] )
// ---------------------------------------------------------------------------
template <int MODE>
__global__ void __launch_bounds__(256)
gemm_k(const float* __restrict__ W, const float* __restrict__ X,
       float* __restrict__ out,
       const float* __restrict__ bias, const float* __restrict__ aux,
       const float* __restrict__ g, const float* __restrict__ bt,
       const float* __restrict__ mn, const float* __restrict__ vr,
       long outB)
{
    __shared__ float As[16][128];
    __shared__ float Bs[16][64];
    const int b  = blockIdx.z;
    const int o0 = blockIdx.y * 128;
    const int p0 = blockIdx.x * 64;
    const float* Xb = X + (long)b * CC * PP;
    const int tid = threadIdx.x;
    const int tm = tid >> 4, tn = tid & 15;

    float acc[8][4];
#pragma unroll
    for (int i = 0; i < 8; i++)
#pragma unroll
        for (int j = 0; j < 4; j++) acc[i][j] = 0.f;

    for (int k0 = 0; k0 < CC; k0 += 16) {
        // A tile: 128(m) x 16(k); each thread: 1 row, 8 consecutive k
        {
            int m = tid >> 1, kh = (tid & 1) * 8;
            const float* wp = W + (long)(o0 + m) * CC + k0 + kh;
            float4 wa = *(const float4*)(wp);
            float4 wb = *(const float4*)(wp + 4);
            As[kh + 0][m] = wa.x; As[kh + 1][m] = wa.y;
            As[kh + 2][m] = wa.z; As[kh + 3][m] = wa.w;
            As[kh + 4][m] = wb.x; As[kh + 5][m] = wb.y;
            As[kh + 6][m] = wb.z; As[kh + 7][m] = wb.w;
        }
        // B tile: 16(k) x 64(n); 4 consecutive n per thread
        {
            int k = tid >> 4, n = (tid & 15) * 4;
            *(float4*)&Bs[k][n] = *(const float4*)(Xb + (long)(k0 + k) * PP + p0 + n);
        }
        __syncthreads();
#pragma unroll
        for (int k = 0; k < 16; k++) {
            float4 a0 = *(const float4*)&As[k][tm * 8];
            float4 a1 = *(const float4*)&As[k][tm * 8 + 4];
            float4 b4 = *(const float4*)&Bs[k][tn * 4];
            float a[8] = {a0.x, a0.y, a0.z, a0.w, a1.x, a1.y, a1.z, a1.w};
            float bb[4] = {b4.x, b4.y, b4.z, b4.w};
#pragma unroll
            for (int i = 0; i < 8; i++)
#pragma unroll
                for (int j = 0; j < 4; j++) acc[i][j] += a[i] * bb[j];
        }
        __syncthreads();
    }

#pragma unroll
    for (int i = 0; i < 8; i++) {
        int o = o0 + tm * 8 + i;
        float bi = 0.f, sc = 0.f, sb = 0.f;
        if (MODE == 0 || MODE == 1) bi = bias[o];
        if (MODE == 2) { sc = g[o] * rsqrtf(vr[o] + EPS); sb = bt[o] - mn[o] * sc; }
        long oi = (long)b * outB + (long)o * PP + p0 + tn * 4;
        float4 r;
        if (MODE == 0) {
            r.x = acc[i][0] + bi; r.y = acc[i][1] + bi;
            r.z = acc[i][2] + bi; r.w = acc[i][3] + bi;
        } else if (MODE == 1) {
            long ai = (long)b * CC * PP + (long)o * PP + p0 + tn * 4;
            float4 av = *(const float4*)(aux + ai);
            r.x = av.x / (1.f + __expf(-(acc[i][0] + bi)));
            r.y = av.y / (1.f + __expf(-(acc[i][1] + bi)));
            r.z = av.z / (1.f + __expf(-(acc[i][2] + bi)));
            r.w = av.w / (1.f + __expf(-(acc[i][3] + bi)));
        } else {
            float t0 = acc[i][0] * sc + sb, t1 = acc[i][1] * sc + sb;
            float t2 = acc[i][2] * sc + sb, t3 = acc[i][3] * sc + sb;
            r.x = t0 > 0.f ? t0 : SLOPE * t0; r.y = t1 > 0.f ? t1 : SLOPE * t1;
            r.z = t2 > 0.f ? t2 : SLOPE * t2; r.w = t3 > 0.f ? t3 : SLOPE * t3;
        }
        *(float4*)(out + oi) = r;
    }
}

// ---------------------------------------------------------------------------
// Implicit-GEMM 3x3 conv (SAME padding), K-dim = C*9 = 2304. BM=128, BN=64.
// Fused epilogue: outQKs = (acc + ksb[o]) * Qbuf[b,o,p]
// ---------------------------------------------------------------------------
__global__ void __launch_bounds__(256)
convgemm_k(const float* __restrict__ Wk, const float* __restrict__ X,
           const float* __restrict__ ksb, const float* __restrict__ Qb,
           float* __restrict__ outQKs)
{
    __shared__ float As[16][128];
    __shared__ float Bs[16][64];
    const int b  = blockIdx.z;
    const int o0 = blockIdx.y * 128;
    const int p0 = blockIdx.x * 64;
    const float* Xb = X + (long)b * CC * PP;
    const int tid = threadIdx.x;
    const int tm = tid >> 4, tn = tid & 15;
    const int KK = CC * 9;

    float acc[8][4];
#pragma unroll
    for (int i = 0; i < 8; i++)
#pragma unroll
        for (int j = 0; j < 4; j++) acc[i][j] = 0.f;

    for (int k0 = 0; k0 < KK; k0 += 16) {
        {
            int m = tid >> 1, kh = (tid & 1) * 8;
            const float* wp = Wk + (long)(o0 + m) * KK + k0 + kh;
            float4 wa = *(const float4*)(wp);
            float4 wb = *(const float4*)(wp + 4);
            As[kh + 0][m] = wa.x; As[kh + 1][m] = wa.y;
            As[kh + 2][m] = wa.z; As[kh + 3][m] = wa.w;
            As[kh + 4][m] = wb.x; As[kh + 5][m] = wb.y;
            As[kh + 6][m] = wb.z; As[kh + 7][m] = wb.w;
        }
        {
            int k = tid >> 4, n0 = (tid & 15) * 4;
            int kk = k0 + k;
            int c = kk / 9, t = kk - c * 9;
            int dy = t / 3 - 1, dx = t - (t / 3) * 3 - 1;
            const float* Xc = Xb + (long)c * PP;
#pragma unroll
            for (int q = 0; q < 4; q++) {
                int p = p0 + n0 + q;
                int y = p / WX, x = p - y * WX;
                int yy = y + dy, xx = x + dx;
                float v = 0.f;
                if ((unsigned)yy < WX && (unsigned)xx < WX)
                    v = Xc[yy * WX + xx];
                Bs[k][n0 + q] = v;
            }
        }
        __syncthreads();
#pragma unroll
        for (int k = 0; k < 16; k++) {
            float4 a0 = *(const float4*)&As[k][tm * 8];
            float4 a1 = *(const float4*)&As[k][tm * 8 + 4];
            float4 b4 = *(const float4*)&Bs[k][tn * 4];
            float a[8] = {a0.x, a0.y, a0.z, a0.w, a1.x, a1.y, a1.z, a1.w};
            float bb[4] = {b4.x, b4.y, b4.z, b4.w};
#pragma unroll
            for (int i = 0; i < 8; i++)
#pragma unroll
                for (int j = 0; j < 4; j++) acc[i][j] += a[i] * bb[j];
        }
        __syncthreads();
    }

#pragma unroll
    for (int i = 0; i < 8; i++) {
        int o = o0 + tm * 8 + i;
        float bi = ksb[o];
        long oi = (long)b * CC * PP + (long)o * PP + p0 + tn * 4;
        float4 qv = *(const float4*)(Qb + oi);
        float4 r;
        r.x = (acc[i][0] + bi) * qv.x; r.y = (acc[i][1] + bi) * qv.y;
        r.z = (acc[i][2] + bi) * qv.z; r.w = (acc[i][3] + bi) * qv.w;
        *(float4*)(outQKs + oi) = r;
    }
}

// ---------------------------------------------------------------------------
// Flash attention with tf32 mma.sync (m16n8k8). Per block: 64 queries for one
// (b,h). 4 warps, each owns a 16-query strip. 49 key tiles of 64 (3136=49*64).
// K/V stored d-major in smem pitch 72 (conflict-free B-frag reads; PV's B
// operand is V[d][key] directly, no transpose). P goes through per-warp
// private smem. fp32 accumulators + online softmax.
// ---------------------------------------------------------------------------
__global__ void __launch_bounds__(128)
attn_mma_k(const float* __restrict__ Q, const float* __restrict__ K,
           const float* __restrict__ V, float* __restrict__ out)
{
    __shared__ float Ks[32 * 72];
    __shared__ float Vs[32 * 72];
    __shared__ float Ps[64 * 68];   // aliased as Qs[64][36] during init

    const int tid = threadIdx.x, lane = tid & 31, w = tid >> 5;
    const int bh = blockIdx.y;
    const int b = bh >> 3, h = bh & 7;
    const long base = ((long)b * CC + h * 32) * PP;
    const float* qp = Q + base;
    const float* kp = K + base;
    const float* vp = V + base;
    const int q0 = blockIdx.x * 64;
    const float scale = 0.17677669529663687f;  // 1/sqrt(32)

    // ---- load Q tile into Ps as Qs[q][d] (pitch 36), scaled + tf32 ----
    float* Qs = Ps;
    for (int i = tid; i < 512; i += 128) {
        int d = i >> 4, q4 = (i & 15) * 4;
        float4 v4 = *(const float4*)(qp + (long)d * PP + q0 + q4);
        Qs[(q4 + 0) * 36 + d] = f2tff(v4.x * scale);
        Qs[(q4 + 1) * 36 + d] = f2tff(v4.y * scale);
        Qs[(q4 + 2) * 36 + d] = f2tff(v4.z * scale);
        Qs[(q4 + 3) * 36 + d] = f2tff(v4.w * scale);
    }
    __syncthreads();

    // ---- hoist Q A-fragments (4 k-chunks of 8) ----
    unsigned af[4][4];
    {
        int r = w * 16 + (lane >> 2);
        int c = lane & 3;
#pragma unroll
        for (int kc = 0; kc < 4; kc++) {
            af[kc][0] = __float_as_uint(Qs[r * 36 + kc * 8 + c]);
            af[kc][1] = __float_as_uint(Qs[(r + 8) * 36 + kc * 8 + c]);
            af[kc][2] = __float_as_uint(Qs[r * 36 + kc * 8 + c + 4]);
            af[kc][3] = __float_as_uint(Qs[(r + 8) * 36 + kc * 8 + c + 4]);
        }
    }
    __syncthreads();  // Ps now free for P use

    float m0 = -1e30f, m1 = -1e30f, l0 = 0.f, l1 = 0.f;
    float o[4][4];
#pragma unroll
    for (int nt = 0; nt < 4; nt++)
#pragma unroll
        for (int j = 0; j < 4; j++) o[nt][j] = 0.f;

    float* Pw = Ps + w * 16 * 68;
    const int lq = lane >> 2;   // lane/4
    const int lr = lane & 3;    // lane%4

    for (int kt = 0; kt < 49; kt++) {
        const int kb = kt * 64;
        __syncthreads();
        // load K, V tiles: [32 d][64 keys], tf32, pitch 72
        for (int i = tid; i < 512; i += 128) {
            int d = i >> 4, k4 = (i & 15) * 4;
            float4 kv = *(const float4*)(kp + (long)d * PP + kb + k4);
            float4 vv = *(const float4*)(vp + (long)d * PP + kb + k4);
            float* kd = Ks + d * 72 + k4;
            float* vd = Vs + d * 72 + k4;
            kd[0] = f2tff(kv.x); kd[1] = f2tff(kv.y);
            kd[2] = f2tff(kv.z); kd[3] = f2tff(kv.w);
            vd[0] = f2tff(vv.x); vd[1] = f2tff(vv.y);
            vd[2] = f2tff(vv.z); vd[3] = f2tff(vv.w);
        }
        __syncthreads();

        // ---- S = Q @ K : 8 n-tiles x 4 k-chunks of mma ----
        float s[8][4];
#pragma unroll
        for (int nt = 0; nt < 8; nt++)
#pragma unroll
            for (int j = 0; j < 4; j++) s[nt][j] = 0.f;
#pragma unroll
        for (int kc = 0; kc < 4; kc++) {
#pragma unroll
            for (int nt = 0; nt < 8; nt++) {
                unsigned b0 = __float_as_uint(Ks[(kc * 8 + lr) * 72 + nt * 8 + lq]);
                unsigned b1 = __float_as_uint(Ks[(kc * 8 + lr + 4) * 72 + nt * 8 + lq]);
                mma8(s[nt], af[kc], b0, b1);
            }
        }

        // ---- online softmax ----
        float mx0 = s[0][0], mx1 = s[0][2];
#pragma unroll
        for (int nt = 0; nt < 8; nt++) {
            mx0 = fmaxf(mx0, fmaxf(s[nt][0], s[nt][1]));
            mx1 = fmaxf(mx1, fmaxf(s[nt][2], s[nt][3]));
        }
        mx0 = fmaxf(mx0, __shfl_xor_sync(0xffffffffu, mx0, 1));
        mx0 = fmaxf(mx0, __shfl_xor_sync(0xffffffffu, mx0, 2));
        mx1 = fmaxf(mx1, __shfl_xor_sync(0xffffffffu, mx1, 1));
        mx1 = fmaxf(mx1, __shfl_xor_sync(0xffffffffu, mx1, 2));
        float nm0 = fmaxf(m0, mx0), nm1 = fmaxf(m1, mx1);
        float a0 = __expf(m0 - nm0), a1 = __expf(m1 - nm1);
        m0 = nm0; m1 = nm1;

        float ps0 = 0.f, ps1 = 0.f;
#pragma unroll
        for (int nt = 0; nt < 8; nt++) {
            s[nt][0] = __expf(s[nt][0] - m0); ps0 += s[nt][0];
            s[nt][1] = __expf(s[nt][1] - m0); ps0 += s[nt][1];
            s[nt][2] = __expf(s[nt][2] - m1); ps1 += s[nt][2];
            s[nt][3] = __expf(s[nt][3] - m1); ps1 += s[nt][3];
        }
        ps0 += __shfl_xor_sync(0xffffffffu, ps0, 1);
        ps0 += __shfl_xor_sync(0xffffffffu, ps0, 2);
        ps1 += __shfl_xor_sync(0xffffffffu, ps1, 1);
        ps1 += __shfl_xor_sync(0xffffffffu, ps1, 2);
        l0 = l0 * a0 + ps0;
        l1 = l1 * a1 + ps1;
#pragma unroll
        for (int nt = 0; nt < 4; nt++) {
            o[nt][0] *= a0; o[nt][1] *= a0;
            o[nt][2] *= a1; o[nt][3] *= a1;
        }

        // ---- write P (tf32) to per-warp private smem ----
        __syncwarp();   // prior PV reads of Pw done before overwrite
#pragma unroll
        for (int nt = 0; nt < 8; nt++) {
            int c = nt * 8 + lr * 2;
            Pw[lq * 68 + c]       = f2tff(s[nt][0]);
            Pw[lq * 68 + c + 1]   = f2tff(s[nt][1]);
            Pw[(lq + 8) * 68 + c]     = f2tff(s[nt][2]);
            Pw[(lq + 8) * 68 + c + 1] = f2tff(s[nt][3]);
        }
        __syncwarp();

        // ---- O += P @ V : 8 k-chunks, 4 n-tiles ----
#pragma unroll
        for (int kc = 0; kc < 8; kc++) {
            unsigned pa[4];
            pa[0] = __float_as_uint(Pw[lq * 68 + kc * 8 + lr]);
            pa[1] = __float_as_uint(Pw[(lq + 8) * 68 + kc * 8 + lr]);
            pa[2] = __float_as_uint(Pw[lq * 68 + kc * 8 + lr + 4]);
            pa[3] = __float_as_uint(Pw[(lq + 8) * 68 + kc * 8 + lr + 4]);
#pragma unroll
            for (int nt = 0; nt < 4; nt++) {
                unsigned b0 = __float_as_uint(Vs[(nt * 8 + lq) * 72 + kc * 8 + lr]);
                unsigned b1 = __float_as_uint(Vs[(nt * 8 + lq) * 72 + kc * 8 + lr + 4]);
                mma8(o[nt], pa, b0, b1);
            }
        }
    }

    // ---- epilogue: O /= l, write to out channels [0, 256) ----
    float inv0 = 1.f / l0, inv1 = 1.f / l1;
    float* op = out + (long)b * (2 * CC * PP) + (long)(h * 32) * PP;
    int qr = q0 + w * 16 + lq;
#pragma unroll
    for (int nt = 0; nt < 4; nt++) {
        int d = nt * 8 + lr * 2;
        op[(long)d * PP + qr]           = o[nt][0] * inv0;
        op[(long)(d + 1) * PP + qr]     = o[nt][1] * inv0;
        op[(long)d * PP + qr + 8]       = o[nt][2] * inv1;
        op[(long)(d + 1) * PP + qr + 8] = o[nt][3] * inv1;
    }
}

// ---------------------------------------------------------------------------
// Depthwise 3x3 conv + BN1 + leaky ReLU (elementwise, L2-fed).
// ---------------------------------------------------------------------------
__global__ void __launch_bounds__(256)
dw_bn_lrelu_k(const float* __restrict__ in, const float* __restrict__ w9,
              const float* __restrict__ g, const float* __restrict__ bt,
              const float* __restrict__ mn, const float* __restrict__ vv,
              float* __restrict__ out)
{
    long idx = (long)blockIdx.x * 256 + threadIdx.x;
    if (idx >= (long)BB * CC * PP) return;
    int p = (int)(idx % PP);
    int c = (int)((idx / PP) % CC);
    int y = p / WX, x = p - y * WX;
    const float* ip = in + (idx - p);
    const float* wc = w9 + c * 9;
    float s = 0.f;
#pragma unroll
    for (int dy = -1; dy <= 1; dy++) {
        int yy = y + dy;
        if ((unsigned)yy >= WX) continue;
#pragma unroll
        for (int dx = -1; dx <= 1; dx++) {
            int xx = x + dx;
            if ((unsigned)xx >= WX) continue;
            s += wc[(dy + 1) * 3 + (dx + 1)] * ip[yy * WX + xx];
        }
    }
    float sc = g[c] * rsqrtf(vv[c] + EPS);
    float t = (s - mn[c]) * sc + bt[c];
    out[idx] = t > 0.f ? t : SLOPE * t;
}

// ---------------------------------------------------------------------------
extern "C" void kernel_launch(void* const* d_in, const int* in_sizes, int n_in,
                              void* d_out, int out_size)
{
    (void)in_sizes; (void)n_in; (void)out_size;
    const float* x    = (const float*)d_in[0];
    const float* qw   = (const float*)d_in[1];
    const float* qb   = (const float*)d_in[2];
    const float* kw   = (const float*)d_in[3];
    const float* kb   = (const float*)d_in[4];
    const float* vw   = (const float*)d_in[5];
    const float* vb   = (const float*)d_in[6];
    const float* ksw  = (const float*)d_in[7];
    const float* ksb  = (const float*)d_in[8];
    const float* sd1w = (const float*)d_in[9];
    const float* sd1b = (const float*)d_in[10];
    const float* sd2w = (const float*)d_in[11];
    const float* sd2b = (const float*)d_in[12];
    const float* dww  = (const float*)d_in[13];
    const float* bn1g = (const float*)d_in[14];
    const float* bn1b = (const float*)d_in[15];
    const float* bn1m = (const float*)d_in[16];
    const float* bn1v = (const float*)d_in[17];
    const float* pww  = (const float*)d_in[18];
    const float* bn2g = (const float*)d_in[19];
    const float* bn2b = (const float*)d_in[20];
    const float* bn2m = (const float*)d_in[21];
    const float* bn2v = (const float*)d_in[22];
    float* out = (float*)d_out;

    float* buf = nullptr;
    cudaGetSymbolAddress((void**)&buf, g_buf);
    float* Q   = buf + 0 * BUFN;
    float* Kb  = buf + 1 * BUFN;
    float* Vb  = buf + 2 * BUFN;
    float* QKs = buf + 3 * BUFN;
    float* VS  = buf + 4 * BUFN;
    float* Y   = buf + 5 * BUFN;
    float* Y2  = buf + 6 * BUFN;

    dim3 gg(PP / 64, CC / 128, BB);  // (49, 2, 2)
    const long bs = (long)CC * PP;

    // Q, K, V projections
    gemm_k<0><<<gg, 256>>>(qw, x, Q,  qb, nullptr, nullptr, nullptr, nullptr, nullptr, bs);
    gemm_k<0><<<gg, 256>>>(kw, x, Kb, kb, nullptr, nullptr, nullptr, nullptr, nullptr, bs);
    gemm_k<0><<<gg, 256>>>(vw, x, Vb, vb, nullptr, nullptr, nullptr, nullptr, nullptr, bs);

    // Ks 3x3 conv, fused *Q  -> QKs
    convgemm_k<<<gg, 256>>>(ksw, x, ksb, Q, QKs);

    // flash attention (tf32 mma) -> out channels [0,256)
    attn_mma_k<<<dim3(49, 16), 128>>>(Q, Kb, Vb, out);

    // gate = sigmoid(sd1(QKs)); VS = V * gate
    gemm_k<1><<<gg, 256>>>(sd1w, QKs, VS, sd1b, Vb, nullptr, nullptr, nullptr, nullptr, bs);

    // depthwise 3x3 + BN1 + leaky -> Y
    long total = (long)BB * CC * PP;
    dw_bn_lrelu_k<<<(int)((total + 255) / 256), 256>>>(VS, dww, bn1g, bn1b, bn1m, bn1v, Y);

    // pointwise pww + BN2 + leaky -> Y2
    gemm_k<2><<<gg, 256>>>(pww, Y, Y2, nullptr, nullptr, bn2g, bn2b, bn2m, bn2v, bs);

    // sd2 projection -> out channels [256,512)
    gemm_k<0><<<gg, 256>>>(sd2w, Y2, out + (long)CC * PP, sd2b,
                           nullptr, nullptr, nullptr, nullptr, nullptr, (long)2 * CC * PP);
}

// round 6
// speedup vs baseline: 2.3983x; 1.3498x over previous
// v3-resubmit (R5): identical logic to R3/R4 submission; re-bench after infra failures.
#include <cuda_runtime.h>
#include <math.h>

#define PP 3136
#define CC 256
#define BB 2
#define WX 56
#define EPS 1e-5f
#define SLOPE 0.01f

// 7 scratch buffers of [B, C, HW] floats: Q, K, V, QKs, VS, Y, Y2
#define BUFN ((long)BB * CC * PP)
__device__ float g_buf[7 * BB * CC * PP];

__device__ __forceinline__ unsigned f2tf(float f) {
    unsigned u;
    asm("cvt.rna.tf32.f32 %0, %1;" : "=r"(u) : "f"(f));
    return u;
}
__device__ __forceinline__ float f2tff(float f) { return __uint_as_float(f2tf(f)); }

__device__ __forceinline__ void mma8(float* c, const unsigned* a, unsigned b0, unsigned b1) {
    asm volatile(
        "mma.sync.aligned.m16n8k8.row.col.f32.tf32.tf32.f32 "
        "{%0,%1,%2,%3}, {%4,%5,%6,%7}, {%8,%9}, {%0,%1,%2,%3};"
        : "+f"(c[0]), "+f"(c[1]), "+f"(c[2]), "+f"(c[3])
        : "r"(a[0]), "r"(a[1]), "r"(a[2]), "r"(a[3]), "r"(b0), "r"(b1));
}

// ---------------------------------------------------------------------------
// Unified tf32 tensor-core GEMM: out[b,o,p] = sum_c W[o,c] * X[b,c,p] (+epi)
// BM=128, BN=64, BK=16. 256 threads = 8 warps in 4(m) x 2(n); each warp owns
// a 32x32 macro-tile = 2(m16) x 4(n8) mma tiles.
// A tile in smem k-major [16][136]; B tile [16][72]; both conflict-free for
// fragment reads (bank = 8*(lane&3) + lane>>2 + const).
// CONV: B tile is an im2col gather over C*9 with SAME padding.
// MODE 0: out = acc + bias[o]
// MODE 1: out = aux * sigmoid(acc + bias[o])
// MODE 2: out = leaky((acc - mn[o])*g[o]/sqrt(v[o]+eps) + bt[o])
// MODE 3: out = (acc + bias[o]) * aux        (Ks-conv fused *Q)
// ---------------------------------------------------------------------------
template <int MODE, bool CONV>
__global__ void __launch_bounds__(256)
mm_k(const float* __restrict__ W, const float* __restrict__ X,
     float* __restrict__ out,
     const float* __restrict__ bias, const float* __restrict__ aux,
     const float* __restrict__ g, const float* __restrict__ bt,
     const float* __restrict__ mn, const float* __restrict__ vr,
     long outB, int KK)
{
    __shared__ float As[16][136];
    __shared__ float Bs[16][72];
    const int b  = blockIdx.z;
    const int o0 = blockIdx.y * 128;
    const int p0 = blockIdx.x * 64;
    const float* Xb = X + (long)b * CC * PP;
    const int tid = threadIdx.x, lane = tid & 31, w = tid >> 5;
    const int wm = w & 3, wn = w >> 2;           // warp tile: 32(m) x 32(n)
    const int mw = wm * 32, nw = wn * 32;
    const int r = lane >> 2, cA = lane & 3;

    float acc[2][4][4];
#pragma unroll
    for (int mt = 0; mt < 2; mt++)
#pragma unroll
        for (int nt = 0; nt < 4; nt++)
#pragma unroll
            for (int j = 0; j < 4; j++) acc[mt][nt][j] = 0.f;

    const int am = tid >> 1, akh = (tid & 1) * 8;

    for (int k0 = 0; k0 < KK; k0 += 16) {
        // ---- A tile: W rows o0..o0+127, cols k0..k0+15 -> As[k][m] tf32 ----
        {
            const float* wp = W + (long)(o0 + am) * KK + k0 + akh;
            float4 wa = *(const float4*)(wp);
            float4 wb = *(const float4*)(wp + 4);
            As[akh + 0][am] = f2tff(wa.x); As[akh + 1][am] = f2tff(wa.y);
            As[akh + 2][am] = f2tff(wa.z); As[akh + 3][am] = f2tff(wa.w);
            As[akh + 4][am] = f2tff(wb.x); As[akh + 5][am] = f2tff(wb.y);
            As[akh + 6][am] = f2tff(wb.z); As[akh + 7][am] = f2tff(wb.w);
        }
        // ---- B tile: 16(k) x 64(n) -> Bs[k][n] tf32 ----
        {
            int k = tid >> 4, n0 = (tid & 15) * 4;
            if (CONV) {
                int kk = k0 + k;
                int c = kk / 9, t = kk - c * 9;
                int dy = t / 3 - 1, dx = t - (t / 3) * 3 - 1;
                const float* Xc = Xb + (long)c * PP;
#pragma unroll
                for (int q = 0; q < 4; q++) {
                    int p = p0 + n0 + q;
                    int y = p / WX, x = p - y * WX;
                    int yy = y + dy, xx = x + dx;
                    float v = 0.f;
                    if ((unsigned)yy < WX && (unsigned)xx < WX)
                        v = Xc[yy * WX + xx];
                    Bs[k][n0 + q] = f2tff(v);
                }
            } else {
                float4 x4 = *(const float4*)(Xb + (long)(k0 + k) * PP + p0 + n0);
                Bs[k][n0 + 0] = f2tff(x4.x); Bs[k][n0 + 1] = f2tff(x4.y);
                Bs[k][n0 + 2] = f2tff(x4.z); Bs[k][n0 + 3] = f2tff(x4.w);
            }
        }
        __syncthreads();

#pragma unroll
        for (int kc = 0; kc < 2; kc++) {
            unsigned af[2][4];
#pragma unroll
            for (int mt = 0; mt < 2; mt++) {
                af[mt][0] = __float_as_uint(As[kc * 8 + cA][mw + mt * 16 + r]);
                af[mt][1] = __float_as_uint(As[kc * 8 + cA][mw + mt * 16 + r + 8]);
                af[mt][2] = __float_as_uint(As[kc * 8 + cA + 4][mw + mt * 16 + r]);
                af[mt][3] = __float_as_uint(As[kc * 8 + cA + 4][mw + mt * 16 + r + 8]);
            }
#pragma unroll
            for (int nt = 0; nt < 4; nt++) {
                unsigned b0 = __float_as_uint(Bs[kc * 8 + cA][nw + nt * 8 + r]);
                unsigned b1 = __float_as_uint(Bs[kc * 8 + cA + 4][nw + nt * 8 + r]);
                mma8(acc[0][nt], af[0], b0, b1);
                mma8(acc[1][nt], af[1], b0, b1);
            }
        }
        __syncthreads();
    }

    // ---- epilogue: C[row r / r+8][2*cA, 2*cA+1] per mma tile ----
#pragma unroll
    for (int mt = 0; mt < 2; mt++) {
        int o_lo = o0 + mw + mt * 16 + r;
        int o_hi = o_lo + 8;
        float bi_lo = 0.f, bi_hi = 0.f, sc_lo = 0.f, sc_hi = 0.f, sb_lo = 0.f, sb_hi = 0.f;
        if (MODE == 0 || MODE == 1 || MODE == 3) { bi_lo = bias[o_lo]; bi_hi = bias[o_hi]; }
        if (MODE == 2) {
            sc_lo = g[o_lo] * rsqrtf(vr[o_lo] + EPS); sb_lo = bt[o_lo] - mn[o_lo] * sc_lo;
            sc_hi = g[o_hi] * rsqrtf(vr[o_hi] + EPS); sb_hi = bt[o_hi] - mn[o_hi] * sc_hi;
        }
#pragma unroll
        for (int nt = 0; nt < 4; nt++) {
            int p = p0 + nw + nt * 8 + 2 * cA;
            long oi_lo = (long)b * outB + (long)o_lo * PP + p;
            long oi_hi = (long)b * outB + (long)o_hi * PP + p;
            float2 rl, rh;
            float a0 = acc[mt][nt][0], a1 = acc[mt][nt][1];
            float a2 = acc[mt][nt][2], a3 = acc[mt][nt][3];
            if (MODE == 0) {
                rl.x = a0 + bi_lo; rl.y = a1 + bi_lo;
                rh.x = a2 + bi_hi; rh.y = a3 + bi_hi;
            } else if (MODE == 1) {
                long ai_lo = (long)b * CC * PP + (long)o_lo * PP + p;
                long ai_hi = (long)b * CC * PP + (long)o_hi * PP + p;
                float2 vl = *(const float2*)(aux + ai_lo);
                float2 vh = *(const float2*)(aux + ai_hi);
                rl.x = vl.x / (1.f + __expf(-(a0 + bi_lo)));
                rl.y = vl.y / (1.f + __expf(-(a1 + bi_lo)));
                rh.x = vh.x / (1.f + __expf(-(a2 + bi_hi)));
                rh.y = vh.y / (1.f + __expf(-(a3 + bi_hi)));
            } else if (MODE == 2) {
                float t0 = a0 * sc_lo + sb_lo, t1 = a1 * sc_lo + sb_lo;
                float t2 = a2 * sc_hi + sb_hi, t3 = a3 * sc_hi + sb_hi;
                rl.x = t0 > 0.f ? t0 : SLOPE * t0; rl.y = t1 > 0.f ? t1 : SLOPE * t1;
                rh.x = t2 > 0.f ? t2 : SLOPE * t2; rh.y = t3 > 0.f ? t3 : SLOPE * t3;
            } else {  // MODE 3
                long ai_lo = (long)b * CC * PP + (long)o_lo * PP + p;
                long ai_hi = (long)b * CC * PP + (long)o_hi * PP + p;
                float2 ql = *(const float2*)(aux + ai_lo);
                float2 qh = *(const float2*)(aux + ai_hi);
                rl.x = (a0 + bi_lo) * ql.x; rl.y = (a1 + bi_lo) * ql.y;
                rh.x = (a2 + bi_hi) * qh.x; rh.y = (a3 + bi_hi) * qh.y;
            }
            *(float2*)(out + oi_lo) = rl;
            *(float2*)(out + oi_hi) = rh;
        }
    }
}

// ---------------------------------------------------------------------------
// Flash attention with tf32 mma.sync (m16n8k8). Per block: 64 queries for one
// (b,h). 4 warps, each owns a 16-query strip. 49 key tiles of 64.
// ---------------------------------------------------------------------------
__global__ void __launch_bounds__(128)
attn_mma_k(const float* __restrict__ Q, const float* __restrict__ K,
           const float* __restrict__ V, float* __restrict__ out)
{
    __shared__ float Ks[32 * 72];
    __shared__ float Vs[32 * 72];
    __shared__ float Ps[64 * 68];   // aliased as Qs[64][36] during init

    const int tid = threadIdx.x, lane = tid & 31, w = tid >> 5;
    const int bh = blockIdx.y;
    const int b = bh >> 3, h = bh & 7;
    const long base = ((long)b * CC + h * 32) * PP;
    const float* qp = Q + base;
    const float* kp = K + base;
    const float* vp = V + base;
    const int q0 = blockIdx.x * 64;
    const float scale = 0.17677669529663687f;  // 1/sqrt(32)

    float* Qs = Ps;
    for (int i = tid; i < 512; i += 128) {
        int d = i >> 4, q4 = (i & 15) * 4;
        float4 v4 = *(const float4*)(qp + (long)d * PP + q0 + q4);
        Qs[(q4 + 0) * 36 + d] = f2tff(v4.x * scale);
        Qs[(q4 + 1) * 36 + d] = f2tff(v4.y * scale);
        Qs[(q4 + 2) * 36 + d] = f2tff(v4.z * scale);
        Qs[(q4 + 3) * 36 + d] = f2tff(v4.w * scale);
    }
    __syncthreads();

    unsigned af[4][4];
    {
        int r = w * 16 + (lane >> 2);
        int c = lane & 3;
#pragma unroll
        for (int kc = 0; kc < 4; kc++) {
            af[kc][0] = __float_as_uint(Qs[r * 36 + kc * 8 + c]);
            af[kc][1] = __float_as_uint(Qs[(r + 8) * 36 + kc * 8 + c]);
            af[kc][2] = __float_as_uint(Qs[r * 36 + kc * 8 + c + 4]);
            af[kc][3] = __float_as_uint(Qs[(r + 8) * 36 + kc * 8 + c + 4]);
        }
    }
    __syncthreads();

    float m0 = -1e30f, m1 = -1e30f, l0 = 0.f, l1 = 0.f;
    float o[4][4];
#pragma unroll
    for (int nt = 0; nt < 4; nt++)
#pragma unroll
        for (int j = 0; j < 4; j++) o[nt][j] = 0.f;

    float* Pw = Ps + w * 16 * 68;
    const int lq = lane >> 2;
    const int lr = lane & 3;

    for (int kt = 0; kt < 49; kt++) {
        const int kb = kt * 64;
        __syncthreads();
        for (int i = tid; i < 512; i += 128) {
            int d = i >> 4, k4 = (i & 15) * 4;
            float4 kv = *(const float4*)(kp + (long)d * PP + kb + k4);
            float4 vv = *(const float4*)(vp + (long)d * PP + kb + k4);
            float* kd = Ks + d * 72 + k4;
            float* vd = Vs + d * 72 + k4;
            kd[0] = f2tff(kv.x); kd[1] = f2tff(kv.y);
            kd[2] = f2tff(kv.z); kd[3] = f2tff(kv.w);
            vd[0] = f2tff(vv.x); vd[1] = f2tff(vv.y);
            vd[2] = f2tff(vv.z); vd[3] = f2tff(vv.w);
        }
        __syncthreads();

        float s[8][4];
#pragma unroll
        for (int nt = 0; nt < 8; nt++)
#pragma unroll
            for (int j = 0; j < 4; j++) s[nt][j] = 0.f;
#pragma unroll
        for (int kc = 0; kc < 4; kc++) {
#pragma unroll
            for (int nt = 0; nt < 8; nt++) {
                unsigned b0 = __float_as_uint(Ks[(kc * 8 + lr) * 72 + nt * 8 + lq]);
                unsigned b1 = __float_as_uint(Ks[(kc * 8 + lr + 4) * 72 + nt * 8 + lq]);
                mma8(s[nt], af[kc], b0, b1);
            }
        }

        float mx0 = s[0][0], mx1 = s[0][2];
#pragma unroll
        for (int nt = 0; nt < 8; nt++) {
            mx0 = fmaxf(mx0, fmaxf(s[nt][0], s[nt][1]));
            mx1 = fmaxf(mx1, fmaxf(s[nt][2], s[nt][3]));
        }
        mx0 = fmaxf(mx0, __shfl_xor_sync(0xffffffffu, mx0, 1));
        mx0 = fmaxf(mx0, __shfl_xor_sync(0xffffffffu, mx0, 2));
        mx1 = fmaxf(mx1, __shfl_xor_sync(0xffffffffu, mx1, 1));
        mx1 = fmaxf(mx1, __shfl_xor_sync(0xffffffffu, mx1, 2));
        float nm0 = fmaxf(m0, mx0), nm1 = fmaxf(m1, mx1);
        float a0 = __expf(m0 - nm0), a1 = __expf(m1 - nm1);
        m0 = nm0; m1 = nm1;

        float ps0 = 0.f, ps1 = 0.f;
#pragma unroll
        for (int nt = 0; nt < 8; nt++) {
            s[nt][0] = __expf(s[nt][0] - m0); ps0 += s[nt][0];
            s[nt][1] = __expf(s[nt][1] - m0); ps0 += s[nt][1];
            s[nt][2] = __expf(s[nt][2] - m1); ps1 += s[nt][2];
            s[nt][3] = __expf(s[nt][3] - m1); ps1 += s[nt][3];
        }
        ps0 += __shfl_xor_sync(0xffffffffu, ps0, 1);
        ps0 += __shfl_xor_sync(0xffffffffu, ps0, 2);
        ps1 += __shfl_xor_sync(0xffffffffu, ps1, 1);
        ps1 += __shfl_xor_sync(0xffffffffu, ps1, 2);
        l0 = l0 * a0 + ps0;
        l1 = l1 * a1 + ps1;
#pragma unroll
        for (int nt = 0; nt < 4; nt++) {
            o[nt][0] *= a0; o[nt][1] *= a0;
            o[nt][2] *= a1; o[nt][3] *= a1;
        }

        __syncwarp();
#pragma unroll
        for (int nt = 0; nt < 8; nt++) {
            int c = nt * 8 + lr * 2;
            Pw[lq * 68 + c]       = f2tff(s[nt][0]);
            Pw[lq * 68 + c + 1]   = f2tff(s[nt][1]);
            Pw[(lq + 8) * 68 + c]     = f2tff(s[nt][2]);
            Pw[(lq + 8) * 68 + c + 1] = f2tff(s[nt][3]);
        }
        __syncwarp();

#pragma unroll
        for (int kc = 0; kc < 8; kc++) {
            unsigned pa[4];
            pa[0] = __float_as_uint(Pw[lq * 68 + kc * 8 + lr]);
            pa[1] = __float_as_uint(Pw[(lq + 8) * 68 + kc * 8 + lr]);
            pa[2] = __float_as_uint(Pw[lq * 68 + kc * 8 + lr + 4]);
            pa[3] = __float_as_uint(Pw[(lq + 8) * 68 + kc * 8 + lr + 4]);
#pragma unroll
            for (int nt = 0; nt < 4; nt++) {
                unsigned b0 = __float_as_uint(Vs[(nt * 8 + lq) * 72 + kc * 8 + lr]);
                unsigned b1 = __float_as_uint(Vs[(nt * 8 + lq) * 72 + kc * 8 + lr + 4]);
                mma8(o[nt], pa, b0, b1);
            }
        }
    }

    float inv0 = 1.f / l0, inv1 = 1.f / l1;
    float* op = out + (long)b * (2 * CC * PP) + (long)(h * 32) * PP;
    int qr = q0 + w * 16 + lq;
#pragma unroll
    for (int nt = 0; nt < 4; nt++) {
        int d = nt * 8 + lr * 2;
        op[(long)d * PP + qr]           = o[nt][0] * inv0;
        op[(long)(d + 1) * PP + qr]     = o[nt][1] * inv0;
        op[(long)d * PP + qr + 8]       = o[nt][2] * inv1;
        op[(long)(d + 1) * PP + qr + 8] = o[nt][3] * inv1;
    }
}

// ---------------------------------------------------------------------------
// Depthwise 3x3 conv + BN1 + leaky ReLU (elementwise, L2-fed).
// ---------------------------------------------------------------------------
__global__ void __launch_bounds__(256)
dw_bn_lrelu_k(const float* __restrict__ in, const float* __restrict__ w9,
              const float* __restrict__ g, const float* __restrict__ bt,
              const float* __restrict__ mn, const float* __restrict__ vv,
              float* __restrict__ out)
{
    long idx = (long)blockIdx.x * 256 + threadIdx.x;
    if (idx >= (long)BB * CC * PP) return;
    int p = (int)(idx % PP);
    int c = (int)((idx / PP) % CC);
    int y = p / WX, x = p - y * WX;
    const float* ip = in + (idx - p);
    const float* wc = w9 + c * 9;
    float s = 0.f;
#pragma unroll
    for (int dy = -1; dy <= 1; dy++) {
        int yy = y + dy;
        if ((unsigned)yy >= WX) continue;
#pragma unroll
        for (int dx = -1; dx <= 1; dx++) {
            int xx = x + dx;
            if ((unsigned)xx >= WX) continue;
            s += wc[(dy + 1) * 3 + (dx + 1)] * ip[yy * WX + xx];
        }
    }
    float sc = g[c] * rsqrtf(vv[c] + EPS);
    float t = (s - mn[c]) * sc + bt[c];
    out[idx] = t > 0.f ? t : SLOPE * t;
}

// ---------------------------------------------------------------------------
extern "C" void kernel_launch(void* const* d_in, const int* in_sizes, int n_in,
                              void* d_out, int out_size)
{
    (void)in_sizes; (void)n_in; (void)out_size;
    const float* x    = (const float*)d_in[0];
    const float* qw   = (const float*)d_in[1];
    const float* qb   = (const float*)d_in[2];
    const float* kw   = (const float*)d_in[3];
    const float* kb   = (const float*)d_in[4];
    const float* vw   = (const float*)d_in[5];
    const float* vb   = (const float*)d_in[6];
    const float* ksw  = (const float*)d_in[7];
    const float* ksb  = (const float*)d_in[8];
    const float* sd1w = (const float*)d_in[9];
    const float* sd1b = (const float*)d_in[10];
    const float* sd2w = (const float*)d_in[11];
    const float* sd2b = (const float*)d_in[12];
    const float* dww  = (const float*)d_in[13];
    const float* bn1g = (const float*)d_in[14];
    const float* bn1b = (const float*)d_in[15];
    const float* bn1m = (const float*)d_in[16];
    const float* bn1v = (const float*)d_in[17];
    const float* pww  = (const float*)d_in[18];
    const float* bn2g = (const float*)d_in[19];
    const float* bn2b = (const float*)d_in[20];
    const float* bn2m = (const float*)d_in[21];
    const float* bn2v = (const float*)d_in[22];
    float* out = (float*)d_out;

    float* buf = nullptr;
    cudaGetSymbolAddress((void**)&buf, g_buf);
    float* Q   = buf + 0 * BUFN;
    float* Kb  = buf + 1 * BUFN;
    float* Vb  = buf + 2 * BUFN;
    float* QKs = buf + 3 * BUFN;
    float* VS  = buf + 4 * BUFN;
    float* Y   = buf + 5 * BUFN;
    float* Y2  = buf + 6 * BUFN;

    dim3 gg(PP / 64, CC / 128, BB);  // (49, 2, 2)
    const long bs = (long)CC * PP;

    // Q, K, V projections (tf32 MMA)
    mm_k<0, false><<<gg, 256>>>(qw, x, Q,  qb, nullptr, nullptr, nullptr, nullptr, nullptr, bs, CC);
    mm_k<0, false><<<gg, 256>>>(kw, x, Kb, kb, nullptr, nullptr, nullptr, nullptr, nullptr, bs, CC);
    mm_k<0, false><<<gg, 256>>>(vw, x, Vb, vb, nullptr, nullptr, nullptr, nullptr, nullptr, bs, CC);

    // flash attention (tf32 mma) -> out channels [0,256)   (only needs Q,K,V)
    attn_mma_k<<<dim3(49, 16), 128>>>(Q, Kb, Vb, out);

    // Ks 3x3 conv (implicit GEMM, tf32 MMA), fused *Q -> QKs
    mm_k<3, true><<<gg, 256>>>(ksw, x, QKs, ksb, Q, nullptr, nullptr, nullptr, nullptr, bs, CC * 9);

    // gate = sigmoid(sd1(QKs)); VS = V * gate
    mm_k<1, false><<<gg, 256>>>(sd1w, QKs, VS, sd1b, Vb, nullptr, nullptr, nullptr, nullptr, bs, CC);

    // depthwise 3x3 + BN1 + leaky -> Y
    long total = (long)BB * CC * PP;
    dw_bn_lrelu_k<<<(int)((total + 255) / 256), 256>>>(VS, dww, bn1g, bn1b, bn1m, bn1v, Y);

    // pointwise pww + BN2 + leaky -> Y2
    mm_k<2, false><<<gg, 256>>>(pww, Y, Y2, nullptr, nullptr, bn2g, bn2b, bn2m, bn2v, bs, CC);

    // sd2 projection -> out channels [256,512)
    mm_k<0, false><<<gg, 256>>>(sd2w, Y2, out + (long)CC * PP, sd2b,
                                nullptr, nullptr, nullptr, nullptr, nullptr, (long)2 * CC * PP, CC);
}

// round 7
// speedup vs baseline: 2.4378x; 1.0165x over previous
// v4: paired float2 V/P fragment layouts in attention; merged QKV launch.
#include <cuda_runtime.h>
#include <math.h>

#define PP 3136
#define CC 256
#define BB 2
#define WX 56
#define EPS 1e-5f
#define SLOPE 0.01f

// 7 scratch buffers of [B, C, HW] floats: Q, K, V, QKs, VS, Y, Y2
#define BUFN ((long)BB * CC * PP)
__device__ float g_buf[7 * BB * CC * PP];

__device__ __forceinline__ unsigned f2tf(float f) {
    unsigned u;
    asm("cvt.rna.tf32.f32 %0, %1;" : "=r"(u) : "f"(f));
    return u;
}
__device__ __forceinline__ float f2tff(float f) { return __uint_as_float(f2tf(f)); }

__device__ __forceinline__ void mma8(float* c, const unsigned* a, unsigned b0, unsigned b1) {
    asm volatile(
        "mma.sync.aligned.m16n8k8.row.col.f32.tf32.tf32.f32 "
        "{%0,%1,%2,%3}, {%4,%5,%6,%7}, {%8,%9}, {%0,%1,%2,%3};"
        : "+f"(c[0]), "+f"(c[1]), "+f"(c[2]), "+f"(c[3])
        : "r"(a[0]), "r"(a[1]), "r"(a[2]), "r"(a[3]), "r"(b0), "r"(b1));
}

// ---------------------------------------------------------------------------
// Unified tf32 tensor-core GEMM body: out[b,o,p] = sum_c W[o,c]*X[b,c,p] (+epi)
// BM=128, BN=64, BK=16. 256 threads = 8 warps in 4(m) x 2(n).
// MODE 0: +bias | 1: aux*sigmoid(+bias) | 2: BN+leaky | 3: (+bias)*aux
// ---------------------------------------------------------------------------
template <int MODE, bool CONV>
__device__ __forceinline__ void mm_body(
    const float* __restrict__ W, const float* __restrict__ X,
    float* __restrict__ out,
    const float* __restrict__ bias, const float* __restrict__ aux,
    const float* __restrict__ g, const float* __restrict__ bt,
    const float* __restrict__ mn, const float* __restrict__ vr,
    long outB, int KK, int b, int o0, int p0,
    float (*As)[136], float (*Bs)[72])
{
    const float* Xb = X + (long)b * CC * PP;
    const int tid = threadIdx.x, lane = tid & 31, w = tid >> 5;
    const int wm = w & 3, wn = w >> 2;
    const int mw = wm * 32, nw = wn * 32;
    const int r = lane >> 2, cA = lane & 3;

    float acc[2][4][4];
#pragma unroll
    for (int mt = 0; mt < 2; mt++)
#pragma unroll
        for (int nt = 0; nt < 4; nt++)
#pragma unroll
            for (int j = 0; j < 4; j++) acc[mt][nt][j] = 0.f;

    const int am = tid >> 1, akh = (tid & 1) * 8;

    for (int k0 = 0; k0 < KK; k0 += 16) {
        {
            const float* wp = W + (long)(o0 + am) * KK + k0 + akh;
            float4 wa = *(const float4*)(wp);
            float4 wb = *(const float4*)(wp + 4);
            As[akh + 0][am] = f2tff(wa.x); As[akh + 1][am] = f2tff(wa.y);
            As[akh + 2][am] = f2tff(wa.z); As[akh + 3][am] = f2tff(wa.w);
            As[akh + 4][am] = f2tff(wb.x); As[akh + 5][am] = f2tff(wb.y);
            As[akh + 6][am] = f2tff(wb.z); As[akh + 7][am] = f2tff(wb.w);
        }
        {
            int k = tid >> 4, n0 = (tid & 15) * 4;
            if (CONV) {
                int kk = k0 + k;
                int c = kk / 9, t = kk - c * 9;
                int dy = t / 3 - 1, dx = t - (t / 3) * 3 - 1;
                const float* Xc = Xb + (long)c * PP;
#pragma unroll
                for (int q = 0; q < 4; q++) {
                    int p = p0 + n0 + q;
                    int y = p / WX, x = p - y * WX;
                    int yy = y + dy, xx = x + dx;
                    float v = 0.f;
                    if ((unsigned)yy < WX && (unsigned)xx < WX)
                        v = Xc[yy * WX + xx];
                    Bs[k][n0 + q] = f2tff(v);
                }
            } else {
                float4 x4 = *(const float4*)(Xb + (long)(k0 + k) * PP + p0 + n0);
                Bs[k][n0 + 0] = f2tff(x4.x); Bs[k][n0 + 1] = f2tff(x4.y);
                Bs[k][n0 + 2] = f2tff(x4.z); Bs[k][n0 + 3] = f2tff(x4.w);
            }
        }
        __syncthreads();

#pragma unroll
        for (int kc = 0; kc < 2; kc++) {
            unsigned af[2][4];
#pragma unroll
            for (int mt = 0; mt < 2; mt++) {
                af[mt][0] = __float_as_uint(As[kc * 8 + cA][mw + mt * 16 + r]);
                af[mt][1] = __float_as_uint(As[kc * 8 + cA][mw + mt * 16 + r + 8]);
                af[mt][2] = __float_as_uint(As[kc * 8 + cA + 4][mw + mt * 16 + r]);
                af[mt][3] = __float_as_uint(As[kc * 8 + cA + 4][mw + mt * 16 + r + 8]);
            }
#pragma unroll
            for (int nt = 0; nt < 4; nt++) {
                unsigned b0 = __float_as_uint(Bs[kc * 8 + cA][nw + nt * 8 + r]);
                unsigned b1 = __float_as_uint(Bs[kc * 8 + cA + 4][nw + nt * 8 + r]);
                mma8(acc[0][nt], af[0], b0, b1);
                mma8(acc[1][nt], af[1], b0, b1);
            }
        }
        __syncthreads();
    }

#pragma unroll
    for (int mt = 0; mt < 2; mt++) {
        int o_lo = o0 + mw + mt * 16 + r;
        int o_hi = o_lo + 8;
        float bi_lo = 0.f, bi_hi = 0.f, sc_lo = 0.f, sc_hi = 0.f, sb_lo = 0.f, sb_hi = 0.f;
        if (MODE == 0 || MODE == 1 || MODE == 3) { bi_lo = bias[o_lo]; bi_hi = bias[o_hi]; }
        if (MODE == 2) {
            sc_lo = g[o_lo] * rsqrtf(vr[o_lo] + EPS); sb_lo = bt[o_lo] - mn[o_lo] * sc_lo;
            sc_hi = g[o_hi] * rsqrtf(vr[o_hi] + EPS); sb_hi = bt[o_hi] - mn[o_hi] * sc_hi;
        }
#pragma unroll
        for (int nt = 0; nt < 4; nt++) {
            int p = p0 + nw + nt * 8 + 2 * cA;
            long oi_lo = (long)b * outB + (long)o_lo * PP + p;
            long oi_hi = (long)b * outB + (long)o_hi * PP + p;
            float2 rl, rh;
            float a0 = acc[mt][nt][0], a1 = acc[mt][nt][1];
            float a2 = acc[mt][nt][2], a3 = acc[mt][nt][3];
            if (MODE == 0) {
                rl.x = a0 + bi_lo; rl.y = a1 + bi_lo;
                rh.x = a2 + bi_hi; rh.y = a3 + bi_hi;
            } else if (MODE == 1) {
                long ai_lo = (long)b * CC * PP + (long)o_lo * PP + p;
                long ai_hi = (long)b * CC * PP + (long)o_hi * PP + p;
                float2 vl = *(const float2*)(aux + ai_lo);
                float2 vh = *(const float2*)(aux + ai_hi);
                rl.x = vl.x / (1.f + __expf(-(a0 + bi_lo)));
                rl.y = vl.y / (1.f + __expf(-(a1 + bi_lo)));
                rh.x = vh.x / (1.f + __expf(-(a2 + bi_hi)));
                rh.y = vh.y / (1.f + __expf(-(a3 + bi_hi)));
            } else if (MODE == 2) {
                float t0 = a0 * sc_lo + sb_lo, t1 = a1 * sc_lo + sb_lo;
                float t2 = a2 * sc_hi + sb_hi, t3 = a3 * sc_hi + sb_hi;
                rl.x = t0 > 0.f ? t0 : SLOPE * t0; rl.y = t1 > 0.f ? t1 : SLOPE * t1;
                rh.x = t2 > 0.f ? t2 : SLOPE * t2; rh.y = t3 > 0.f ? t3 : SLOPE * t3;
            } else {
                long ai_lo = (long)b * CC * PP + (long)o_lo * PP + p;
                long ai_hi = (long)b * CC * PP + (long)o_hi * PP + p;
                float2 ql = *(const float2*)(aux + ai_lo);
                float2 qh = *(const float2*)(aux + ai_hi);
                rl.x = (a0 + bi_lo) * ql.x; rl.y = (a1 + bi_lo) * ql.y;
                rh.x = (a2 + bi_hi) * qh.x; rh.y = (a3 + bi_hi) * qh.y;
            }
            *(float2*)(out + oi_lo) = rl;
            *(float2*)(out + oi_hi) = rh;
        }
    }
}

template <int MODE, bool CONV>
__global__ void __launch_bounds__(256)
mm_k(const float* __restrict__ W, const float* __restrict__ X,
     float* __restrict__ out,
     const float* __restrict__ bias, const float* __restrict__ aux,
     const float* __restrict__ g, const float* __restrict__ bt,
     const float* __restrict__ mn, const float* __restrict__ vr,
     long outB, int KK)
{
    __shared__ float As[16][136];
    __shared__ float Bs[16][72];
    mm_body<MODE, CONV>(W, X, out, bias, aux, g, bt, mn, vr, outB, KK,
                        blockIdx.z, blockIdx.y * 128, blockIdx.x * 64, As, Bs);
}

// Merged Q/K/V projection: blockIdx.y in 0..5 selects weight + output half.
__global__ void __launch_bounds__(256)
qkv_k(const float* __restrict__ qw, const float* __restrict__ qb,
      const float* __restrict__ kw, const float* __restrict__ kb,
      const float* __restrict__ vw, const float* __restrict__ vb,
      const float* __restrict__ X,
      float* __restrict__ Q, float* __restrict__ Kb, float* __restrict__ Vb)
{
    __shared__ float As[16][136];
    __shared__ float Bs[16][72];
    const int y = blockIdx.y;
    const int sel = y >> 1;
    const float* W    = sel == 0 ? qw : (sel == 1 ? kw : vw);
    const float* bias = sel == 0 ? qb : (sel == 1 ? kb : vb);
    float* out        = sel == 0 ? Q  : (sel == 1 ? Kb : Vb);
    mm_body<0, false>(W, X, out, bias, nullptr, nullptr, nullptr, nullptr, nullptr,
                      (long)CC * PP, CC, blockIdx.z, (y & 1) * 128, blockIdx.x * 64,
                      As, Bs);
}

// ---------------------------------------------------------------------------
// Flash attention, tf32 mma. 64 queries/block, 4 warps, 49 key tiles of 64.
// K scalar layout [d][key] stride 72. V and P in paired-float2 layouts so the
// PV phase uses LDS.64 (half the LDS instruction count):
//   VP[d][j] = {V[d][8*(j/4)+(j%4)], V[d][8*(j/4)+(j%4)+4]}, stride 36 float2.
//   P same pairing along columns, per-warp region of 16 rows x 36 float2.
// ---------------------------------------------------------------------------
__global__ void __launch_bounds__(128)
attn_mma_k(const float* __restrict__ Q, const float* __restrict__ K,
           const float* __restrict__ V, float* __restrict__ out)
{
    __shared__ float  Ks[32 * 72];     // K [d][key]
    __shared__ float2 VP[32 * 36];     // V paired cols
    __shared__ float2 PPs[4 * 16 * 36];// per-warp paired P; aliased as Qs at init

    const int tid = threadIdx.x, lane = tid & 31, w = tid >> 5;
    const int bh = blockIdx.y;
    const int b = bh >> 3, h = bh & 7;
    const long base = ((long)b * CC + h * 32) * PP;
    const float* qp = Q + base;
    const float* kp = K + base;
    const float* vp = V + base;
    const int q0 = blockIdx.x * 64;
    const float scale = 0.17677669529663687f;  // 1/sqrt(32)

    // ---- Q tile into aliased smem as Qs[q][d] (pitch 36 floats) ----
    float* Qs = (float*)PPs;
    for (int i = tid; i < 512; i += 128) {
        int d = i >> 4, q4 = (i & 15) * 4;
        float4 v4 = *(const float4*)(qp + (long)d * PP + q0 + q4);
        Qs[(q4 + 0) * 36 + d] = f2tff(v4.x * scale);
        Qs[(q4 + 1) * 36 + d] = f2tff(v4.y * scale);
        Qs[(q4 + 2) * 36 + d] = f2tff(v4.z * scale);
        Qs[(q4 + 3) * 36 + d] = f2tff(v4.w * scale);
    }
    __syncthreads();

    unsigned af[4][4];
    {
        int rr = w * 16 + (lane >> 2);
        int c = lane & 3;
#pragma unroll
        for (int kc = 0; kc < 4; kc++) {
            af[kc][0] = __float_as_uint(Qs[rr * 36 + kc * 8 + c]);
            af[kc][1] = __float_as_uint(Qs[(rr + 8) * 36 + kc * 8 + c]);
            af[kc][2] = __float_as_uint(Qs[rr * 36 + kc * 8 + c + 4]);
            af[kc][3] = __float_as_uint(Qs[(rr + 8) * 36 + kc * 8 + c + 4]);
        }
    }
    __syncthreads();  // PPs region now free for P use

    float m0 = -1e30f, m1 = -1e30f, l0 = 0.f, l1 = 0.f;
    float o[4][4];
#pragma unroll
    for (int nt = 0; nt < 4; nt++)
#pragma unroll
        for (int j = 0; j < 4; j++) o[nt][j] = 0.f;

    float* Pw = (float*)PPs + w * 16 * 72;  // this warp's paired-P region
    const int lq = lane >> 2;
    const int lr = lane & 3;
    // paired-column write offsets for this lane's S fragment columns (2lr, 2lr+1)
    const int cbase = 2 * ((2 * lr) & 3) + (lr >> 1);

    for (int kt = 0; kt < 49; kt++) {
        const int kb = kt * 64;
        __syncthreads();
        for (int i = tid; i < 512; i += 128) {
            int d = i >> 4, k4 = (i & 15) * 4;
            float4 kv = *(const float4*)(kp + (long)d * PP + kb + k4);
            float4 vv = *(const float4*)(vp + (long)d * PP + kb + k4);
            float* kd = Ks + d * 72 + k4;
            kd[0] = f2tff(kv.x); kd[1] = f2tff(kv.y);
            kd[2] = f2tff(kv.z); kd[3] = f2tff(kv.w);
            // paired V: float index d*72 + (k4/8)*8 + ((k4/4)&1) + 2j
            float* vf = (float*)VP + d * 72 + (k4 >> 3) * 8 + ((k4 >> 2) & 1);
            vf[0] = f2tff(vv.x); vf[2] = f2tff(vv.y);
            vf[4] = f2tff(vv.z); vf[6] = f2tff(vv.w);
        }
        __syncthreads();

        // ---- S = Q @ K ----
        float s[8][4];
#pragma unroll
        for (int nt = 0; nt < 8; nt++)
#pragma unroll
            for (int j = 0; j < 4; j++) s[nt][j] = 0.f;
#pragma unroll
        for (int kc = 0; kc < 4; kc++) {
#pragma unroll
            for (int nt = 0; nt < 8; nt++) {
                unsigned b0 = __float_as_uint(Ks[(kc * 8 + lr) * 72 + nt * 8 + lq]);
                unsigned b1 = __float_as_uint(Ks[(kc * 8 + lr + 4) * 72 + nt * 8 + lq]);
                mma8(s[nt], af[kc], b0, b1);
            }
        }

        // ---- online softmax ----
        float mx0 = s[0][0], mx1 = s[0][2];
#pragma unroll
        for (int nt = 0; nt < 8; nt++) {
            mx0 = fmaxf(mx0, fmaxf(s[nt][0], s[nt][1]));
            mx1 = fmaxf(mx1, fmaxf(s[nt][2], s[nt][3]));
        }
        mx0 = fmaxf(mx0, __shfl_xor_sync(0xffffffffu, mx0, 1));
        mx0 = fmaxf(mx0, __shfl_xor_sync(0xffffffffu, mx0, 2));
        mx1 = fmaxf(mx1, __shfl_xor_sync(0xffffffffu, mx1, 1));
        mx1 = fmaxf(mx1, __shfl_xor_sync(0xffffffffu, mx1, 2));
        float nm0 = fmaxf(m0, mx0), nm1 = fmaxf(m1, mx1);
        float a0 = __expf(m0 - nm0), a1 = __expf(m1 - nm1);
        m0 = nm0; m1 = nm1;

        float ps0 = 0.f, ps1 = 0.f;
#pragma unroll
        for (int nt = 0; nt < 8; nt++) {
            s[nt][0] = __expf(s[nt][0] - m0); ps0 += s[nt][0];
            s[nt][1] = __expf(s[nt][1] - m0); ps0 += s[nt][1];
            s[nt][2] = __expf(s[nt][2] - m1); ps1 += s[nt][2];
            s[nt][3] = __expf(s[nt][3] - m1); ps1 += s[nt][3];
        }
        ps0 += __shfl_xor_sync(0xffffffffu, ps0, 1);
        ps0 += __shfl_xor_sync(0xffffffffu, ps0, 2);
        ps1 += __shfl_xor_sync(0xffffffffu, ps1, 1);
        ps1 += __shfl_xor_sync(0xffffffffu, ps1, 2);
        l0 = l0 * a0 + ps0;
        l1 = l1 * a1 + ps1;
#pragma unroll
        for (int nt = 0; nt < 4; nt++) {
            o[nt][0] *= a0; o[nt][1] *= a0;
            o[nt][2] *= a1; o[nt][3] *= a1;
        }

        // ---- write P (tf32) into paired-column per-warp smem ----
        __syncwarp();
#pragma unroll
        for (int nt = 0; nt < 8; nt++) {
            float* pr = Pw + lq * 72 + nt * 8 + cbase;
            pr[0] = f2tff(s[nt][0]);
            pr[2] = f2tff(s[nt][1]);
            float* pr2 = pr + 8 * 72;
            pr2[0] = f2tff(s[nt][2]);
            pr2[2] = f2tff(s[nt][3]);
        }
        __syncwarp();

        // ---- O += P @ V (paired LDS.64 fragments) ----
#pragma unroll
        for (int kc = 0; kc < 8; kc++) {
            unsigned pa[4];
            float2 plo = *(const float2*)(Pw + lq * 72 + kc * 8 + 2 * lr);
            float2 phi = *(const float2*)(Pw + (lq + 8) * 72 + kc * 8 + 2 * lr);
            pa[0] = __float_as_uint(plo.x); pa[1] = __float_as_uint(phi.x);
            pa[2] = __float_as_uint(plo.y); pa[3] = __float_as_uint(phi.y);
#pragma unroll
            for (int nt = 0; nt < 4; nt++) {
                float2 v2 = VP[(nt * 8 + lq) * 36 + kc * 4 + lr];
                mma8(o[nt], pa, __float_as_uint(v2.x), __float_as_uint(v2.y));
            }
        }
    }

    float inv0 = 1.f / l0, inv1 = 1.f / l1;
    float* op = out + (long)b * (2 * CC * PP) + (long)(h * 32) * PP;
    int qr = q0 + w * 16 + lq;
#pragma unroll
    for (int nt = 0; nt < 4; nt++) {
        int d = nt * 8 + lr * 2;
        op[(long)d * PP + qr]           = o[nt][0] * inv0;
        op[(long)(d + 1) * PP + qr]     = o[nt][1] * inv0;
        op[(long)d * PP + qr + 8]       = o[nt][2] * inv1;
        op[(long)(d + 1) * PP + qr + 8] = o[nt][3] * inv1;
    }
}

// ---------------------------------------------------------------------------
// Depthwise 3x3 conv + BN1 + leaky ReLU (elementwise).
// ---------------------------------------------------------------------------
__global__ void __launch_bounds__(256)
dw_bn_lrelu_k(const float* __restrict__ in, const float* __restrict__ w9,
              const float* __restrict__ g, const float* __restrict__ bt,
              const float* __restrict__ mn, const float* __restrict__ vv,
              float* __restrict__ out)
{
    long idx = (long)blockIdx.x * 256 + threadIdx.x;
    if (idx >= (long)BB * CC * PP) return;
    int p = (int)(idx % PP);
    int c = (int)((idx / PP) % CC);
    int y = p / WX, x = p - y * WX;
    const float* ip = in + (idx - p);
    const float* wc = w9 + c * 9;
    float s = 0.f;
#pragma unroll
    for (int dy = -1; dy <= 1; dy++) {
        int yy = y + dy;
        if ((unsigned)yy >= WX) continue;
#pragma unroll
        for (int dx = -1; dx <= 1; dx++) {
            int xx = x + dx;
            if ((unsigned)xx >= WX) continue;
            s += wc[(dy + 1) * 3 + (dx + 1)] * ip[yy * WX + xx];
        }
    }
    float sc = g[c] * rsqrtf(vv[c] + EPS);
    float t = (s - mn[c]) * sc + bt[c];
    out[idx] = t > 0.f ? t : SLOPE * t;
}

// ---------------------------------------------------------------------------
extern "C" void kernel_launch(void* const* d_in, const int* in_sizes, int n_in,
                              void* d_out, int out_size)
{
    (void)in_sizes; (void)n_in; (void)out_size;
    const float* x    = (const float*)d_in[0];
    const float* qw   = (const float*)d_in[1];
    const float* qb   = (const float*)d_in[2];
    const float* kw   = (const float*)d_in[3];
    const float* kb   = (const float*)d_in[4];
    const float* vw   = (const float*)d_in[5];
    const float* vb   = (const float*)d_in[6];
    const float* ksw  = (const float*)d_in[7];
    const float* ksb  = (const float*)d_in[8];
    const float* sd1w = (const float*)d_in[9];
    const float* sd1b = (const float*)d_in[10];
    const float* sd2w = (const float*)d_in[11];
    const float* sd2b = (const float*)d_in[12];
    const float* dww  = (const float*)d_in[13];
    const float* bn1g = (const float*)d_in[14];
    const float* bn1b = (const float*)d_in[15];
    const float* bn1m = (const float*)d_in[16];
    const float* bn1v = (const float*)d_in[17];
    const float* pww  = (const float*)d_in[18];
    const float* bn2g = (const float*)d_in[19];
    const float* bn2b = (const float*)d_in[20];
    const float* bn2m = (const float*)d_in[21];
    const float* bn2v = (const float*)d_in[22];
    float* out = (float*)d_out;

    float* buf = nullptr;
    cudaGetSymbolAddress((void**)&buf, g_buf);
    float* Q   = buf + 0 * BUFN;
    float* Kb  = buf + 1 * BUFN;
    float* Vb  = buf + 2 * BUFN;
    float* QKs = buf + 3 * BUFN;
    float* VS  = buf + 4 * BUFN;
    float* Y   = buf + 5 * BUFN;
    float* Y2  = buf + 6 * BUFN;

    dim3 gg(PP / 64, CC / 128, BB);   // (49, 2, 2)
    const long bs = (long)CC * PP;

    // merged Q, K, V projections
    qkv_k<<<dim3(PP / 64, 6, BB), 256>>>(qw, qb, kw, kb, vw, vb, x, Q, Kb, Vb);

    // flash attention -> out channels [0,256)
    attn_mma_k<<<dim3(49, 16), 128>>>(Q, Kb, Vb, out);

    // Ks 3x3 conv (implicit GEMM), fused *Q -> QKs
    mm_k<3, true><<<gg, 256>>>(ksw, x, QKs, ksb, Q, nullptr, nullptr, nullptr, nullptr, bs, CC * 9);

    // gate = sigmoid(sd1(QKs)); VS = V * gate
    mm_k<1, false><<<gg, 256>>>(sd1w, QKs, VS, sd1b, Vb, nullptr, nullptr, nullptr, nullptr, bs, CC);

    // depthwise 3x3 + BN1 + leaky -> Y
    long total = (long)BB * CC * PP;
    dw_bn_lrelu_k<<<(int)((total + 255) / 256), 256>>>(VS, dww, bn1g, bn1b, bn1m, bn1v, Y);

    // pointwise pww + BN2 + leaky -> Y2
    mm_k<2, false><<<gg, 256>>>(pww, Y, Y2, nullptr, nullptr, bn2g, bn2b, bn2m, bn2v, bs, CC);

    // sd2 projection -> out channels [256,512)
    mm_k<0, false><<<gg, 256>>>(sd2w, Y2, out + (long)CC * PP, sd2b,
                                nullptr, nullptr, nullptr, nullptr, nullptr, (long)2 * CC * PP, CC);
}

// round 9
// speedup vs baseline: 2.7736x; 1.1378x over previous
// v5: register double-buffered tile loads in attention + all GEMMs.
#include <cuda_runtime.h>
#include <math.h>

#define PP 3136
#define CC 256
#define BB 2
#define WX 56
#define EPS 1e-5f
#define SLOPE 0.01f

#define BUFN ((long)BB * CC * PP)
__device__ float g_buf[7 * BB * CC * PP];

__device__ __forceinline__ unsigned f2tf(float f) {
    unsigned u;
    asm("cvt.rna.tf32.f32 %0, %1;" : "=r"(u) : "f"(f));
    return u;
}
__device__ __forceinline__ float f2tff(float f) { return __uint_as_float(f2tf(f)); }

__device__ __forceinline__ void mma8(float* c, const unsigned* a, unsigned b0, unsigned b1) {
    asm volatile(
        "mma.sync.aligned.m16n8k8.row.col.f32.tf32.tf32.f32 "
        "{%0,%1,%2,%3}, {%4,%5,%6,%7}, {%8,%9}, {%0,%1,%2,%3};"
        : "+f"(c[0]), "+f"(c[1]), "+f"(c[2]), "+f"(c[3])
        : "r"(a[0]), "r"(a[1]), "r"(a[2]), "r"(a[3]), "r"(b0), "r"(b1));
}

// ---------------------------------------------------------------------------
// Unified tf32 GEMM body, register double-buffered.
// out[b,o,p] = sum_c W[o,c]*X[b,c,p] (+epi). BM=128,BN=64,BK=16, 8 warps.
// MODE 0: +bias | 1: aux*sigmoid(+bias) | 2: BN+leaky | 3: (+bias)*aux
// ---------------------------------------------------------------------------
template <int MODE, bool CONV>
__device__ __forceinline__ void mm_body(
    const float* __restrict__ W, const float* __restrict__ X,
    float* __restrict__ out,
    const float* __restrict__ bias, const float* __restrict__ aux,
    const float* __restrict__ g, const float* __restrict__ bt,
    const float* __restrict__ mn, const float* __restrict__ vr,
    long outB, int KK, int b, int o0, int p0,
    float (*As)[136], float (*Bs)[72])
{
    const float* Xb = X + (long)b * CC * PP;
    const int tid = threadIdx.x, lane = tid & 31, w = tid >> 5;
    const int wm = w & 3, wn = w >> 2;
    const int mw = wm * 32, nw = wn * 32;
    const int r = lane >> 2, cA = lane & 3;

    float acc[2][4][4];
#pragma unroll
    for (int mt = 0; mt < 2; mt++)
#pragma unroll
        for (int nt = 0; nt < 4; nt++)
#pragma unroll
            for (int j = 0; j < 4; j++) acc[mt][nt][j] = 0.f;

    const int am = tid >> 1, akh = (tid & 1) * 8;
    const int bk = tid >> 4, bn0 = (tid & 15) * 4;

    float ast[8], bst[4];

    // loader: fills ast/bst (tf32-converted) for k-slab k0
    auto load_slab = [&](int k0) {
        const float* wp = W + (long)(o0 + am) * KK + k0 + akh;
        float4 wa = *(const float4*)(wp);
        float4 wb = *(const float4*)(wp + 4);
        ast[0] = f2tff(wa.x); ast[1] = f2tff(wa.y);
        ast[2] = f2tff(wa.z); ast[3] = f2tff(wa.w);
        ast[4] = f2tff(wb.x); ast[5] = f2tff(wb.y);
        ast[6] = f2tff(wb.z); ast[7] = f2tff(wb.w);
        if (CONV) {
            int kk = k0 + bk;
            int c = kk / 9, t = kk - c * 9;
            int dy = t / 3 - 1, dx = t - (t / 3) * 3 - 1;
            const float* Xc = Xb + (long)c * PP;
#pragma unroll
            for (int q = 0; q < 4; q++) {
                int p = p0 + bn0 + q;
                int y = p / WX, x = p - y * WX;
                int yy = y + dy, xx = x + dx;
                float v = 0.f;
                if ((unsigned)yy < WX && (unsigned)xx < WX)
                    v = Xc[yy * WX + xx];
                bst[q] = f2tff(v);
            }
        } else {
            float4 x4 = *(const float4*)(Xb + (long)(k0 + bk) * PP + p0 + bn0);
            bst[0] = f2tff(x4.x); bst[1] = f2tff(x4.y);
            bst[2] = f2tff(x4.z); bst[3] = f2tff(x4.w);
        }
    };

    load_slab(0);

    for (int k0 = 0; k0 < KK; k0 += 16) {
        __syncthreads();
        // store staged slab to smem
        As[akh + 0][am] = ast[0]; As[akh + 1][am] = ast[1];
        As[akh + 2][am] = ast[2]; As[akh + 3][am] = ast[3];
        As[akh + 4][am] = ast[4]; As[akh + 5][am] = ast[5];
        As[akh + 6][am] = ast[6]; As[akh + 7][am] = ast[7];
        *(float4*)&Bs[bk][bn0] = make_float4(bst[0], bst[1], bst[2], bst[3]);
        __syncthreads();
        // prefetch next slab (in flight during MMA below)
        if (k0 + 16 < KK) load_slab(k0 + 16);

#pragma unroll
        for (int kc = 0; kc < 2; kc++) {
            unsigned af[2][4];
#pragma unroll
            for (int mt = 0; mt < 2; mt++) {
                af[mt][0] = __float_as_uint(As[kc * 8 + cA][mw + mt * 16 + r]);
                af[mt][1] = __float_as_uint(As[kc * 8 + cA][mw + mt * 16 + r + 8]);
                af[mt][2] = __float_as_uint(As[kc * 8 + cA + 4][mw + mt * 16 + r]);
                af[mt][3] = __float_as_uint(As[kc * 8 + cA + 4][mw + mt * 16 + r + 8]);
            }
#pragma unroll
            for (int nt = 0; nt < 4; nt++) {
                unsigned b0 = __float_as_uint(Bs[kc * 8 + cA][nw + nt * 8 + r]);
                unsigned b1 = __float_as_uint(Bs[kc * 8 + cA + 4][nw + nt * 8 + r]);
                mma8(acc[0][nt], af[0], b0, b1);
                mma8(acc[1][nt], af[1], b0, b1);
            }
        }
    }

#pragma unroll
    for (int mt = 0; mt < 2; mt++) {
        int o_lo = o0 + mw + mt * 16 + r;
        int o_hi = o_lo + 8;
        float bi_lo = 0.f, bi_hi = 0.f, sc_lo = 0.f, sc_hi = 0.f, sb_lo = 0.f, sb_hi = 0.f;
        if (MODE == 0 || MODE == 1 || MODE == 3) { bi_lo = bias[o_lo]; bi_hi = bias[o_hi]; }
        if (MODE == 2) {
            sc_lo = g[o_lo] * rsqrtf(vr[o_lo] + EPS); sb_lo = bt[o_lo] - mn[o_lo] * sc_lo;
            sc_hi = g[o_hi] * rsqrtf(vr[o_hi] + EPS); sb_hi = bt[o_hi] - mn[o_hi] * sc_hi;
        }
#pragma unroll
        for (int nt = 0; nt < 4; nt++) {
            int p = p0 + nw + nt * 8 + 2 * cA;
            long oi_lo = (long)b * outB + (long)o_lo * PP + p;
            long oi_hi = (long)b * outB + (long)o_hi * PP + p;
            float2 rl, rh;
            float a0 = acc[mt][nt][0], a1 = acc[mt][nt][1];
            float a2 = acc[mt][nt][2], a3 = acc[mt][nt][3];
            if (MODE == 0) {
                rl.x = a0 + bi_lo; rl.y = a1 + bi_lo;
                rh.x = a2 + bi_hi; rh.y = a3 + bi_hi;
            } else if (MODE == 1) {
                long ai_lo = (long)b * CC * PP + (long)o_lo * PP + p;
                long ai_hi = (long)b * CC * PP + (long)o_hi * PP + p;
                float2 vl = *(const float2*)(aux + ai_lo);
                float2 vh = *(const float2*)(aux + ai_hi);
                rl.x = vl.x / (1.f + __expf(-(a0 + bi_lo)));
                rl.y = vl.y / (1.f + __expf(-(a1 + bi_lo)));
                rh.x = vh.x / (1.f + __expf(-(a2 + bi_hi)));
                rh.y = vh.y / (1.f + __expf(-(a3 + bi_hi)));
            } else if (MODE == 2) {
                float t0 = a0 * sc_lo + sb_lo, t1 = a1 * sc_lo + sb_lo;
                float t2 = a2 * sc_hi + sb_hi, t3 = a3 * sc_hi + sb_hi;
                rl.x = t0 > 0.f ? t0 : SLOPE * t0; rl.y = t1 > 0.f ? t1 : SLOPE * t1;
                rh.x = t2 > 0.f ? t2 : SLOPE * t2; rh.y = t3 > 0.f ? t3 : SLOPE * t3;
            } else {
                long ai_lo = (long)b * CC * PP + (long)o_lo * PP + p;
                long ai_hi = (long)b * CC * PP + (long)o_hi * PP + p;
                float2 ql = *(const float2*)(aux + ai_lo);
                float2 qh = *(const float2*)(aux + ai_hi);
                rl.x = (a0 + bi_lo) * ql.x; rl.y = (a1 + bi_lo) * ql.y;
                rh.x = (a2 + bi_hi) * qh.x; rh.y = (a3 + bi_hi) * qh.y;
            }
            *(float2*)(out + oi_lo) = rl;
            *(float2*)(out + oi_hi) = rh;
        }
    }
}

template <int MODE, bool CONV>
__global__ void __launch_bounds__(256)
mm_k(const float* __restrict__ W, const float* __restrict__ X,
     float* __restrict__ out,
     const float* __restrict__ bias, const float* __restrict__ aux,
     const float* __restrict__ g, const float* __restrict__ bt,
     const float* __restrict__ mn, const float* __restrict__ vr,
     long outB, int KK)
{
    __shared__ float As[16][136];
    __shared__ float Bs[16][72];
    mm_body<MODE, CONV>(W, X, out, bias, aux, g, bt, mn, vr, outB, KK,
                        blockIdx.z, blockIdx.y * 128, blockIdx.x * 64, As, Bs);
}

// Merged Q/K/V projection: blockIdx.y in 0..5 selects weight + output half.
__global__ void __launch_bounds__(256)
qkv_k(const float* __restrict__ qw, const float* __restrict__ qb,
      const float* __restrict__ kw, const float* __restrict__ kb,
      const float* __restrict__ vw, const float* __restrict__ vb,
      const float* __restrict__ X,
      float* __restrict__ Q, float* __restrict__ Kb, float* __restrict__ Vb)
{
    __shared__ float As[16][136];
    __shared__ float Bs[16][72];
    const int y = blockIdx.y;
    const int sel = y >> 1;
    const float* W    = sel == 0 ? qw : (sel == 1 ? kw : vw);
    const float* bias = sel == 0 ? qb : (sel == 1 ? kb : vb);
    float* out        = sel == 0 ? Q  : (sel == 1 ? Kb : Vb);
    mm_body<0, false>(W, X, out, bias, nullptr, nullptr, nullptr, nullptr, nullptr,
                      (long)CC * PP, CC, blockIdx.z, (y & 1) * 128, blockIdx.x * 64,
                      As, Bs);
}

// ---------------------------------------------------------------------------
// Flash attention, tf32 mma, register double-buffered K/V tile loads.
// 64 queries/block, 4 warps, 49 key tiles of 64. K [d][key] stride 72;
// V & P paired-float2 layouts (LDS.64 fragments).
// ---------------------------------------------------------------------------
__global__ void __launch_bounds__(128)
attn_mma_k(const float* __restrict__ Q, const float* __restrict__ K,
           const float* __restrict__ V, float* __restrict__ out)
{
    __shared__ float  Ks[32 * 72];
    __shared__ float2 VP[32 * 36];
    __shared__ float2 PPs[4 * 16 * 36];

    const int tid = threadIdx.x, lane = tid & 31, w = tid >> 5;
    const int bh = blockIdx.y;
    const int b = bh >> 3, h = bh & 7;
    const long base = ((long)b * CC + h * 32) * PP;
    const float* qp = Q + base;
    const float* kp = K + base;
    const float* vp = V + base;
    const int q0 = blockIdx.x * 64;
    const float scale = 0.17677669529663687f;

    // staged next-tile registers (4 slabs of K + V float4 each)
    uint4 kst[4], vst[4];
    auto load_tile = [&](int kb) {
#pragma unroll
        for (int j = 0; j < 4; j++) {
            int i = tid + j * 128;
            int d = i >> 4, k4 = (i & 15) * 4;
            float4 kv = *(const float4*)(kp + (long)d * PP + kb + k4);
            float4 vv = *(const float4*)(vp + (long)d * PP + kb + k4);
            kst[j] = make_uint4(f2tf(kv.x), f2tf(kv.y), f2tf(kv.z), f2tf(kv.w));
            vst[j] = make_uint4(f2tf(vv.x), f2tf(vv.y), f2tf(vv.z), f2tf(vv.w));
        }
    };

    load_tile(0);   // prologue: tile 0 in flight during Q setup

    // ---- Q tile into aliased smem as Qs[q][d] (pitch 36 floats) ----
    float* Qs = (float*)PPs;
    for (int i = tid; i < 512; i += 128) {
        int d = i >> 4, q4 = (i & 15) * 4;
        float4 v4 = *(const float4*)(qp + (long)d * PP + q0 + q4);
        Qs[(q4 + 0) * 36 + d] = f2tff(v4.x * scale);
        Qs[(q4 + 1) * 36 + d] = f2tff(v4.y * scale);
        Qs[(q4 + 2) * 36 + d] = f2tff(v4.z * scale);
        Qs[(q4 + 3) * 36 + d] = f2tff(v4.w * scale);
    }
    __syncthreads();

    unsigned af[4][4];
    {
        int rr = w * 16 + (lane >> 2);
        int c = lane & 3;
#pragma unroll
        for (int kc = 0; kc < 4; kc++) {
            af[kc][0] = __float_as_uint(Qs[rr * 36 + kc * 8 + c]);
            af[kc][1] = __float_as_uint(Qs[(rr + 8) * 36 + kc * 8 + c]);
            af[kc][2] = __float_as_uint(Qs[rr * 36 + kc * 8 + c + 4]);
            af[kc][3] = __float_as_uint(Qs[(rr + 8) * 36 + kc * 8 + c + 4]);
        }
    }
    __syncthreads();  // PPs region now free for P use

    float m0 = -1e30f, m1 = -1e30f, l0 = 0.f, l1 = 0.f;
    float o[4][4];
#pragma unroll
    for (int nt = 0; nt < 4; nt++)
#pragma unroll
        for (int j = 0; j < 4; j++) o[nt][j] = 0.f;

    float* Pw = (float*)PPs + w * 16 * 72;
    const int lq = lane >> 2;
    const int lr = lane & 3;
    const int cbase = 2 * ((2 * lr) & 3) + (lr >> 1);

    for (int kt = 0; kt < 49; kt++) {
        __syncthreads();
        // store staged tile to smem
#pragma unroll
        for (int j = 0; j < 4; j++) {
            int i = tid + j * 128;
            int d = i >> 4, k4 = (i & 15) * 4;
            *(uint4*)(Ks + d * 72 + k4) = kst[j];
            float* vf = (float*)VP + d * 72 + (k4 >> 3) * 8 + ((k4 >> 2) & 1);
            vf[0] = __uint_as_float(vst[j].x); vf[2] = __uint_as_float(vst[j].y);
            vf[4] = __uint_as_float(vst[j].z); vf[6] = __uint_as_float(vst[j].w);
        }
        __syncthreads();
        // prefetch next tile (in flight during the whole compute below)
        if (kt < 48) load_tile((kt + 1) * 64);

        // ---- S = Q @ K ----
        float s[8][4];
#pragma unroll
        for (int nt = 0; nt < 8; nt++)
#pragma unroll
            for (int j = 0; j < 4; j++) s[nt][j] = 0.f;
#pragma unroll
        for (int kc = 0; kc < 4; kc++) {
#pragma unroll
            for (int nt = 0; nt < 8; nt++) {
                unsigned b0 = __float_as_uint(Ks[(kc * 8 + lr) * 72 + nt * 8 + lq]);
                unsigned b1 = __float_as_uint(Ks[(kc * 8 + lr + 4) * 72 + nt * 8 + lq]);
                mma8(s[nt], af[kc], b0, b1);
            }
        }

        // ---- online softmax ----
        float mx0 = s[0][0], mx1 = s[0][2];
#pragma unroll
        for (int nt = 0; nt < 8; nt++) {
            mx0 = fmaxf(mx0, fmaxf(s[nt][0], s[nt][1]));
            mx1 = fmaxf(mx1, fmaxf(s[nt][2], s[nt][3]));
        }
        mx0 = fmaxf(mx0, __shfl_xor_sync(0xffffffffu, mx0, 1));
        mx0 = fmaxf(mx0, __shfl_xor_sync(0xffffffffu, mx0, 2));
        mx1 = fmaxf(mx1, __shfl_xor_sync(0xffffffffu, mx1, 1));
        mx1 = fmaxf(mx1, __shfl_xor_sync(0xffffffffu, mx1, 2));
        float nm0 = fmaxf(m0, mx0), nm1 = fmaxf(m1, mx1);
        float a0 = __expf(m0 - nm0), a1 = __expf(m1 - nm1);
        m0 = nm0; m1 = nm1;

        float ps0 = 0.f, ps1 = 0.f;
#pragma unroll
        for (int nt = 0; nt < 8; nt++) {
            s[nt][0] = __expf(s[nt][0] - m0); ps0 += s[nt][0];
            s[nt][1] = __expf(s[nt][1] - m0); ps0 += s[nt][1];
            s[nt][2] = __expf(s[nt][2] - m1); ps1 += s[nt][2];
            s[nt][3] = __expf(s[nt][3] - m1); ps1 += s[nt][3];
        }
        ps0 += __shfl_xor_sync(0xffffffffu, ps0, 1);
        ps0 += __shfl_xor_sync(0xffffffffu, ps0, 2);
        ps1 += __shfl_xor_sync(0xffffffffu, ps1, 1);
        ps1 += __shfl_xor_sync(0xffffffffu, ps1, 2);
        l0 = l0 * a0 + ps0;
        l1 = l1 * a1 + ps1;
#pragma unroll
        for (int nt = 0; nt < 4; nt++) {
            o[nt][0] *= a0; o[nt][1] *= a0;
            o[nt][2] *= a1; o[nt][3] *= a1;
        }

        // ---- write P (tf32) into paired-column per-warp smem ----
        __syncwarp();
#pragma unroll
        for (int nt = 0; nt < 8; nt++) {
            float* pr = Pw + lq * 72 + nt * 8 + cbase;
            pr[0] = f2tff(s[nt][0]);
            pr[2] = f2tff(s[nt][1]);
            float* pr2 = pr + 8 * 72;
            pr2[0] = f2tff(s[nt][2]);
            pr2[2] = f2tff(s[nt][3]);
        }
        __syncwarp();

        // ---- O += P @ V (paired LDS.64 fragments) ----
#pragma unroll
        for (int kc = 0; kc < 8; kc++) {
            unsigned pa[4];
            float2 plo = *(const float2*)(Pw + lq * 72 + kc * 8 + 2 * lr);
            float2 phi = *(const float2*)(Pw + (lq + 8) * 72 + kc * 8 + 2 * lr);
            pa[0] = __float_as_uint(plo.x); pa[1] = __float_as_uint(phi.x);
            pa[2] = __float_as_uint(plo.y); pa[3] = __float_as_uint(phi.y);
#pragma unroll
            for (int nt = 0; nt < 4; nt++) {
                float2 v2 = VP[(nt * 8 + lq) * 36 + kc * 4 + lr];
                mma8(o[nt], pa, __float_as_uint(v2.x), __float_as_uint(v2.y));
            }
        }
    }

    float inv0 = 1.f / l0, inv1 = 1.f / l1;
    float* op = out + (long)b * (2 * CC * PP) + (long)(h * 32) * PP;
    int qr = q0 + w * 16 + lq;
#pragma unroll
    for (int nt = 0; nt < 4; nt++) {
        int d = nt * 8 + lr * 2;
        op[(long)d * PP + qr]           = o[nt][0] * inv0;
        op[(long)(d + 1) * PP + qr]     = o[nt][1] * inv0;
        op[(long)d * PP + qr + 8]       = o[nt][2] * inv1;
        op[(long)(d + 1) * PP + qr + 8] = o[nt][3] * inv1;
    }
}

// ---------------------------------------------------------------------------
// Depthwise 3x3 conv + BN1 + leaky ReLU (elementwise).
// ---------------------------------------------------------------------------
__global__ void __launch_bounds__(256)
dw_bn_lrelu_k(const float* __restrict__ in, const float* __restrict__ w9,
              const float* __restrict__ g, const float* __restrict__ bt,
              const float* __restrict__ mn, const float* __restrict__ vv,
              float* __restrict__ out)
{
    long idx = (long)blockIdx.x * 256 + threadIdx.x;
    if (idx >= (long)BB * CC * PP) return;
    int p = (int)(idx % PP);
    int c = (int)((idx / PP) % CC);
    int y = p / WX, x = p - y * WX;
    const float* ip = in + (idx - p);
    const float* wc = w9 + c * 9;
    float s = 0.f;
#pragma unroll
    for (int dy = -1; dy <= 1; dy++) {
        int yy = y + dy;
        if ((unsigned)yy >= WX) continue;
#pragma unroll
        for (int dx = -1; dx <= 1; dx++) {
            int xx = x + dx;
            if ((unsigned)xx >= WX) continue;
            s += wc[(dy + 1) * 3 + (dx + 1)] * ip[yy * WX + xx];
        }
    }
    float sc = g[c] * rsqrtf(vv[c] + EPS);
    float t = (s - mn[c]) * sc + bt[c];
    out[idx] = t > 0.f ? t : SLOPE * t;
}

// ---------------------------------------------------------------------------
extern "C" void kernel_launch(void* const* d_in, const int* in_sizes, int n_in,
                              void* d_out, int out_size)
{
    (void)in_sizes; (void)n_in; (void)out_size;
    const float* x    = (const float*)d_in[0];
    const float* qw   = (const float*)d_in[1];
    const float* qb   = (const float*)d_in[2];
    const float* kw   = (const float*)d_in[3];
    const float* kb   = (const float*)d_in[4];
    const float* vw   = (const float*)d_in[5];
    const float* vb   = (const float*)d_in[6];
    const float* ksw  = (const float*)d_in[7];
    const float* ksb  = (const float*)d_in[8];
    const float* sd1w = (const float*)d_in[9];
    const float* sd1b = (const float*)d_in[10];
    const float* sd2w = (const float*)d_in[11];
    const float* sd2b = (const float*)d_in[12];
    const float* dww  = (const float*)d_in[13];
    const float* bn1g = (const float*)d_in[14];
    const float* bn1b = (const float*)d_in[15];
    const float* bn1m = (const float*)d_in[16];
    const float* bn1v = (const float*)d_in[17];
    const float* pww  = (const float*)d_in[18];
    const float* bn2g = (const float*)d_in[19];
    const float* bn2b = (const float*)d_in[20];
    const float* bn2m = (const float*)d_in[21];
    const float* bn2v = (const float*)d_in[22];
    float* out = (float*)d_out;

    float* buf = nullptr;
    cudaGetSymbolAddress((void**)&buf, g_buf);
    float* Q   = buf + 0 * BUFN;
    float* Kb  = buf + 1 * BUFN;
    float* Vb  = buf + 2 * BUFN;
    float* QKs = buf + 3 * BUFN;
    float* VS  = buf + 4 * BUFN;
    float* Y   = buf + 5 * BUFN;
    float* Y2  = buf + 6 * BUFN;

    dim3 gg(PP / 64, CC / 128, BB);   // (49, 2, 2)
    const long bs = (long)CC * PP;

    // merged Q, K, V projections
    qkv_k<<<dim3(PP / 64, 6, BB), 256>>>(qw, qb, kw, kb, vw, vb, x, Q, Kb, Vb);

    // flash attention -> out channels [0,256)
    attn_mma_k<<<dim3(49, 16), 128>>>(Q, Kb, Vb, out);

    // Ks 3x3 conv (implicit GEMM), fused *Q -> QKs
    mm_k<3, true><<<gg, 256>>>(ksw, x, QKs, ksb, Q, nullptr, nullptr, nullptr, nullptr, bs, CC * 9);

    // gate = sigmoid(sd1(QKs)); VS = V * gate
    mm_k<1, false><<<gg, 256>>>(sd1w, QKs, VS, sd1b, Vb, nullptr, nullptr, nullptr, nullptr, bs, CC);

    // depthwise 3x3 + BN1 + leaky -> Y
    long total = (long)BB * CC * PP;
    dw_bn_lrelu_k<<<(int)((total + 255) / 256), 256>>>(VS, dww, bn1g, bn1b, bn1m, bn1v, Y);

    // pointwise pww + BN2 + leaky -> Y2
    mm_k<2, false><<<gg, 256>>>(pww, Y, Y2, nullptr, nullptr, bn2g, bn2b, bn2m, bn2v, bs, CC);

    // sd2 projection -> out channels [256,512)
    mm_k<0, false><<<gg, 256>>>(sd2w, Y2, out + (long)CC * PP, sd2b,
                                nullptr, nullptr, nullptr, nullptr, nullptr, (long)2 * CC * PP, CC);
}

// round 10
// speedup vs baseline: 2.8822x; 1.0392x over previous
// v6: tf32-pre-rounded QKV (kills loader cvts) + ex2 softmax (kills exp FMULs).
#include <cuda_runtime.h>
#include <math.h>

#define PP 3136
#define CC 256
#define BB 2
#define WX 56
#define EPS 1e-5f
#define SLOPE 0.01f

#define BUFN ((long)BB * CC * PP)
__device__ float g_buf[7 * BB * CC * PP];

__device__ __forceinline__ unsigned f2tf(float f) {
    unsigned u;
    asm("cvt.rna.tf32.f32 %0, %1;" : "=r"(u) : "f"(f));
    return u;
}
__device__ __forceinline__ float f2tff(float f) { return __uint_as_float(f2tf(f)); }

__device__ __forceinline__ float ex2f(float x) {
    float r;
    asm("ex2.approx.f32 %0, %1;" : "=f"(r) : "f"(x));
    return r;
}

__device__ __forceinline__ void mma8(float* c, const unsigned* a, unsigned b0, unsigned b1) {
    asm volatile(
        "mma.sync.aligned.m16n8k8.row.col.f32.tf32.tf32.f32 "
        "{%0,%1,%2,%3}, {%4,%5,%6,%7}, {%8,%9}, {%0,%1,%2,%3};"
        : "+f"(c[0]), "+f"(c[1]), "+f"(c[2]), "+f"(c[3])
        : "r"(a[0]), "r"(a[1]), "r"(a[2]), "r"(a[3]), "r"(b0), "r"(b1));
}

// ---------------------------------------------------------------------------
// Unified tf32 GEMM body, register double-buffered.
// MODE 0: +bias | 1: aux*sigmoid(+bias) | 2: BN+leaky | 3: (+bias)*aux
// MODE 4: +bias, output tf32-rounded (for attention inputs)
// ---------------------------------------------------------------------------
template <int MODE, bool CONV>
__device__ __forceinline__ void mm_body(
    const float* __restrict__ W, const float* __restrict__ X,
    float* __restrict__ out,
    const float* __restrict__ bias, const float* __restrict__ aux,
    const float* __restrict__ g, const float* __restrict__ bt,
    const float* __restrict__ mn, const float* __restrict__ vr,
    long outB, int KK, int b, int o0, int p0,
    float (*As)[136], float (*Bs)[72])
{
    const float* Xb = X + (long)b * CC * PP;
    const int tid = threadIdx.x, lane = tid & 31, w = tid >> 5;
    const int wm = w & 3, wn = w >> 2;
    const int mw = wm * 32, nw = wn * 32;
    const int r = lane >> 2, cA = lane & 3;

    float acc[2][4][4];
#pragma unroll
    for (int mt = 0; mt < 2; mt++)
#pragma unroll
        for (int nt = 0; nt < 4; nt++)
#pragma unroll
            for (int j = 0; j < 4; j++) acc[mt][nt][j] = 0.f;

    const int am = tid >> 1, akh = (tid & 1) * 8;
    const int bk = tid >> 4, bn0 = (tid & 15) * 4;

    float ast[8], bst[4];

    auto load_slab = [&](int k0) {
        const float* wp = W + (long)(o0 + am) * KK + k0 + akh;
        float4 wa = *(const float4*)(wp);
        float4 wb = *(const float4*)(wp + 4);
        ast[0] = f2tff(wa.x); ast[1] = f2tff(wa.y);
        ast[2] = f2tff(wa.z); ast[3] = f2tff(wa.w);
        ast[4] = f2tff(wb.x); ast[5] = f2tff(wb.y);
        ast[6] = f2tff(wb.z); ast[7] = f2tff(wb.w);
        if (CONV) {
            int kk = k0 + bk;
            int c = kk / 9, t = kk - c * 9;
            int dy = t / 3 - 1, dx = t - (t / 3) * 3 - 1;
            const float* Xc = Xb + (long)c * PP;
#pragma unroll
            for (int q = 0; q < 4; q++) {
                int p = p0 + bn0 + q;
                int y = p / WX, x = p - y * WX;
                int yy = y + dy, xx = x + dx;
                float v = 0.f;
                if ((unsigned)yy < WX && (unsigned)xx < WX)
                    v = Xc[yy * WX + xx];
                bst[q] = f2tff(v);
            }
        } else {
            float4 x4 = *(const float4*)(Xb + (long)(k0 + bk) * PP + p0 + bn0);
            bst[0] = f2tff(x4.x); bst[1] = f2tff(x4.y);
            bst[2] = f2tff(x4.z); bst[3] = f2tff(x4.w);
        }
    };

    load_slab(0);

    for (int k0 = 0; k0 < KK; k0 += 16) {
        __syncthreads();
        As[akh + 0][am] = ast[0]; As[akh + 1][am] = ast[1];
        As[akh + 2][am] = ast[2]; As[akh + 3][am] = ast[3];
        As[akh + 4][am] = ast[4]; As[akh + 5][am] = ast[5];
        As[akh + 6][am] = ast[6]; As[akh + 7][am] = ast[7];
        *(float4*)&Bs[bk][bn0] = make_float4(bst[0], bst[1], bst[2], bst[3]);
        __syncthreads();
        if (k0 + 16 < KK) load_slab(k0 + 16);

#pragma unroll
        for (int kc = 0; kc < 2; kc++) {
            unsigned af[2][4];
#pragma unroll
            for (int mt = 0; mt < 2; mt++) {
                af[mt][0] = __float_as_uint(As[kc * 8 + cA][mw + mt * 16 + r]);
                af[mt][1] = __float_as_uint(As[kc * 8 + cA][mw + mt * 16 + r + 8]);
                af[mt][2] = __float_as_uint(As[kc * 8 + cA + 4][mw + mt * 16 + r]);
                af[mt][3] = __float_as_uint(As[kc * 8 + cA + 4][mw + mt * 16 + r + 8]);
            }
#pragma unroll
            for (int nt = 0; nt < 4; nt++) {
                unsigned b0 = __float_as_uint(Bs[kc * 8 + cA][nw + nt * 8 + r]);
                unsigned b1 = __float_as_uint(Bs[kc * 8 + cA + 4][nw + nt * 8 + r]);
                mma8(acc[0][nt], af[0], b0, b1);
                mma8(acc[1][nt], af[1], b0, b1);
            }
        }
    }

#pragma unroll
    for (int mt = 0; mt < 2; mt++) {
        int o_lo = o0 + mw + mt * 16 + r;
        int o_hi = o_lo + 8;
        float bi_lo = 0.f, bi_hi = 0.f, sc_lo = 0.f, sc_hi = 0.f, sb_lo = 0.f, sb_hi = 0.f;
        if (MODE != 2) { bi_lo = bias[o_lo]; bi_hi = bias[o_hi]; }
        if (MODE == 2) {
            sc_lo = g[o_lo] * rsqrtf(vr[o_lo] + EPS); sb_lo = bt[o_lo] - mn[o_lo] * sc_lo;
            sc_hi = g[o_hi] * rsqrtf(vr[o_hi] + EPS); sb_hi = bt[o_hi] - mn[o_hi] * sc_hi;
        }
#pragma unroll
        for (int nt = 0; nt < 4; nt++) {
            int p = p0 + nw + nt * 8 + 2 * cA;
            long oi_lo = (long)b * outB + (long)o_lo * PP + p;
            long oi_hi = (long)b * outB + (long)o_hi * PP + p;
            float2 rl, rh;
            float a0 = acc[mt][nt][0], a1 = acc[mt][nt][1];
            float a2 = acc[mt][nt][2], a3 = acc[mt][nt][3];
            if (MODE == 0) {
                rl.x = a0 + bi_lo; rl.y = a1 + bi_lo;
                rh.x = a2 + bi_hi; rh.y = a3 + bi_hi;
            } else if (MODE == 4) {
                rl.x = f2tff(a0 + bi_lo); rl.y = f2tff(a1 + bi_lo);
                rh.x = f2tff(a2 + bi_hi); rh.y = f2tff(a3 + bi_hi);
            } else if (MODE == 1) {
                long ai_lo = (long)b * CC * PP + (long)o_lo * PP + p;
                long ai_hi = (long)b * CC * PP + (long)o_hi * PP + p;
                float2 vl = *(const float2*)(aux + ai_lo);
                float2 vh = *(const float2*)(aux + ai_hi);
                rl.x = vl.x / (1.f + __expf(-(a0 + bi_lo)));
                rl.y = vl.y / (1.f + __expf(-(a1 + bi_lo)));
                rh.x = vh.x / (1.f + __expf(-(a2 + bi_hi)));
                rh.y = vh.y / (1.f + __expf(-(a3 + bi_hi)));
            } else if (MODE == 2) {
                float t0 = a0 * sc_lo + sb_lo, t1 = a1 * sc_lo + sb_lo;
                float t2 = a2 * sc_hi + sb_hi, t3 = a3 * sc_hi + sb_hi;
                rl.x = t0 > 0.f ? t0 : SLOPE * t0; rl.y = t1 > 0.f ? t1 : SLOPE * t1;
                rh.x = t2 > 0.f ? t2 : SLOPE * t2; rh.y = t3 > 0.f ? t3 : SLOPE * t3;
            } else {
                long ai_lo = (long)b * CC * PP + (long)o_lo * PP + p;
                long ai_hi = (long)b * CC * PP + (long)o_hi * PP + p;
                float2 ql = *(const float2*)(aux + ai_lo);
                float2 qh = *(const float2*)(aux + ai_hi);
                rl.x = (a0 + bi_lo) * ql.x; rl.y = (a1 + bi_lo) * ql.y;
                rh.x = (a2 + bi_hi) * qh.x; rh.y = (a3 + bi_hi) * qh.y;
            }
            *(float2*)(out + oi_lo) = rl;
            *(float2*)(out + oi_hi) = rh;
        }
    }
}

template <int MODE, bool CONV>
__global__ void __launch_bounds__(256)
mm_k(const float* __restrict__ W, const float* __restrict__ X,
     float* __restrict__ out,
     const float* __restrict__ bias, const float* __restrict__ aux,
     const float* __restrict__ g, const float* __restrict__ bt,
     const float* __restrict__ mn, const float* __restrict__ vr,
     long outB, int KK)
{
    __shared__ float As[16][136];
    __shared__ float Bs[16][72];
    mm_body<MODE, CONV>(W, X, out, bias, aux, g, bt, mn, vr, outB, KK,
                        blockIdx.z, blockIdx.y * 128, blockIdx.x * 64, As, Bs);
}

// Merged Q/K/V projection, outputs tf32-rounded (MODE 4).
__global__ void __launch_bounds__(256)
qkv_k(const float* __restrict__ qw, const float* __restrict__ qb,
      const float* __restrict__ kw, const float* __restrict__ kb,
      const float* __restrict__ vw, const float* __restrict__ vb,
      const float* __restrict__ X,
      float* __restrict__ Q, float* __restrict__ Kb, float* __restrict__ Vb)
{
    __shared__ float As[16][136];
    __shared__ float Bs[16][72];
    const int y = blockIdx.y;
    const int sel = y >> 1;
    const float* W    = sel == 0 ? qw : (sel == 1 ? kw : vw);
    const float* bias = sel == 0 ? qb : (sel == 1 ? kb : vb);
    float* out        = sel == 0 ? Q  : (sel == 1 ? Kb : Vb);
    mm_body<4, false>(W, X, out, bias, nullptr, nullptr, nullptr, nullptr, nullptr,
                      (long)CC * PP, CC, blockIdx.z, (y & 1) * 128, blockIdx.x * 64,
                      As, Bs);
}

// ---------------------------------------------------------------------------
// Flash attention, tf32 mma, double-buffered, inputs pre-rounded to tf32.
// Softmax in log2 domain (ex2), log2e folded into Q scale.
// ---------------------------------------------------------------------------
__global__ void __launch_bounds__(128)
attn_mma_k(const float* __restrict__ Q, const float* __restrict__ K,
           const float* __restrict__ V, float* __restrict__ out)
{
    __shared__ float  Ks[32 * 72];
    __shared__ float2 VP[32 * 36];
    __shared__ float2 PPs[4 * 16 * 36];

    const int tid = threadIdx.x, lane = tid & 31, w = tid >> 5;
    const int bh = blockIdx.y;
    const int b = bh >> 3, h = bh & 7;
    const long base = ((long)b * CC + h * 32) * PP;
    const float* qp = Q + base;
    const float* kp = K + base;
    const float* vp = V + base;
    const int q0 = blockIdx.x * 64;
    const float SC = 0.17677669529663687f * 1.4426950408889634f;  // /sqrt(32)*log2e

    // staged next-tile registers (inputs already tf32 — no cvt needed)
    uint4 kst[4], vst[4];
    auto load_tile = [&](int kb) {
#pragma unroll
        for (int j = 0; j < 4; j++) {
            int i = tid + j * 128;
            int d = i >> 4, k4 = (i & 15) * 4;
            kst[j] = *(const uint4*)(kp + (long)d * PP + kb + k4);
            vst[j] = *(const uint4*)(vp + (long)d * PP + kb + k4);
        }
    };

    load_tile(0);

    float* Qs = (float*)PPs;
    for (int i = tid; i < 512; i += 128) {
        int d = i >> 4, q4 = (i & 15) * 4;
        float4 v4 = *(const float4*)(qp + (long)d * PP + q0 + q4);
        Qs[(q4 + 0) * 36 + d] = f2tff(v4.x * SC);
        Qs[(q4 + 1) * 36 + d] = f2tff(v4.y * SC);
        Qs[(q4 + 2) * 36 + d] = f2tff(v4.z * SC);
        Qs[(q4 + 3) * 36 + d] = f2tff(v4.w * SC);
    }
    __syncthreads();

    unsigned af[4][4];
    {
        int rr = w * 16 + (lane >> 2);
        int c = lane & 3;
#pragma unroll
        for (int kc = 0; kc < 4; kc++) {
            af[kc][0] = __float_as_uint(Qs[rr * 36 + kc * 8 + c]);
            af[kc][1] = __float_as_uint(Qs[(rr + 8) * 36 + kc * 8 + c]);
            af[kc][2] = __float_as_uint(Qs[rr * 36 + kc * 8 + c + 4]);
            af[kc][3] = __float_as_uint(Qs[(rr + 8) * 36 + kc * 8 + c + 4]);
        }
    }
    __syncthreads();

    float m0 = -1e30f, m1 = -1e30f, l0 = 0.f, l1 = 0.f;
    float o[4][4];
#pragma unroll
    for (int nt = 0; nt < 4; nt++)
#pragma unroll
        for (int j = 0; j < 4; j++) o[nt][j] = 0.f;

    float* Pw = (float*)PPs + w * 16 * 72;
    const int lq = lane >> 2;
    const int lr = lane & 3;
    const int cbase = 2 * ((2 * lr) & 3) + (lr >> 1);

    for (int kt = 0; kt < 49; kt++) {
        __syncthreads();
#pragma unroll
        for (int j = 0; j < 4; j++) {
            int i = tid + j * 128;
            int d = i >> 4, k4 = (i & 15) * 4;
            *(uint4*)(Ks + d * 72 + k4) = kst[j];
            float* vf = (float*)VP + d * 72 + (k4 >> 3) * 8 + ((k4 >> 2) & 1);
            vf[0] = __uint_as_float(vst[j].x); vf[2] = __uint_as_float(vst[j].y);
            vf[4] = __uint_as_float(vst[j].z); vf[6] = __uint_as_float(vst[j].w);
        }
        __syncthreads();
        if (kt < 48) load_tile((kt + 1) * 64);

        // ---- S = Q @ K (log2 domain) ----
        float s[8][4];
#pragma unroll
        for (int nt = 0; nt < 8; nt++)
#pragma unroll
            for (int j = 0; j < 4; j++) s[nt][j] = 0.f;
#pragma unroll
        for (int kc = 0; kc < 4; kc++) {
#pragma unroll
            for (int nt = 0; nt < 8; nt++) {
                unsigned b0 = __float_as_uint(Ks[(kc * 8 + lr) * 72 + nt * 8 + lq]);
                unsigned b1 = __float_as_uint(Ks[(kc * 8 + lr + 4) * 72 + nt * 8 + lq]);
                mma8(s[nt], af[kc], b0, b1);
            }
        }

        // ---- online softmax (base-2) ----
        float mx0 = s[0][0], mx1 = s[0][2];
#pragma unroll
        for (int nt = 0; nt < 8; nt++) {
            mx0 = fmaxf(mx0, fmaxf(s[nt][0], s[nt][1]));
            mx1 = fmaxf(mx1, fmaxf(s[nt][2], s[nt][3]));
        }
        mx0 = fmaxf(mx0, __shfl_xor_sync(0xffffffffu, mx0, 1));
        mx0 = fmaxf(mx0, __shfl_xor_sync(0xffffffffu, mx0, 2));
        mx1 = fmaxf(mx1, __shfl_xor_sync(0xffffffffu, mx1, 1));
        mx1 = fmaxf(mx1, __shfl_xor_sync(0xffffffffu, mx1, 2));
        float nm0 = fmaxf(m0, mx0), nm1 = fmaxf(m1, mx1);
        float a0 = ex2f(m0 - nm0), a1 = ex2f(m1 - nm1);
        m0 = nm0; m1 = nm1;

        float ps0 = 0.f, ps1 = 0.f;
#pragma unroll
        for (int nt = 0; nt < 8; nt++) {
            s[nt][0] = ex2f(s[nt][0] - m0); ps0 += s[nt][0];
            s[nt][1] = ex2f(s[nt][1] - m0); ps0 += s[nt][1];
            s[nt][2] = ex2f(s[nt][2] - m1); ps1 += s[nt][2];
            s[nt][3] = ex2f(s[nt][3] - m1); ps1 += s[nt][3];
        }
        ps0 += __shfl_xor_sync(0xffffffffu, ps0, 1);
        ps0 += __shfl_xor_sync(0xffffffffu, ps0, 2);
        ps1 += __shfl_xor_sync(0xffffffffu, ps1, 1);
        ps1 += __shfl_xor_sync(0xffffffffu, ps1, 2);
        l0 = l0 * a0 + ps0;
        l1 = l1 * a1 + ps1;
#pragma unroll
        for (int nt = 0; nt < 4; nt++) {
            o[nt][0] *= a0; o[nt][1] *= a0;
            o[nt][2] *= a1; o[nt][3] *= a1;
        }

        // ---- write P (tf32) into paired-column per-warp smem ----
        __syncwarp();
#pragma unroll
        for (int nt = 0; nt < 8; nt++) {
            float* pr = Pw + lq * 72 + nt * 8 + cbase;
            pr[0] = f2tff(s[nt][0]);
            pr[2] = f2tff(s[nt][1]);
            float* pr2 = pr + 8 * 72;
            pr2[0] = f2tff(s[nt][2]);
            pr2[2] = f2tff(s[nt][3]);
        }
        __syncwarp();

        // ---- O += P @ V ----
#pragma unroll
        for (int kc = 0; kc < 8; kc++) {
            unsigned pa[4];
            float2 plo = *(const float2*)(Pw + lq * 72 + kc * 8 + 2 * lr);
            float2 phi = *(const float2*)(Pw + (lq + 8) * 72 + kc * 8 + 2 * lr);
            pa[0] = __float_as_uint(plo.x); pa[1] = __float_as_uint(phi.x);
            pa[2] = __float_as_uint(plo.y); pa[3] = __float_as_uint(phi.y);
#pragma unroll
            for (int nt = 0; nt < 4; nt++) {
                float2 v2 = VP[(nt * 8 + lq) * 36 + kc * 4 + lr];
                mma8(o[nt], pa, __float_as_uint(v2.x), __float_as_uint(v2.y));
            }
        }
    }

    float inv0 = 1.f / l0, inv1 = 1.f / l1;
    float* op = out + (long)b * (2 * CC * PP) + (long)(h * 32) * PP;
    int qr = q0 + w * 16 + lq;
#pragma unroll
    for (int nt = 0; nt < 4; nt++) {
        int d = nt * 8 + lr * 2;
        op[(long)d * PP + qr]           = o[nt][0] * inv0;
        op[(long)(d + 1) * PP + qr]     = o[nt][1] * inv0;
        op[(long)d * PP + qr + 8]       = o[nt][2] * inv1;
        op[(long)(d + 1) * PP + qr + 8] = o[nt][3] * inv1;
    }
}

// ---------------------------------------------------------------------------
// Depthwise 3x3 conv + BN1 + leaky ReLU (elementwise).
// ---------------------------------------------------------------------------
__global__ void __launch_bounds__(256)
dw_bn_lrelu_k(const float* __restrict__ in, const float* __restrict__ w9,
              const float* __restrict__ g, const float* __restrict__ bt,
              const float* __restrict__ mn, const float* __restrict__ vv,
              float* __restrict__ out)
{
    long idx = (long)blockIdx.x * 256 + threadIdx.x;
    if (idx >= (long)BB * CC * PP) return;
    int p = (int)(idx % PP);
    int c = (int)((idx / PP) % CC);
    int y = p / WX, x = p - y * WX;
    const float* ip = in + (idx - p);
    const float* wc = w9 + c * 9;
    float s = 0.f;
#pragma unroll
    for (int dy = -1; dy <= 1; dy++) {
        int yy = y + dy;
        if ((unsigned)yy >= WX) continue;
#pragma unroll
        for (int dx = -1; dx <= 1; dx++) {
            int xx = x + dx;
            if ((unsigned)xx >= WX) continue;
            s += wc[(dy + 1) * 3 + (dx + 1)] * ip[yy * WX + xx];
        }
    }
    float sc = g[c] * rsqrtf(vv[c] + EPS);
    float t = (s - mn[c]) * sc + bt[c];
    out[idx] = t > 0.f ? t : SLOPE * t;
}

// ---------------------------------------------------------------------------
extern "C" void kernel_launch(void* const* d_in, const int* in_sizes, int n_in,
                              void* d_out, int out_size)
{
    (void)in_sizes; (void)n_in; (void)out_size;
    const float* x    = (const float*)d_in[0];
    const float* qw   = (const float*)d_in[1];
    const float* qb   = (const float*)d_in[2];
    const float* kw   = (const float*)d_in[3];
    const float* kb   = (const float*)d_in[4];
    const float* vw   = (const float*)d_in[5];
    const float* vb   = (const float*)d_in[6];
    const float* ksw  = (const float*)d_in[7];
    const float* ksb  = (const float*)d_in[8];
    const float* sd1w = (const float*)d_in[9];
    const float* sd1b = (const float*)d_in[10];
    const float* sd2w = (const float*)d_in[11];
    const float* sd2b = (const float*)d_in[12];
    const float* dww  = (const float*)d_in[13];
    const float* bn1g = (const float*)d_in[14];
    const float* bn1b = (const float*)d_in[15];
    const float* bn1m = (const float*)d_in[16];
    const float* bn1v = (const float*)d_in[17];
    const float* pww  = (const float*)d_in[18];
    const float* bn2g = (const float*)d_in[19];
    const float* bn2b = (const float*)d_in[20];
    const float* bn2m = (const float*)d_in[21];
    const float* bn2v = (const float*)d_in[22];
    float* out = (float*)d_out;

    float* buf = nullptr;
    cudaGetSymbolAddress((void**)&buf, g_buf);
    float* Q   = buf + 0 * BUFN;
    float* Kb  = buf + 1 * BUFN;
    float* Vb  = buf + 2 * BUFN;
    float* QKs = buf + 3 * BUFN;
    float* VS  = buf + 4 * BUFN;
    float* Y   = buf + 5 * BUFN;
    float* Y2  = buf + 6 * BUFN;

    dim3 gg(PP / 64, CC / 128, BB);   // (49, 2, 2)
    const long bs = (long)CC * PP;

    // merged Q, K, V projections (tf32-rounded outputs)
    qkv_k<<<dim3(PP / 64, 6, BB), 256>>>(qw, qb, kw, kb, vw, vb, x, Q, Kb, Vb);

    // flash attention -> out channels [0,256)
    attn_mma_k<<<dim3(49, 16), 128>>>(Q, Kb, Vb, out);

    // Ks 3x3 conv (implicit GEMM), fused *Q -> QKs
    mm_k<3, true><<<gg, 256>>>(ksw, x, QKs, ksb, Q, nullptr, nullptr, nullptr, nullptr, bs, CC * 9);

    // gate = sigmoid(sd1(QKs)); VS = V * gate
    mm_k<1, false><<<gg, 256>>>(sd1w, QKs, VS, sd1b, Vb, nullptr, nullptr, nullptr, nullptr, bs, CC);

    // depthwise 3x3 + BN1 + leaky -> Y
    long total = (long)BB * CC * PP;
    dw_bn_lrelu_k<<<(int)((total + 255) / 256), 256>>>(VS, dww, bn1g, bn1b, bn1m, bn1v, Y);

    // pointwise pww + BN2 + leaky -> Y2
    mm_k<2, false><<<gg, 256>>>(pww, Y, Y2, nullptr, nullptr, bn2g, bn2b, bn2m, bn2v, bs, CC);

    // sd2 projection -> out channels [256,512)
    mm_k<0, false><<<gg, 256>>>(sd2w, Y2, out + (long)CC * PP, sd2b,
                                nullptr, nullptr, nullptr, nullptr, nullptr, (long)2 * CC * PP, CC);
}

// round 11
// speedup vs baseline: 2.8906x; 1.0029x over previous
// v7: cp.async double-buffered attention K/V + deferred l-reduction.
#include <cuda_runtime.h>
#include <math.h>

#define PP 3136
#define CC 256
#define BB 2
#define WX 56
#define EPS 1e-5f
#define SLOPE 0.01f

#define BUFN ((long)BB * CC * PP)
__device__ float g_buf[7 * BB * CC * PP];

__device__ __forceinline__ unsigned f2tf(float f) {
    unsigned u;
    asm("cvt.rna.tf32.f32 %0, %1;" : "=r"(u) : "f"(f));
    return u;
}
__device__ __forceinline__ float f2tff(float f) { return __uint_as_float(f2tf(f)); }

__device__ __forceinline__ float ex2f(float x) {
    float r;
    asm("ex2.approx.f32 %0, %1;" : "=f"(r) : "f"(x));
    return r;
}

__device__ __forceinline__ void mma8(float* c, const unsigned* a, unsigned b0, unsigned b1) {
    asm volatile(
        "mma.sync.aligned.m16n8k8.row.col.f32.tf32.tf32.f32 "
        "{%0,%1,%2,%3}, {%4,%5,%6,%7}, {%8,%9}, {%0,%1,%2,%3};"
        : "+f"(c[0]), "+f"(c[1]), "+f"(c[2]), "+f"(c[3])
        : "r"(a[0]), "r"(a[1]), "r"(a[2]), "r"(a[3]), "r"(b0), "r"(b1));
}

// ---------------------------------------------------------------------------
// Unified tf32 GEMM body, register double-buffered.
// MODE 0: +bias | 1: aux*sigmoid(+bias) | 2: BN+leaky | 3: (+bias)*aux
// MODE 4: +bias, output tf32-rounded (for attention inputs)
// ---------------------------------------------------------------------------
template <int MODE, bool CONV>
__device__ __forceinline__ void mm_body(
    const float* __restrict__ W, const float* __restrict__ X,
    float* __restrict__ out,
    const float* __restrict__ bias, const float* __restrict__ aux,
    const float* __restrict__ g, const float* __restrict__ bt,
    const float* __restrict__ mn, const float* __restrict__ vr,
    long outB, int KK, int b, int o0, int p0,
    float (*As)[136], float (*Bs)[72])
{
    const float* Xb = X + (long)b * CC * PP;
    const int tid = threadIdx.x, lane = tid & 31, w = tid >> 5;
    const int wm = w & 3, wn = w >> 2;
    const int mw = wm * 32, nw = wn * 32;
    const int r = lane >> 2, cA = lane & 3;

    float acc[2][4][4];
#pragma unroll
    for (int mt = 0; mt < 2; mt++)
#pragma unroll
        for (int nt = 0; nt < 4; nt++)
#pragma unroll
            for (int j = 0; j < 4; j++) acc[mt][nt][j] = 0.f;

    const int am = tid >> 1, akh = (tid & 1) * 8;
    const int bk = tid >> 4, bn0 = (tid & 15) * 4;

    float ast[8], bst[4];

    auto load_slab = [&](int k0) {
        const float* wp = W + (long)(o0 + am) * KK + k0 + akh;
        float4 wa = *(const float4*)(wp);
        float4 wb = *(const float4*)(wp + 4);
        ast[0] = f2tff(wa.x); ast[1] = f2tff(wa.y);
        ast[2] = f2tff(wa.z); ast[3] = f2tff(wa.w);
        ast[4] = f2tff(wb.x); ast[5] = f2tff(wb.y);
        ast[6] = f2tff(wb.z); ast[7] = f2tff(wb.w);
        if (CONV) {
            int kk = k0 + bk;
            int c = kk / 9, t = kk - c * 9;
            int dy = t / 3 - 1, dx = t - (t / 3) * 3 - 1;
            const float* Xc = Xb + (long)c * PP;
#pragma unroll
            for (int q = 0; q < 4; q++) {
                int p = p0 + bn0 + q;
                int y = p / WX, x = p - y * WX;
                int yy = y + dy, xx = x + dx;
                float v = 0.f;
                if ((unsigned)yy < WX && (unsigned)xx < WX)
                    v = Xc[yy * WX + xx];
                bst[q] = f2tff(v);
            }
        } else {
            float4 x4 = *(const float4*)(Xb + (long)(k0 + bk) * PP + p0 + bn0);
            bst[0] = f2tff(x4.x); bst[1] = f2tff(x4.y);
            bst[2] = f2tff(x4.z); bst[3] = f2tff(x4.w);
        }
    };

    load_slab(0);

    for (int k0 = 0; k0 < KK; k0 += 16) {
        __syncthreads();
        As[akh + 0][am] = ast[0]; As[akh + 1][am] = ast[1];
        As[akh + 2][am] = ast[2]; As[akh + 3][am] = ast[3];
        As[akh + 4][am] = ast[4]; As[akh + 5][am] = ast[5];
        As[akh + 6][am] = ast[6]; As[akh + 7][am] = ast[7];
        *(float4*)&Bs[bk][bn0] = make_float4(bst[0], bst[1], bst[2], bst[3]);
        __syncthreads();
        if (k0 + 16 < KK) load_slab(k0 + 16);

#pragma unroll
        for (int kc = 0; kc < 2; kc++) {
            unsigned af[2][4];
#pragma unroll
            for (int mt = 0; mt < 2; mt++) {
                af[mt][0] = __float_as_uint(As[kc * 8 + cA][mw + mt * 16 + r]);
                af[mt][1] = __float_as_uint(As[kc * 8 + cA][mw + mt * 16 + r + 8]);
                af[mt][2] = __float_as_uint(As[kc * 8 + cA + 4][mw + mt * 16 + r]);
                af[mt][3] = __float_as_uint(As[kc * 8 + cA + 4][mw + mt * 16 + r + 8]);
            }
#pragma unroll
            for (int nt = 0; nt < 4; nt++) {
                unsigned b0 = __float_as_uint(Bs[kc * 8 + cA][nw + nt * 8 + r]);
                unsigned b1 = __float_as_uint(Bs[kc * 8 + cA + 4][nw + nt * 8 + r]);
                mma8(acc[0][nt], af[0], b0, b1);
                mma8(acc[1][nt], af[1], b0, b1);
            }
        }
    }

#pragma unroll
    for (int mt = 0; mt < 2; mt++) {
        int o_lo = o0 + mw + mt * 16 + r;
        int o_hi = o_lo + 8;
        float bi_lo = 0.f, bi_hi = 0.f, sc_lo = 0.f, sc_hi = 0.f, sb_lo = 0.f, sb_hi = 0.f;
        if (MODE != 2) { bi_lo = bias[o_lo]; bi_hi = bias[o_hi]; }
        if (MODE == 2) {
            sc_lo = g[o_lo] * rsqrtf(vr[o_lo] + EPS); sb_lo = bt[o_lo] - mn[o_lo] * sc_lo;
            sc_hi = g[o_hi] * rsqrtf(vr[o_hi] + EPS); sb_hi = bt[o_hi] - mn[o_hi] * sc_hi;
        }
#pragma unroll
        for (int nt = 0; nt < 4; nt++) {
            int p = p0 + nw + nt * 8 + 2 * cA;
            long oi_lo = (long)b * outB + (long)o_lo * PP + p;
            long oi_hi = (long)b * outB + (long)o_hi * PP + p;
            float2 rl, rh;
            float a0 = acc[mt][nt][0], a1 = acc[mt][nt][1];
            float a2 = acc[mt][nt][2], a3 = acc[mt][nt][3];
            if (MODE == 0) {
                rl.x = a0 + bi_lo; rl.y = a1 + bi_lo;
                rh.x = a2 + bi_hi; rh.y = a3 + bi_hi;
            } else if (MODE == 4) {
                rl.x = f2tff(a0 + bi_lo); rl.y = f2tff(a1 + bi_lo);
                rh.x = f2tff(a2 + bi_hi); rh.y = f2tff(a3 + bi_hi);
            } else if (MODE == 1) {
                long ai_lo = (long)b * CC * PP + (long)o_lo * PP + p;
                long ai_hi = (long)b * CC * PP + (long)o_hi * PP + p;
                float2 vl = *(const float2*)(aux + ai_lo);
                float2 vh = *(const float2*)(aux + ai_hi);
                rl.x = vl.x / (1.f + __expf(-(a0 + bi_lo)));
                rl.y = vl.y / (1.f + __expf(-(a1 + bi_lo)));
                rh.x = vh.x / (1.f + __expf(-(a2 + bi_hi)));
                rh.y = vh.y / (1.f + __expf(-(a3 + bi_hi)));
            } else if (MODE == 2) {
                float t0 = a0 * sc_lo + sb_lo, t1 = a1 * sc_lo + sb_lo;
                float t2 = a2 * sc_hi + sb_hi, t3 = a3 * sc_hi + sb_hi;
                rl.x = t0 > 0.f ? t0 : SLOPE * t0; rl.y = t1 > 0.f ? t1 : SLOPE * t1;
                rh.x = t2 > 0.f ? t2 : SLOPE * t2; rh.y = t3 > 0.f ? t3 : SLOPE * t3;
            } else {
                long ai_lo = (long)b * CC * PP + (long)o_lo * PP + p;
                long ai_hi = (long)b * CC * PP + (long)o_hi * PP + p;
                float2 ql = *(const float2*)(aux + ai_lo);
                float2 qh = *(const float2*)(aux + ai_hi);
                rl.x = (a0 + bi_lo) * ql.x; rl.y = (a1 + bi_lo) * ql.y;
                rh.x = (a2 + bi_hi) * qh.x; rh.y = (a3 + bi_hi) * qh.y;
            }
            *(float2*)(out + oi_lo) = rl;
            *(float2*)(out + oi_hi) = rh;
        }
    }
}

template <int MODE, bool CONV>
__global__ void __launch_bounds__(256)
mm_k(const float* __restrict__ W, const float* __restrict__ X,
     float* __restrict__ out,
     const float* __restrict__ bias, const float* __restrict__ aux,
     const float* __restrict__ g, const float* __restrict__ bt,
     const float* __restrict__ mn, const float* __restrict__ vr,
     long outB, int KK)
{
    __shared__ float As[16][136];
    __shared__ float Bs[16][72];
    mm_body<MODE, CONV>(W, X, out, bias, aux, g, bt, mn, vr, outB, KK,
                        blockIdx.z, blockIdx.y * 128, blockIdx.x * 64, As, Bs);
}

// Merged Q/K/V projection, outputs tf32-rounded (MODE 4).
__global__ void __launch_bounds__(256)
qkv_k(const float* __restrict__ qw, const float* __restrict__ qb,
      const float* __restrict__ kw, const float* __restrict__ kb,
      const float* __restrict__ vw, const float* __restrict__ vb,
      const float* __restrict__ X,
      float* __restrict__ Q, float* __restrict__ Kb, float* __restrict__ Vb)
{
    __shared__ float As[16][136];
    __shared__ float Bs[16][72];
    const int y = blockIdx.y;
    const int sel = y >> 1;
    const float* W    = sel == 0 ? qw : (sel == 1 ? kw : vw);
    const float* bias = sel == 0 ? qb : (sel == 1 ? kb : vb);
    float* out        = sel == 0 ? Q  : (sel == 1 ? Kb : Vb);
    mm_body<4, false>(W, X, out, bias, nullptr, nullptr, nullptr, nullptr, nullptr,
                      (long)CC * PP, CC, blockIdx.z, (y & 1) * 128, blockIdx.x * 64,
                      As, Bs);
}

// ---------------------------------------------------------------------------
// Flash attention v7: cp.async double-buffered K/V (inputs pre-tf32 in gmem),
// deferred lane-local l-reduction, base-2 softmax, paired P smem.
// Dynamic smem: K0,K1,V0,V1 (each 32x72 f) + P pool (4608 f) = 55296 B.
// ---------------------------------------------------------------------------
__global__ void __launch_bounds__(128)
attn_mma_k(const float* __restrict__ Q, const float* __restrict__ K,
           const float* __restrict__ V, float* __restrict__ out)
{
    extern __shared__ float dsm[];
    float* KB0 = dsm;
    float* KB1 = dsm + 2304;
    float* VB0 = dsm + 4608;
    float* VB1 = dsm + 6912;
    float* Ppool = dsm + 9216;   // 4608 floats; aliased as Qs during init

    const int tid = threadIdx.x, lane = tid & 31, w = tid >> 5;
    const int bh = blockIdx.y;
    const int b = bh >> 3, h = bh & 7;
    const long base = ((long)b * CC + h * 32) * PP;
    const float* qp = Q + base;
    const float* kp = K + base;
    const float* vp = V + base;
    const int q0 = blockIdx.x * 64;
    const float SC = 0.17677669529663687f * 1.4426950408889634f;  // /sqrt(32)*log2e

    const int ld_d = tid >> 4, ld_k4 = (tid & 15) * 4;   // this thread's copy slots

    auto issue_tile = [&](int kb, float* Kd, float* Vd) {
#pragma unroll
        for (int j = 0; j < 4; j++) {
            int d = ld_d + j * 8;
            unsigned ks = (unsigned)__cvta_generic_to_shared(Kd + d * 72 + ld_k4);
            unsigned vs = (unsigned)__cvta_generic_to_shared(Vd + d * 72 + ld_k4);
            const float* kg = kp + (long)d * PP + kb + ld_k4;
            const float* vg = vp + (long)d * PP + kb + ld_k4;
            asm volatile("cp.async.ca.shared.global [%0], [%1], 16;" :: "r"(ks), "l"(kg));
            asm volatile("cp.async.ca.shared.global [%0], [%1], 16;" :: "r"(vs), "l"(vg));
        }
        asm volatile("cp.async.commit_group;" ::: "memory");
    };

    issue_tile(0, KB0, VB0);   // tile 0 flies during Q setup

    // ---- Q tile into Ppool as Qs[q][d] (pitch 36) ----
    float* Qs = Ppool;
    for (int i = tid; i < 512; i += 128) {
        int d = i >> 4, q4 = (i & 15) * 4;
        float4 v4 = *(const float4*)(qp + (long)d * PP + q0 + q4);
        Qs[(q4 + 0) * 36 + d] = f2tff(v4.x * SC);
        Qs[(q4 + 1) * 36 + d] = f2tff(v4.y * SC);
        Qs[(q4 + 2) * 36 + d] = f2tff(v4.z * SC);
        Qs[(q4 + 3) * 36 + d] = f2tff(v4.w * SC);
    }
    __syncthreads();

    unsigned af[4][4];
    {
        int rr = w * 16 + (lane >> 2);
        int c = lane & 3;
#pragma unroll
        for (int kc = 0; kc < 4; kc++) {
            af[kc][0] = __float_as_uint(Qs[rr * 36 + kc * 8 + c]);
            af[kc][1] = __float_as_uint(Qs[(rr + 8) * 36 + kc * 8 + c]);
            af[kc][2] = __float_as_uint(Qs[rr * 36 + kc * 8 + c + 4]);
            af[kc][3] = __float_as_uint(Qs[(rr + 8) * 36 + kc * 8 + c + 4]);
        }
    }
    // loop-top sync of iteration 0 orders these af reads vs first P writes

    float m0 = -1e30f, m1 = -1e30f, l0 = 0.f, l1 = 0.f;   // l lane-local (deferred)
    float o[4][4];
#pragma unroll
    for (int nt = 0; nt < 4; nt++)
#pragma unroll
        for (int j = 0; j < 4; j++) o[nt][j] = 0.f;

    float* Pw = Ppool + w * 16 * 72;
    const int lq = lane >> 2;
    const int lr = lane & 3;
    const int cbase = 2 * ((2 * lr) & 3) + (lr >> 1);

    for (int kt = 0; kt < 49; kt++) {
        asm volatile("cp.async.wait_group 0;" ::: "memory");
        __syncthreads();   // tile kt visible; all warps done with tile kt-1
        if (kt < 48) {
            int nb = (kt + 1) & 1;
            issue_tile((kt + 1) * 64, nb ? KB1 : KB0, nb ? VB1 : VB0);
        }
        const float* Ksb = (kt & 1) ? KB1 : KB0;
        const float* Vsb = (kt & 1) ? VB1 : VB0;

        // ---- S = Q @ K (log2 domain) ----
        float s[8][4];
#pragma unroll
        for (int nt = 0; nt < 8; nt++)
#pragma unroll
            for (int j = 0; j < 4; j++) s[nt][j] = 0.f;
#pragma unroll
        for (int kc = 0; kc < 4; kc++) {
#pragma unroll
            for (int nt = 0; nt < 8; nt++) {
                unsigned b0 = __float_as_uint(Ksb[(kc * 8 + lr) * 72 + nt * 8 + lq]);
                unsigned b1 = __float_as_uint(Ksb[(kc * 8 + lr + 4) * 72 + nt * 8 + lq]);
                mma8(s[nt], af[kc], b0, b1);
            }
        }

        // ---- online softmax (base-2), deferred l ----
        float mx0 = s[0][0], mx1 = s[0][2];
#pragma unroll
        for (int nt = 0; nt < 8; nt++) {
            mx0 = fmaxf(mx0, fmaxf(s[nt][0], s[nt][1]));
            mx1 = fmaxf(mx1, fmaxf(s[nt][2], s[nt][3]));
        }
        mx0 = fmaxf(mx0, __shfl_xor_sync(0xffffffffu, mx0, 1));
        mx0 = fmaxf(mx0, __shfl_xor_sync(0xffffffffu, mx0, 2));
        mx1 = fmaxf(mx1, __shfl_xor_sync(0xffffffffu, mx1, 1));
        mx1 = fmaxf(mx1, __shfl_xor_sync(0xffffffffu, mx1, 2));
        float nm0 = fmaxf(m0, mx0), nm1 = fmaxf(m1, mx1);
        float a0 = ex2f(m0 - nm0), a1 = ex2f(m1 - nm1);
        m0 = nm0; m1 = nm1;

        float ps0 = 0.f, ps1 = 0.f;
#pragma unroll
        for (int nt = 0; nt < 8; nt++) {
            s[nt][0] = ex2f(s[nt][0] - m0); ps0 += s[nt][0];
            s[nt][1] = ex2f(s[nt][1] - m0); ps0 += s[nt][1];
            s[nt][2] = ex2f(s[nt][2] - m1); ps1 += s[nt][2];
            s[nt][3] = ex2f(s[nt][3] - m1); ps1 += s[nt][3];
        }
        l0 = l0 * a0 + ps0;    // lane-local; quad-reduced once after loop
        l1 = l1 * a1 + ps1;
#pragma unroll
        for (int nt = 0; nt < 4; nt++) {
            o[nt][0] *= a0; o[nt][1] *= a0;
            o[nt][2] *= a1; o[nt][3] *= a1;
        }

        // ---- write P (tf32) into paired-column per-warp smem ----
        __syncwarp();
#pragma unroll
        for (int nt = 0; nt < 8; nt++) {
            float* pr = Pw + lq * 72 + nt * 8 + cbase;
            pr[0] = f2tff(s[nt][0]);
            pr[2] = f2tff(s[nt][1]);
            float* pr2 = pr + 8 * 72;
            pr2[0] = f2tff(s[nt][2]);
            pr2[2] = f2tff(s[nt][3]);
        }
        __syncwarp();

        // ---- O += P @ V ----
#pragma unroll
        for (int kc = 0; kc < 8; kc++) {
            unsigned pa[4];
            float2 plo = *(const float2*)(Pw + lq * 72 + kc * 8 + 2 * lr);
            float2 phi = *(const float2*)(Pw + (lq + 8) * 72 + kc * 8 + 2 * lr);
            pa[0] = __float_as_uint(plo.x); pa[1] = __float_as_uint(phi.x);
            pa[2] = __float_as_uint(plo.y); pa[3] = __float_as_uint(phi.y);
#pragma unroll
            for (int nt = 0; nt < 4; nt++) {
                unsigned b0 = __float_as_uint(Vsb[(nt * 8 + lq) * 72 + kc * 8 + lr]);
                unsigned b1 = __float_as_uint(Vsb[(nt * 8 + lq) * 72 + kc * 8 + lr + 4]);
                mma8(o[nt], pa, b0, b1);
            }
        }
    }

    // final l reduction (deferred from the mainloop)
    l0 += __shfl_xor_sync(0xffffffffu, l0, 1);
    l0 += __shfl_xor_sync(0xffffffffu, l0, 2);
    l1 += __shfl_xor_sync(0xffffffffu, l1, 1);
    l1 += __shfl_xor_sync(0xffffffffu, l1, 2);

    float inv0 = 1.f / l0, inv1 = 1.f / l1;
    float* op = out + (long)b * (2 * CC * PP) + (long)(h * 32) * PP;
    int qr = q0 + w * 16 + lq;
#pragma unroll
    for (int nt = 0; nt < 4; nt++) {
        int d = nt * 8 + lr * 2;
        op[(long)d * PP + qr]           = o[nt][0] * inv0;
        op[(long)(d + 1) * PP + qr]     = o[nt][1] * inv0;
        op[(long)d * PP + qr + 8]       = o[nt][2] * inv1;
        op[(long)(d + 1) * PP + qr + 8] = o[nt][3] * inv1;
    }
}

// ---------------------------------------------------------------------------
// Depthwise 3x3 conv + BN1 + leaky ReLU (elementwise).
// ---------------------------------------------------------------------------
__global__ void __launch_bounds__(256)
dw_bn_lrelu_k(const float* __restrict__ in, const float* __restrict__ w9,
              const float* __restrict__ g, const float* __restrict__ bt,
              const float* __restrict__ mn, const float* __restrict__ vv,
              float* __restrict__ out)
{
    long idx = (long)blockIdx.x * 256 + threadIdx.x;
    if (idx >= (long)BB * CC * PP) return;
    int p = (int)(idx % PP);
    int c = (int)((idx / PP) % CC);
    int y = p / WX, x = p - y * WX;
    const float* ip = in + (idx - p);
    const float* wc = w9 + c * 9;
    float s = 0.f;
#pragma unroll
    for (int dy = -1; dy <= 1; dy++) {
        int yy = y + dy;
        if ((unsigned)yy >= WX) continue;
#pragma unroll
        for (int dx = -1; dx <= 1; dx++) {
            int xx = x + dx;
            if ((unsigned)xx >= WX) continue;
            s += wc[(dy + 1) * 3 + (dx + 1)] * ip[yy * WX + xx];
        }
    }
    float sc = g[c] * rsqrtf(vv[c] + EPS);
    float t = (s - mn[c]) * sc + bt[c];
    out[idx] = t > 0.f ? t : SLOPE * t;
}

// ---------------------------------------------------------------------------
extern "C" void kernel_launch(void* const* d_in, const int* in_sizes, int n_in,
                              void* d_out, int out_size)
{
    (void)in_sizes; (void)n_in; (void)out_size;
    const float* x    = (const float*)d_in[0];
    const float* qw   = (const float*)d_in[1];
    const float* qb   = (const float*)d_in[2];
    const float* kw   = (const float*)d_in[3];
    const float* kb   = (const float*)d_in[4];
    const float* vw   = (const float*)d_in[5];
    const float* vb   = (const float*)d_in[6];
    const float* ksw  = (const float*)d_in[7];
    const float* ksb  = (const float*)d_in[8];
    const float* sd1w = (const float*)d_in[9];
    const float* sd1b = (const float*)d_in[10];
    const float* sd2w = (const float*)d_in[11];
    const float* sd2b = (const float*)d_in[12];
    const float* dww  = (const float*)d_in[13];
    const float* bn1g = (const float*)d_in[14];
    const float* bn1b = (const float*)d_in[15];
    const float* bn1m = (const float*)d_in[16];
    const float* bn1v = (const float*)d_in[17];
    const float* pww  = (const float*)d_in[18];
    const float* bn2g = (const float*)d_in[19];
    const float* bn2b = (const float*)d_in[20];
    const float* bn2m = (const float*)d_in[21];
    const float* bn2v = (const float*)d_in[22];
    float* out = (float*)d_out;

    float* buf = nullptr;
    cudaGetSymbolAddress((void**)&buf, g_buf);
    float* Q   = buf + 0 * BUFN;
    float* Kb  = buf + 1 * BUFN;
    float* Vb  = buf + 2 * BUFN;
    float* QKs = buf + 3 * BUFN;
    float* VS  = buf + 4 * BUFN;
    float* Y   = buf + 5 * BUFN;
    float* Y2  = buf + 6 * BUFN;

    const int ATTN_SMEM = 55296;
    cudaFuncSetAttribute(attn_mma_k, cudaFuncAttributeMaxDynamicSharedMemorySize, ATTN_SMEM);

    dim3 gg(PP / 64, CC / 128, BB);   // (49, 2, 2)
    const long bs = (long)CC * PP;

    // merged Q, K, V projections (tf32-rounded outputs)
    qkv_k<<<dim3(PP / 64, 6, BB), 256>>>(qw, qb, kw, kb, vw, vb, x, Q, Kb, Vb);

    // flash attention -> out channels [0,256)
    attn_mma_k<<<dim3(49, 16), 128, ATTN_SMEM>>>(Q, Kb, Vb, out);

    // Ks 3x3 conv (implicit GEMM), fused *Q -> QKs
    mm_k<3, true><<<gg, 256>>>(ksw, x, QKs, ksb, Q, nullptr, nullptr, nullptr, nullptr, bs, CC * 9);

    // gate = sigmoid(sd1(QKs)); VS = V * gate
    mm_k<1, false><<<gg, 256>>>(sd1w, QKs, VS, sd1b, Vb, nullptr, nullptr, nullptr, nullptr, bs, CC);

    // depthwise 3x3 + BN1 + leaky -> Y
    long total = (long)BB * CC * PP;
    dw_bn_lrelu_k<<<(int)((total + 255) / 256), 256>>>(VS, dww, bn1g, bn1b, bn1m, bn1v, Y);

    // pointwise pww + BN2 + leaky -> Y2
    mm_k<2, false><<<gg, 256>>>(pww, Y, Y2, nullptr, nullptr, bn2g, bn2b, bn2m, bn2v, bs, CC);

    // sd2 projection -> out channels [256,512)
    mm_k<0, false><<<gg, 256>>>(sd2w, Y2, out + (long)CC * PP, sd2b,
                                nullptr, nullptr, nullptr, nullptr, nullptr, (long)2 * CC * PP, CC);
}

// round 14
// speedup vs baseline: 2.8942x; 1.0012x over previous
// v8-resubmit-2 (R14): identical logic to R12/R13 submissions; re-bench after infra failures.
#include <cuda_runtime.h>
#include <math.h>

#define PP 3136
#define CC 256
#define BB 2
#define WX 56
#define EPS 1e-5f
#define SLOPE 0.01f

#define BUFN ((long)BB * CC * PP)
__device__ float g_buf[7 * BB * CC * PP];

// 4-stage pipelined GEMM smem: stage = A(128x20 f) + B(16x72 f) = 3712 floats
#define MM_STAGE_F 3712
#define MM_SMEM (4 * MM_STAGE_F * 4)   // 59392 bytes

__device__ __forceinline__ unsigned f2tf(float f) {
    unsigned u;
    asm("cvt.rna.tf32.f32 %0, %1;" : "=r"(u) : "f"(f));
    return u;
}
__device__ __forceinline__ float f2tff(float f) { return __uint_as_float(f2tf(f)); }

__device__ __forceinline__ float ex2f(float x) {
    float r;
    asm("ex2.approx.f32 %0, %1;" : "=f"(r) : "f"(x));
    return r;
}

__device__ __forceinline__ void mma8(float* c, const unsigned* a, unsigned b0, unsigned b1) {
    asm volatile(
        "mma.sync.aligned.m16n8k8.row.col.f32.tf32.tf32.f32 "
        "{%0,%1,%2,%3}, {%4,%5,%6,%7}, {%8,%9}, {%0,%1,%2,%3};"
        : "+f"(c[0]), "+f"(c[1]), "+f"(c[2]), "+f"(c[3])
        : "r"(a[0]), "r"(a[1]), "r"(a[2]), "r"(a[3]), "r"(b0), "r"(b1));
}

// ---------------------------------------------------------------------------
// Pipelined dense tf32 GEMM body (KK = 256 fixed, 16 slabs, 4-stage cp.async).
// out[b,o,p] = sum_c W[o,c]*X[b,c,p] (+epi). BM=128, BN=64, 256 threads.
// A staged raw fp32 row-major pitch 20 (conflict-free); B pitch 72.
// tf32 rounding applied at fragment load -> bit-identical to v7 numerics.
// MODE 0: +bias | 1: aux*sigmoid(+bias) | 2: BN+leaky | 4: +bias, tf32-rounded
// ---------------------------------------------------------------------------
template <int MODE>
__device__ __forceinline__ void mmp_body(
    const float* __restrict__ W, const float* __restrict__ X,
    float* __restrict__ out,
    const float* __restrict__ bias, const float* __restrict__ aux,
    const float* __restrict__ g, const float* __restrict__ bt,
    const float* __restrict__ mn, const float* __restrict__ vr,
    long outB, int b, int o0, int p0, float* sm)
{
    const float* Xb = X + (long)b * CC * PP;
    const int tid = threadIdx.x, lane = tid & 31, w = tid >> 5;
    const int wm = w & 3, wn = w >> 2;
    const int mw = wm * 32, nw = wn * 32;
    const int r = lane >> 2, cA = lane & 3;

    const int arow = tid >> 1, aoff = (tid & 1) * 8;
    const int brow = tid >> 4, boff = (tid & 15) * 4;

    auto issue_slab = [&](int s) {
        if (s < 16) {
            float* Asm = sm + (s & 3) * MM_STAGE_F;
            float* Bsm = Asm + 2560;
            const float* wsrc = W + (long)(o0 + arow) * CC + s * 16 + aoff;
            unsigned ad = (unsigned)__cvta_generic_to_shared(Asm + arow * 20 + aoff);
            asm volatile("cp.async.cg.shared.global [%0], [%1], 16;" :: "r"(ad), "l"(wsrc));
            asm volatile("cp.async.cg.shared.global [%0], [%1], 16;" :: "r"(ad + 16u), "l"(wsrc + 4));
            const float* xsrc = Xb + (long)(s * 16 + brow) * PP + p0 + boff;
            unsigned bd = (unsigned)__cvta_generic_to_shared(Bsm + brow * 72 + boff);
            asm volatile("cp.async.cg.shared.global [%0], [%1], 16;" :: "r"(bd), "l"(xsrc));
        }
        asm volatile("cp.async.commit_group;" ::: "memory");
    };

    issue_slab(0); issue_slab(1); issue_slab(2);

    float acc[2][4][4];
#pragma unroll
    for (int mt = 0; mt < 2; mt++)
#pragma unroll
        for (int nt = 0; nt < 4; nt++)
#pragma unroll
            for (int j = 0; j < 4; j++) acc[mt][nt][j] = 0.f;

    for (int s = 0; s < 16; s++) {
        asm volatile("cp.async.wait_group 2;" ::: "memory");
        __syncthreads();
        issue_slab(s + 3);   // empty commit past the end keeps group math uniform
        const float* Asm = sm + (s & 3) * MM_STAGE_F;
        const float* Bsm = Asm + 2560;
#pragma unroll
        for (int kc = 0; kc < 2; kc++) {
            unsigned af[2][4];
#pragma unroll
            for (int mt = 0; mt < 2; mt++) {
                int mb = mw + mt * 16 + r;
                af[mt][0] = f2tf(Asm[mb * 20 + kc * 8 + cA]);
                af[mt][1] = f2tf(Asm[(mb + 8) * 20 + kc * 8 + cA]);
                af[mt][2] = f2tf(Asm[mb * 20 + kc * 8 + cA + 4]);
                af[mt][3] = f2tf(Asm[(mb + 8) * 20 + kc * 8 + cA + 4]);
            }
#pragma unroll
            for (int nt = 0; nt < 4; nt++) {
                unsigned b0 = f2tf(Bsm[(kc * 8 + cA) * 72 + nw + nt * 8 + r]);
                unsigned b1 = f2tf(Bsm[(kc * 8 + cA + 4) * 72 + nw + nt * 8 + r]);
                mma8(acc[0][nt], af[0], b0, b1);
                mma8(acc[1][nt], af[1], b0, b1);
            }
        }
    }

#pragma unroll
    for (int mt = 0; mt < 2; mt++) {
        int o_lo = o0 + mw + mt * 16 + r;
        int o_hi = o_lo + 8;
        float bi_lo = 0.f, bi_hi = 0.f, sc_lo = 0.f, sc_hi = 0.f, sb_lo = 0.f, sb_hi = 0.f;
        if (MODE != 2) { bi_lo = bias[o_lo]; bi_hi = bias[o_hi]; }
        if (MODE == 2) {
            sc_lo = g[o_lo] * rsqrtf(vr[o_lo] + EPS); sb_lo = bt[o_lo] - mn[o_lo] * sc_lo;
            sc_hi = g[o_hi] * rsqrtf(vr[o_hi] + EPS); sb_hi = bt[o_hi] - mn[o_hi] * sc_hi;
        }
#pragma unroll
        for (int nt = 0; nt < 4; nt++) {
            int p = p0 + nw + nt * 8 + 2 * cA;
            long oi_lo = (long)b * outB + (long)o_lo * PP + p;
            long oi_hi = (long)b * outB + (long)o_hi * PP + p;
            float2 rl, rh;
            float a0 = acc[mt][nt][0], a1 = acc[mt][nt][1];
            float a2 = acc[mt][nt][2], a3 = acc[mt][nt][3];
            if (MODE == 0) {
                rl.x = a0 + bi_lo; rl.y = a1 + bi_lo;
                rh.x = a2 + bi_hi; rh.y = a3 + bi_hi;
            } else if (MODE == 4) {
                rl.x = f2tff(a0 + bi_lo); rl.y = f2tff(a1 + bi_lo);
                rh.x = f2tff(a2 + bi_hi); rh.y = f2tff(a3 + bi_hi);
            } else if (MODE == 1) {
                long ai_lo = (long)b * CC * PP + (long)o_lo * PP + p;
                long ai_hi = (long)b * CC * PP + (long)o_hi * PP + p;
                float2 vl = *(const float2*)(aux + ai_lo);
                float2 vh = *(const float2*)(aux + ai_hi);
                rl.x = vl.x / (1.f + __expf(-(a0 + bi_lo)));
                rl.y = vl.y / (1.f + __expf(-(a1 + bi_lo)));
                rh.x = vh.x / (1.f + __expf(-(a2 + bi_hi)));
                rh.y = vh.y / (1.f + __expf(-(a3 + bi_hi)));
            } else {
                float t0 = a0 * sc_lo + sb_lo, t1 = a1 * sc_lo + sb_lo;
                float t2 = a2 * sc_hi + sb_hi, t3 = a3 * sc_hi + sb_hi;
                rl.x = t0 > 0.f ? t0 : SLOPE * t0; rl.y = t1 > 0.f ? t1 : SLOPE * t1;
                rh.x = t2 > 0.f ? t2 : SLOPE * t2; rh.y = t3 > 0.f ? t3 : SLOPE * t3;
            }
            *(float2*)(out + oi_lo) = rl;
            *(float2*)(out + oi_hi) = rh;
        }
    }
}

template <int MODE>
__global__ void __launch_bounds__(256)
mmp_k(const float* __restrict__ W, const float* __restrict__ X,
      float* __restrict__ out,
      const float* __restrict__ bias, const float* __restrict__ aux,
      const float* __restrict__ g, const float* __restrict__ bt,
      const float* __restrict__ mn, const float* __restrict__ vr,
      long outB)
{
    extern __shared__ float sm[];
    mmp_body<MODE>(W, X, out, bias, aux, g, bt, mn, vr, outB,
                   blockIdx.z, blockIdx.y * 128, blockIdx.x * 64, sm);
}

// Merged Q/K/V projection (pipelined, MODE 4 tf32-rounded outputs).
__global__ void __launch_bounds__(256)
qkvp_k(const float* __restrict__ qw, const float* __restrict__ qb,
       const float* __restrict__ kw, const float* __restrict__ kb,
       const float* __restrict__ vw, const float* __restrict__ vb,
       const float* __restrict__ X,
       float* __restrict__ Q, float* __restrict__ Kb, float* __restrict__ Vb)
{
    extern __shared__ float sm[];
    const int y = blockIdx.y;
    const int sel = y >> 1;
    const float* W    = sel == 0 ? qw : (sel == 1 ? kw : vw);
    const float* bias = sel == 0 ? qb : (sel == 1 ? kb : vb);
    float* out        = sel == 0 ? Q  : (sel == 1 ? Kb : Vb);
    mmp_body<4>(W, X, out, bias, nullptr, nullptr, nullptr, nullptr, nullptr,
                (long)CC * PP, blockIdx.z, (y & 1) * 128, blockIdx.x * 64, sm);
}

// ---------------------------------------------------------------------------
// Conv GEMM (Ks 3x3, K=2304) — register double-buffered (unchanged from v7).
// Epilogue: out = (acc + ksb[o]) * Q.
// ---------------------------------------------------------------------------
__global__ void __launch_bounds__(256)
convmm_k(const float* __restrict__ W, const float* __restrict__ X,
         float* __restrict__ out, const float* __restrict__ bias,
         const float* __restrict__ aux)
{
    __shared__ float As[16][136];
    __shared__ float Bs[16][72];
    const int b = blockIdx.z, o0 = blockIdx.y * 128, p0 = blockIdx.x * 64;
    const int KK = CC * 9;
    const float* Xb = X + (long)b * CC * PP;
    const int tid = threadIdx.x, lane = tid & 31, w = tid >> 5;
    const int wm = w & 3, wn = w >> 2;
    const int mw = wm * 32, nw = wn * 32;
    const int r = lane >> 2, cA = lane & 3;

    float acc[2][4][4];
#pragma unroll
    for (int mt = 0; mt < 2; mt++)
#pragma unroll
        for (int nt = 0; nt < 4; nt++)
#pragma unroll
            for (int j = 0; j < 4; j++) acc[mt][nt][j] = 0.f;

    const int am = tid >> 1, akh = (tid & 1) * 8;
    const int bk = tid >> 4, bn0 = (tid & 15) * 4;

    float ast[8], bst[4];
    auto load_slab = [&](int k0) {
        const float* wp = W + (long)(o0 + am) * KK + k0 + akh;
        float4 wa = *(const float4*)(wp);
        float4 wb = *(const float4*)(wp + 4);
        ast[0] = f2tff(wa.x); ast[1] = f2tff(wa.y);
        ast[2] = f2tff(wa.z); ast[3] = f2tff(wa.w);
        ast[4] = f2tff(wb.x); ast[5] = f2tff(wb.y);
        ast[6] = f2tff(wb.z); ast[7] = f2tff(wb.w);
        int kk = k0 + bk;
        int c = kk / 9, t = kk - c * 9;
        int dy = t / 3 - 1, dx = t - (t / 3) * 3 - 1;
        const float* Xc = Xb + (long)c * PP;
#pragma unroll
        for (int q = 0; q < 4; q++) {
            int p = p0 + bn0 + q;
            int y = p / WX, x = p - y * WX;
            int yy = y + dy, xx = x + dx;
            float v = 0.f;
            if ((unsigned)yy < WX && (unsigned)xx < WX)
                v = Xc[yy * WX + xx];
            bst[q] = f2tff(v);
        }
    };

    load_slab(0);
    for (int k0 = 0; k0 < KK; k0 += 16) {
        __syncthreads();
        As[akh + 0][am] = ast[0]; As[akh + 1][am] = ast[1];
        As[akh + 2][am] = ast[2]; As[akh + 3][am] = ast[3];
        As[akh + 4][am] = ast[4]; As[akh + 5][am] = ast[5];
        As[akh + 6][am] = ast[6]; As[akh + 7][am] = ast[7];
        *(float4*)&Bs[bk][bn0] = make_float4(bst[0], bst[1], bst[2], bst[3]);
        __syncthreads();
        if (k0 + 16 < KK) load_slab(k0 + 16);
#pragma unroll
        for (int kc = 0; kc < 2; kc++) {
            unsigned af[2][4];
#pragma unroll
            for (int mt = 0; mt < 2; mt++) {
                af[mt][0] = __float_as_uint(As[kc * 8 + cA][mw + mt * 16 + r]);
                af[mt][1] = __float_as_uint(As[kc * 8 + cA][mw + mt * 16 + r + 8]);
                af[mt][2] = __float_as_uint(As[kc * 8 + cA + 4][mw + mt * 16 + r]);
                af[mt][3] = __float_as_uint(As[kc * 8 + cA + 4][mw + mt * 16 + r + 8]);
            }
#pragma unroll
            for (int nt = 0; nt < 4; nt++) {
                unsigned b0 = __float_as_uint(Bs[kc * 8 + cA][nw + nt * 8 + r]);
                unsigned b1 = __float_as_uint(Bs[kc * 8 + cA + 4][nw + nt * 8 + r]);
                mma8(acc[0][nt], af[0], b0, b1);
                mma8(acc[1][nt], af[1], b0, b1);
            }
        }
    }

#pragma unroll
    for (int mt = 0; mt < 2; mt++) {
        int o_lo = o0 + mw + mt * 16 + r;
        int o_hi = o_lo + 8;
        float bi_lo = bias[o_lo], bi_hi = bias[o_hi];
#pragma unroll
        for (int nt = 0; nt < 4; nt++) {
            int p = p0 + nw + nt * 8 + 2 * cA;
            long oi_lo = (long)b * CC * PP + (long)o_lo * PP + p;
            long oi_hi = (long)b * CC * PP + (long)o_hi * PP + p;
            float2 ql = *(const float2*)(aux + oi_lo);
            float2 qh = *(const float2*)(aux + oi_hi);
            float2 rl, rh;
            rl.x = (acc[mt][nt][0] + bi_lo) * ql.x; rl.y = (acc[mt][nt][1] + bi_lo) * ql.y;
            rh.x = (acc[mt][nt][2] + bi_hi) * qh.x; rh.y = (acc[mt][nt][3] + bi_hi) * qh.y;
            *(float2*)(out + oi_lo) = rl;
            *(float2*)(out + oi_hi) = rh;
        }
    }
}

// ---------------------------------------------------------------------------
// Flash attention v7 (unchanged): cp.async double-buffered K/V, base-2 softmax,
// deferred l, paired P smem. Dynamic smem 55296 B.
// ---------------------------------------------------------------------------
__global__ void __launch_bounds__(128)
attn_mma_k(const float* __restrict__ Q, const float* __restrict__ K,
           const float* __restrict__ V, float* __restrict__ out)
{
    extern __shared__ float dsm[];
    float* KB0 = dsm;
    float* KB1 = dsm + 2304;
    float* VB0 = dsm + 4608;
    float* VB1 = dsm + 6912;
    float* Ppool = dsm + 9216;

    const int tid = threadIdx.x, lane = tid & 31, w = tid >> 5;
    const int bh = blockIdx.y;
    const int b = bh >> 3, h = bh & 7;
    const long base = ((long)b * CC + h * 32) * PP;
    const float* qp = Q + base;
    const float* kp = K + base;
    const float* vp = V + base;
    const int q0 = blockIdx.x * 64;
    const float SC = 0.17677669529663687f * 1.4426950408889634f;

    const int ld_d = tid >> 4, ld_k4 = (tid & 15) * 4;

    auto issue_tile = [&](int kb, float* Kd, float* Vd) {
#pragma unroll
        for (int j = 0; j < 4; j++) {
            int d = ld_d + j * 8;
            unsigned ks = (unsigned)__cvta_generic_to_shared(Kd + d * 72 + ld_k4);
            unsigned vs = (unsigned)__cvta_generic_to_shared(Vd + d * 72 + ld_k4);
            const float* kg = kp + (long)d * PP + kb + ld_k4;
            const float* vg = vp + (long)d * PP + kb + ld_k4;
            asm volatile("cp.async.ca.shared.global [%0], [%1], 16;" :: "r"(ks), "l"(kg));
            asm volatile("cp.async.ca.shared.global [%0], [%1], 16;" :: "r"(vs), "l"(vg));
        }
        asm volatile("cp.async.commit_group;" ::: "memory");
    };

    issue_tile(0, KB0, VB0);

    float* Qs = Ppool;
    for (int i = tid; i < 512; i += 128) {
        int d = i >> 4, q4 = (i & 15) * 4;
        float4 v4 = *(const float4*)(qp + (long)d * PP + q0 + q4);
        Qs[(q4 + 0) * 36 + d] = f2tff(v4.x * SC);
        Qs[(q4 + 1) * 36 + d] = f2tff(v4.y * SC);
        Qs[(q4 + 2) * 36 + d] = f2tff(v4.z * SC);
        Qs[(q4 + 3) * 36 + d] = f2tff(v4.w * SC);
    }
    __syncthreads();

    unsigned af[4][4];
    {
        int rr = w * 16 + (lane >> 2);
        int c = lane & 3;
#pragma unroll
        for (int kc = 0; kc < 4; kc++) {
            af[kc][0] = __float_as_uint(Qs[rr * 36 + kc * 8 + c]);
            af[kc][1] = __float_as_uint(Qs[(rr + 8) * 36 + kc * 8 + c]);
            af[kc][2] = __float_as_uint(Qs[rr * 36 + kc * 8 + c + 4]);
            af[kc][3] = __float_as_uint(Qs[(rr + 8) * 36 + kc * 8 + c + 4]);
        }
    }

    float m0 = -1e30f, m1 = -1e30f, l0 = 0.f, l1 = 0.f;
    float o[4][4];
#pragma unroll
    for (int nt = 0; nt < 4; nt++)
#pragma unroll
        for (int j = 0; j < 4; j++) o[nt][j] = 0.f;

    float* Pw = Ppool + w * 16 * 72;
    const int lq = lane >> 2;
    const int lr = lane & 3;
    const int cbase = 2 * ((2 * lr) & 3) + (lr >> 1);

    for (int kt = 0; kt < 49; kt++) {
        asm volatile("cp.async.wait_group 0;" ::: "memory");
        __syncthreads();
        if (kt < 48) {
            int nb = (kt + 1) & 1;
            issue_tile((kt + 1) * 64, nb ? KB1 : KB0, nb ? VB1 : VB0);
        }
        const float* Ksb = (kt & 1) ? KB1 : KB0;
        const float* Vsb = (kt & 1) ? VB1 : VB0;

        float s[8][4];
#pragma unroll
        for (int nt = 0; nt < 8; nt++)
#pragma unroll
            for (int j = 0; j < 4; j++) s[nt][j] = 0.f;
#pragma unroll
        for (int kc = 0; kc < 4; kc++) {
#pragma unroll
            for (int nt = 0; nt < 8; nt++) {
                unsigned b0 = __float_as_uint(Ksb[(kc * 8 + lr) * 72 + nt * 8 + lq]);
                unsigned b1 = __float_as_uint(Ksb[(kc * 8 + lr + 4) * 72 + nt * 8 + lq]);
                mma8(s[nt], af[kc], b0, b1);
            }
        }

        float mx0 = s[0][0], mx1 = s[0][2];
#pragma unroll
        for (int nt = 0; nt < 8; nt++) {
            mx0 = fmaxf(mx0, fmaxf(s[nt][0], s[nt][1]));
            mx1 = fmaxf(mx1, fmaxf(s[nt][2], s[nt][3]));
        }
        mx0 = fmaxf(mx0, __shfl_xor_sync(0xffffffffu, mx0, 1));
        mx0 = fmaxf(mx0, __shfl_xor_sync(0xffffffffu, mx0, 2));
        mx1 = fmaxf(mx1, __shfl_xor_sync(0xffffffffu, mx1, 1));
        mx1 = fmaxf(mx1, __shfl_xor_sync(0xffffffffu, mx1, 2));
        float nm0 = fmaxf(m0, mx0), nm1 = fmaxf(m1, mx1);
        float a0 = ex2f(m0 - nm0), a1 = ex2f(m1 - nm1);
        m0 = nm0; m1 = nm1;

        float ps0 = 0.f, ps1 = 0.f;
#pragma unroll
        for (int nt = 0; nt < 8; nt++) {
            s[nt][0] = ex2f(s[nt][0] - m0); ps0 += s[nt][0];
            s[nt][1] = ex2f(s[nt][1] - m0); ps0 += s[nt][1];
            s[nt][2] = ex2f(s[nt][2] - m1); ps1 += s[nt][2];
            s[nt][3] = ex2f(s[nt][3] - m1); ps1 += s[nt][3];
        }
        l0 = l0 * a0 + ps0;
        l1 = l1 * a1 + ps1;
#pragma unroll
        for (int nt = 0; nt < 4; nt++) {
            o[nt][0] *= a0; o[nt][1] *= a0;
            o[nt][2] *= a1; o[nt][3] *= a1;
        }

        __syncwarp();
#pragma unroll
        for (int nt = 0; nt < 8; nt++) {
            float* pr = Pw + lq * 72 + nt * 8 + cbase;
            pr[0] = f2tff(s[nt][0]);
            pr[2] = f2tff(s[nt][1]);
            float* pr2 = pr + 8 * 72;
            pr2[0] = f2tff(s[nt][2]);
            pr2[2] = f2tff(s[nt][3]);
        }
        __syncwarp();

#pragma unroll
        for (int kc = 0; kc < 8; kc++) {
            unsigned pa[4];
            float2 plo = *(const float2*)(Pw + lq * 72 + kc * 8 + 2 * lr);
            float2 phi = *(const float2*)(Pw + (lq + 8) * 72 + kc * 8 + 2 * lr);
            pa[0] = __float_as_uint(plo.x); pa[1] = __float_as_uint(phi.x);
            pa[2] = __float_as_uint(plo.y); pa[3] = __float_as_uint(phi.y);
#pragma unroll
            for (int nt = 0; nt < 4; nt++) {
                unsigned b0 = __float_as_uint(Vsb[(nt * 8 + lq) * 72 + kc * 8 + lr]);
                unsigned b1 = __float_as_uint(Vsb[(nt * 8 + lq) * 72 + kc * 8 + lr + 4]);
                mma8(o[nt], pa, b0, b1);
            }
        }
    }

    l0 += __shfl_xor_sync(0xffffffffu, l0, 1);
    l0 += __shfl_xor_sync(0xffffffffu, l0, 2);
    l1 += __shfl_xor_sync(0xffffffffu, l1, 1);
    l1 += __shfl_xor_sync(0xffffffffu, l1, 2);

    float inv0 = 1.f / l0, inv1 = 1.f / l1;
    float* op = out + (long)b * (2 * CC * PP) + (long)(h * 32) * PP;
    int qr = q0 + w * 16 + lq;
#pragma unroll
    for (int nt = 0; nt < 4; nt++) {
        int d = nt * 8 + lr * 2;
        op[(long)d * PP + qr]           = o[nt][0] * inv0;
        op[(long)(d + 1) * PP + qr]     = o[nt][1] * inv0;
        op[(long)d * PP + qr + 8]       = o[nt][2] * inv1;
        op[(long)(d + 1) * PP + qr + 8] = o[nt][3] * inv1;
    }
}

// ---------------------------------------------------------------------------
// Depthwise 3x3 conv + BN1 + leaky ReLU (elementwise).
// ---------------------------------------------------------------------------
__global__ void __launch_bounds__(256)
dw_bn_lrelu_k(const float* __restrict__ in, const float* __restrict__ w9,
              const float* __restrict__ g, const float* __restrict__ bt,
              const float* __restrict__ mn, const float* __restrict__ vv,
              float* __restrict__ out)
{
    long idx = (long)blockIdx.x * 256 + threadIdx.x;
    if (idx >= (long)BB * CC * PP) return;
    int p = (int)(idx % PP);
    int c = (int)((idx / PP) % CC);
    int y = p / WX, x = p - y * WX;
    const float* ip = in + (idx - p);
    const float* wc = w9 + c * 9;
    float s = 0.f;
#pragma unroll
    for (int dy = -1; dy <= 1; dy++) {
        int yy = y + dy;
        if ((unsigned)yy >= WX) continue;
#pragma unroll
        for (int dx = -1; dx <= 1; dx++) {
            int xx = x + dx;
            if ((unsigned)xx >= WX) continue;
            s += wc[(dy + 1) * 3 + (dx + 1)] * ip[yy * WX + xx];
        }
    }
    float sc = g[c] * rsqrtf(vv[c] + EPS);
    float t = (s - mn[c]) * sc + bt[c];
    out[idx] = t > 0.f ? t : SLOPE * t;
}

// ---------------------------------------------------------------------------
extern "C" void kernel_launch(void* const* d_in, const int* in_sizes, int n_in,
                              void* d_out, int out_size)
{
    (void)in_sizes; (void)n_in; (void)out_size;
    const float* x    = (const float*)d_in[0];
    const float* qw   = (const float*)d_in[1];
    const float* qb   = (const float*)d_in[2];
    const float* kw   = (const float*)d_in[3];
    const float* kb   = (const float*)d_in[4];
    const float* vw   = (const float*)d_in[5];
    const float* vb   = (const float*)d_in[6];
    const float* ksw  = (const float*)d_in[7];
    const float* ksb  = (const float*)d_in[8];
    const float* sd1w = (const float*)d_in[9];
    const float* sd1b = (const float*)d_in[10];
    const float* sd2w = (const float*)d_in[11];
    const float* sd2b = (const float*)d_in[12];
    const float* dww  = (const float*)d_in[13];
    const float* bn1g = (const float*)d_in[14];
    const float* bn1b = (const float*)d_in[15];
    const float* bn1m = (const float*)d_in[16];
    const float* bn1v = (const float*)d_in[17];
    const float* pww  = (const float*)d_in[18];
    const float* bn2g = (const float*)d_in[19];
    const float* bn2b = (const float*)d_in[20];
    const float* bn2m = (const float*)d_in[21];
    const float* bn2v = (const float*)d_in[22];
    float* out = (float*)d_out;

    float* buf = nullptr;
    cudaGetSymbolAddress((void**)&buf, g_buf);
    float* Q   = buf + 0 * BUFN;
    float* Kb  = buf + 1 * BUFN;
    float* Vb  = buf + 2 * BUFN;
    float* QKs = buf + 3 * BUFN;
    float* VS  = buf + 4 * BUFN;
    float* Y   = buf + 5 * BUFN;
    float* Y2  = buf + 6 * BUFN;

    const int ATTN_SMEM = 55296;
    cudaFuncSetAttribute(attn_mma_k, cudaFuncAttributeMaxDynamicSharedMemorySize, ATTN_SMEM);
    cudaFuncSetAttribute(qkvp_k,  cudaFuncAttributeMaxDynamicSharedMemorySize, MM_SMEM);
    cudaFuncSetAttribute(mmp_k<0>, cudaFuncAttributeMaxDynamicSharedMemorySize, MM_SMEM);
    cudaFuncSetAttribute(mmp_k<1>, cudaFuncAttributeMaxDynamicSharedMemorySize, MM_SMEM);
    cudaFuncSetAttribute(mmp_k<2>, cudaFuncAttributeMaxDynamicSharedMemorySize, MM_SMEM);

    dim3 gg(PP / 64, CC / 128, BB);   // (49, 2, 2)
    const long bs = (long)CC * PP;

    // merged Q, K, V projections (pipelined, tf32-rounded outputs)
    qkvp_k<<<dim3(PP / 64, 6, BB), 256, MM_SMEM>>>(qw, qb, kw, kb, vw, vb, x, Q, Kb, Vb);

    // flash attention -> out channels [0,256)
    attn_mma_k<<<dim3(49, 16), 128, ATTN_SMEM>>>(Q, Kb, Vb, out);

    // Ks 3x3 conv (implicit GEMM, register-staged), fused *Q -> QKs
    convmm_k<<<gg, 256>>>(ksw, x, QKs, ksb, Q);

    // gate = sigmoid(sd1(QKs)); VS = V * gate
    mmp_k<1><<<gg, 256, MM_SMEM>>>(sd1w, QKs, VS, sd1b, Vb, nullptr, nullptr, nullptr, nullptr, bs);

    // depthwise 3x3 + BN1 + leaky -> Y
    long total = (long)BB * CC * PP;
    dw_bn_lrelu_k<<<(int)((total + 255) / 256), 256>>>(VS, dww, bn1g, bn1b, bn1m, bn1v, Y);

    // pointwise pww + BN2 + leaky -> Y2
    mmp_k<2><<<gg, 256, MM_SMEM>>>(pww, Y, Y2, nullptr, nullptr, bn2g, bn2b, bn2m, bn2v, bs);

    // sd2 projection -> out channels [256,512)
    mmp_k<0><<<gg, 256, MM_SMEM>>>(sd2w, Y2, out + (long)CC * PP, sd2b,
                                   nullptr, nullptr, nullptr, nullptr, nullptr, (long)2 * CC * PP);
}

// round 16
// speedup vs baseline: 3.0635x; 1.0585x over previous
// v9-resubmit (R16): identical logic to R15 submission; re-bench after infra failure.
#include <cuda_runtime.h>
#include <math.h>

#define PP 3136
#define CC 256
#define BB 2
#define WX 56
#define EPS 1e-5f
#define SLOPE 0.01f

#define BUFN ((long)BB * CC * PP)
__device__ float g_buf[7 * BB * CC * PP];

#define MM_STAGE_F 3712
#define MM_SMEM (4 * MM_STAGE_F * 4)   // 59392 bytes
#define FUSED_SMEM 55296

__device__ __forceinline__ unsigned f2tf(float f) {
    unsigned u;
    asm("cvt.rna.tf32.f32 %0, %1;" : "=r"(u) : "f"(f));
    return u;
}
__device__ __forceinline__ float f2tff(float f) { return __uint_as_float(f2tf(f)); }

__device__ __forceinline__ float ex2f(float x) {
    float r;
    asm("ex2.approx.f32 %0, %1;" : "=f"(r) : "f"(x));
    return r;
}

__device__ __forceinline__ void mma8(float* c, const unsigned* a, unsigned b0, unsigned b1) {
    asm volatile(
        "mma.sync.aligned.m16n8k8.row.col.f32.tf32.tf32.f32 "
        "{%0,%1,%2,%3}, {%4,%5,%6,%7}, {%8,%9}, {%0,%1,%2,%3};"
        : "+f"(c[0]), "+f"(c[1]), "+f"(c[2]), "+f"(c[3])
        : "r"(a[0]), "r"(a[1]), "r"(a[2]), "r"(a[3]), "r"(b0), "r"(b1));
}

// ---------------------------------------------------------------------------
// Attention unit (device fn): 64 queries for one (b,h), 4 warps (128 thr).
// cp.async double-buffered K/V, base-2 softmax, deferred l, paired P smem.
// Uses 55296 B of dsm.
// ---------------------------------------------------------------------------
__device__ __forceinline__ void attn_body(
    const float* __restrict__ Q, const float* __restrict__ K,
    const float* __restrict__ V, float* __restrict__ out,
    int q0, int b, int h, float* dsm)
{
    float* KB0 = dsm;
    float* KB1 = dsm + 2304;
    float* VB0 = dsm + 4608;
    float* VB1 = dsm + 6912;
    float* Ppool = dsm + 9216;

    const int tid = threadIdx.x, lane = tid & 31, w = tid >> 5;
    const long base = ((long)b * CC + h * 32) * PP;
    const float* qp = Q + base;
    const float* kp = K + base;
    const float* vp = V + base;
    const float SC = 0.17677669529663687f * 1.4426950408889634f;

    const int ld_d = tid >> 4, ld_k4 = (tid & 15) * 4;

    auto issue_tile = [&](int kb, float* Kd, float* Vd) {
#pragma unroll
        for (int j = 0; j < 4; j++) {
            int d = ld_d + j * 8;
            unsigned ks = (unsigned)__cvta_generic_to_shared(Kd + d * 72 + ld_k4);
            unsigned vs = (unsigned)__cvta_generic_to_shared(Vd + d * 72 + ld_k4);
            const float* kg = kp + (long)d * PP + kb + ld_k4;
            const float* vg = vp + (long)d * PP + kb + ld_k4;
            asm volatile("cp.async.ca.shared.global [%0], [%1], 16;" :: "r"(ks), "l"(kg));
            asm volatile("cp.async.ca.shared.global [%0], [%1], 16;" :: "r"(vs), "l"(vg));
        }
        asm volatile("cp.async.commit_group;" ::: "memory");
    };

    issue_tile(0, KB0, VB0);

    float* Qs = Ppool;
    for (int i = tid; i < 512; i += 128) {
        int d = i >> 4, q4 = (i & 15) * 4;
        float4 v4 = *(const float4*)(qp + (long)d * PP + q0 + q4);
        Qs[(q4 + 0) * 36 + d] = f2tff(v4.x * SC);
        Qs[(q4 + 1) * 36 + d] = f2tff(v4.y * SC);
        Qs[(q4 + 2) * 36 + d] = f2tff(v4.z * SC);
        Qs[(q4 + 3) * 36 + d] = f2tff(v4.w * SC);
    }
    __syncthreads();

    unsigned af[4][4];
    {
        int rr = w * 16 + (lane >> 2);
        int c = lane & 3;
#pragma unroll
        for (int kc = 0; kc < 4; kc++) {
            af[kc][0] = __float_as_uint(Qs[rr * 36 + kc * 8 + c]);
            af[kc][1] = __float_as_uint(Qs[(rr + 8) * 36 + kc * 8 + c]);
            af[kc][2] = __float_as_uint(Qs[rr * 36 + kc * 8 + c + 4]);
            af[kc][3] = __float_as_uint(Qs[(rr + 8) * 36 + kc * 8 + c + 4]);
        }
    }

    float m0 = -1e30f, m1 = -1e30f, l0 = 0.f, l1 = 0.f;
    float o[4][4];
#pragma unroll
    for (int nt = 0; nt < 4; nt++)
#pragma unroll
        for (int j = 0; j < 4; j++) o[nt][j] = 0.f;

    float* Pw = Ppool + w * 16 * 72;
    const int lq = lane >> 2;
    const int lr = lane & 3;
    const int cbase = 2 * ((2 * lr) & 3) + (lr >> 1);

    for (int kt = 0; kt < 49; kt++) {
        asm volatile("cp.async.wait_group 0;" ::: "memory");
        __syncthreads();
        if (kt < 48) {
            int nb = (kt + 1) & 1;
            issue_tile((kt + 1) * 64, nb ? KB1 : KB0, nb ? VB1 : VB0);
        }
        const float* Ksb = (kt & 1) ? KB1 : KB0;
        const float* Vsb = (kt & 1) ? VB1 : VB0;

        float s[8][4];
#pragma unroll
        for (int nt = 0; nt < 8; nt++)
#pragma unroll
            for (int j = 0; j < 4; j++) s[nt][j] = 0.f;
#pragma unroll
        for (int kc = 0; kc < 4; kc++) {
#pragma unroll
            for (int nt = 0; nt < 8; nt++) {
                unsigned b0 = __float_as_uint(Ksb[(kc * 8 + lr) * 72 + nt * 8 + lq]);
                unsigned b1 = __float_as_uint(Ksb[(kc * 8 + lr + 4) * 72 + nt * 8 + lq]);
                mma8(s[nt], af[kc], b0, b1);
            }
        }

        float mx0 = s[0][0], mx1 = s[0][2];
#pragma unroll
        for (int nt = 0; nt < 8; nt++) {
            mx0 = fmaxf(mx0, fmaxf(s[nt][0], s[nt][1]));
            mx1 = fmaxf(mx1, fmaxf(s[nt][2], s[nt][3]));
        }
        mx0 = fmaxf(mx0, __shfl_xor_sync(0xffffffffu, mx0, 1));
        mx0 = fmaxf(mx0, __shfl_xor_sync(0xffffffffu, mx0, 2));
        mx1 = fmaxf(mx1, __shfl_xor_sync(0xffffffffu, mx1, 1));
        mx1 = fmaxf(mx1, __shfl_xor_sync(0xffffffffu, mx1, 2));
        float nm0 = fmaxf(m0, mx0), nm1 = fmaxf(m1, mx1);
        float a0 = ex2f(m0 - nm0), a1 = ex2f(m1 - nm1);
        m0 = nm0; m1 = nm1;

        float ps0 = 0.f, ps1 = 0.f;
#pragma unroll
        for (int nt = 0; nt < 8; nt++) {
            s[nt][0] = ex2f(s[nt][0] - m0); ps0 += s[nt][0];
            s[nt][1] = ex2f(s[nt][1] - m0); ps0 += s[nt][1];
            s[nt][2] = ex2f(s[nt][2] - m1); ps1 += s[nt][2];
            s[nt][3] = ex2f(s[nt][3] - m1); ps1 += s[nt][3];
        }
        l0 = l0 * a0 + ps0;
        l1 = l1 * a1 + ps1;
#pragma unroll
        for (int nt = 0; nt < 4; nt++) {
            o[nt][0] *= a0; o[nt][1] *= a0;
            o[nt][2] *= a1; o[nt][3] *= a1;
        }

        __syncwarp();
#pragma unroll
        for (int nt = 0; nt < 8; nt++) {
            float* pr = Pw + lq * 72 + nt * 8 + cbase;
            pr[0] = f2tff(s[nt][0]);
            pr[2] = f2tff(s[nt][1]);
            float* pr2 = pr + 8 * 72;
            pr2[0] = f2tff(s[nt][2]);
            pr2[2] = f2tff(s[nt][3]);
        }
        __syncwarp();

#pragma unroll
        for (int kc = 0; kc < 8; kc++) {
            unsigned pa[4];
            float2 plo = *(const float2*)(Pw + lq * 72 + kc * 8 + 2 * lr);
            float2 phi = *(const float2*)(Pw + (lq + 8) * 72 + kc * 8 + 2 * lr);
            pa[0] = __float_as_uint(plo.x); pa[1] = __float_as_uint(phi.x);
            pa[2] = __float_as_uint(plo.y); pa[3] = __float_as_uint(phi.y);
#pragma unroll
            for (int nt = 0; nt < 4; nt++) {
                unsigned b0 = __float_as_uint(Vsb[(nt * 8 + lq) * 72 + kc * 8 + lr]);
                unsigned b1 = __float_as_uint(Vsb[(nt * 8 + lq) * 72 + kc * 8 + lr + 4]);
                mma8(o[nt], pa, b0, b1);
            }
        }
    }

    l0 += __shfl_xor_sync(0xffffffffu, l0, 1);
    l0 += __shfl_xor_sync(0xffffffffu, l0, 2);
    l1 += __shfl_xor_sync(0xffffffffu, l1, 1);
    l1 += __shfl_xor_sync(0xffffffffu, l1, 2);

    float inv0 = 1.f / l0, inv1 = 1.f / l1;
    float* op = out + (long)b * (2 * CC * PP) + (long)(h * 32) * PP;
    int qr = q0 + w * 16 + lq;
#pragma unroll
    for (int nt = 0; nt < 4; nt++) {
        int d = nt * 8 + lr * 2;
        op[(long)d * PP + qr]           = o[nt][0] * inv0;
        op[(long)(d + 1) * PP + qr]     = o[nt][1] * inv0;
        op[(long)d * PP + qr + 8]       = o[nt][2] * inv1;
        op[(long)(d + 1) * PP + qr + 8] = o[nt][3] * inv1;
    }
}

// ---------------------------------------------------------------------------
// Conv unit (device fn): Ks 3x3 implicit GEMM, BM=64, BN=64, 128 threads
// (4 warps in 2x2), register double-buffered, K=2304 (same k order as before
// -> bit-identical sums). Epilogue: out = (acc + bias[o]) * Qbuf.
// Uses 9216 B of dsm.
// ---------------------------------------------------------------------------
__device__ __forceinline__ void conv64_body(
    const float* __restrict__ W, const float* __restrict__ X,
    float* __restrict__ out, const float* __restrict__ bias,
    const float* __restrict__ aux, int b, int o0, int p0, float* dsm)
{
    float* As = dsm;             // [16][72] k-major
    float* Bs = dsm + 16 * 72;   // [16][72]
    const int KK = CC * 9;
    const float* Xb = X + (long)b * CC * PP;
    const int tid = threadIdx.x, lane = tid & 31, w = tid >> 5;
    const int mw = (w & 1) * 32, nw = (w >> 1) * 32;
    const int r = lane >> 2, cA = lane & 3;

    float acc[2][4][4];
#pragma unroll
    for (int mt = 0; mt < 2; mt++)
#pragma unroll
        for (int nt = 0; nt < 4; nt++)
#pragma unroll
            for (int j = 0; j < 4; j++) acc[mt][nt][j] = 0.f;

    const int arow = tid >> 1, aoff = (tid & 1) * 8;   // A: 64 rows x 16 k
    const int brow = tid >> 3, bn0 = (tid & 7) * 8;    // B: 16 k x 64 n

    float ast[8], bst[8];
    auto load_slab = [&](int k0) {
        const float* wp = W + (long)(o0 + arow) * KK + k0 + aoff;
        float4 wa = *(const float4*)(wp);
        float4 wb = *(const float4*)(wp + 4);
        ast[0] = f2tff(wa.x); ast[1] = f2tff(wa.y);
        ast[2] = f2tff(wa.z); ast[3] = f2tff(wa.w);
        ast[4] = f2tff(wb.x); ast[5] = f2tff(wb.y);
        ast[6] = f2tff(wb.z); ast[7] = f2tff(wb.w);
        int kk = k0 + brow;
        int c = kk / 9, t = kk - c * 9;
        int dy = t / 3 - 1, dx = t - (t / 3) * 3 - 1;
        const float* Xc = Xb + (long)c * PP;
#pragma unroll
        for (int q = 0; q < 8; q++) {
            int p = p0 + bn0 + q;
            int y = p / WX, x = p - y * WX;
            int yy = y + dy, xx = x + dx;
            float v = 0.f;
            if ((unsigned)yy < WX && (unsigned)xx < WX)
                v = Xc[yy * WX + xx];
            bst[q] = f2tff(v);
        }
    };

    load_slab(0);
    for (int k0 = 0; k0 < KK; k0 += 16) {
        __syncthreads();
#pragma unroll
        for (int j = 0; j < 8; j++) As[(aoff + j) * 72 + arow] = ast[j];
#pragma unroll
        for (int q = 0; q < 8; q++) Bs[brow * 72 + bn0 + q] = bst[q];
        __syncthreads();
        if (k0 + 16 < KK) load_slab(k0 + 16);
#pragma unroll
        for (int kc = 0; kc < 2; kc++) {
            unsigned af[2][4];
#pragma unroll
            for (int mt = 0; mt < 2; mt++) {
                int mb = mw + mt * 16 + r;
                af[mt][0] = __float_as_uint(As[(kc * 8 + cA) * 72 + mb]);
                af[mt][1] = __float_as_uint(As[(kc * 8 + cA) * 72 + mb + 8]);
                af[mt][2] = __float_as_uint(As[(kc * 8 + cA + 4) * 72 + mb]);
                af[mt][3] = __float_as_uint(As[(kc * 8 + cA + 4) * 72 + mb + 8]);
            }
#pragma unroll
            for (int nt = 0; nt < 4; nt++) {
                unsigned b0 = __float_as_uint(Bs[(kc * 8 + cA) * 72 + nw + nt * 8 + r]);
                unsigned b1 = __float_as_uint(Bs[(kc * 8 + cA + 4) * 72 + nw + nt * 8 + r]);
                mma8(acc[0][nt], af[0], b0, b1);
                mma8(acc[1][nt], af[1], b0, b1);
            }
        }
    }

#pragma unroll
    for (int mt = 0; mt < 2; mt++) {
        int o_lo = o0 + mw + mt * 16 + r;
        int o_hi = o_lo + 8;
        float bi_lo = bias[o_lo], bi_hi = bias[o_hi];
#pragma unroll
        for (int nt = 0; nt < 4; nt++) {
            int p = p0 + nw + nt * 8 + 2 * cA;
            long oi_lo = (long)b * CC * PP + (long)o_lo * PP + p;
            long oi_hi = (long)b * CC * PP + (long)o_hi * PP + p;
            float2 ql = *(const float2*)(aux + oi_lo);
            float2 qh = *(const float2*)(aux + oi_hi);
            float2 rl, rh;
            rl.x = (acc[mt][nt][0] + bi_lo) * ql.x; rl.y = (acc[mt][nt][1] + bi_lo) * ql.y;
            rh.x = (acc[mt][nt][2] + bi_hi) * qh.x; rh.y = (acc[mt][nt][3] + bi_hi) * qh.y;
            *(float2*)(out + oi_lo) = rl;
            *(float2*)(out + oi_hi) = rh;
        }
    }
}

// ---------------------------------------------------------------------------
// Fused mega-kernel: 1176 blocks x 128 threads.
// bx%3 in {0,1} -> attention unit (784 total); bx%3==2 -> conv block (392).
// ---------------------------------------------------------------------------
__global__ void __launch_bounds__(128)
fused_attn_conv_k(const float* __restrict__ Q, const float* __restrict__ K,
                  const float* __restrict__ V, float* __restrict__ out,
                  const float* __restrict__ ksw, const float* __restrict__ x,
                  const float* __restrict__ ksb, float* __restrict__ QKs)
{
    extern __shared__ float dsm[];
    const int bx = blockIdx.x;
    const int mod = bx % 3;
    if (mod < 2) {
        int ai = (bx / 3) * 2 + mod;        // 0..783
        int qtile = ai % 49, bh = ai / 49;
        attn_body(Q, K, V, out, qtile * 64, bh >> 3, bh & 7, dsm);
    } else {
        int ci = bx / 3;                    // 0..391
        int ptile = ci % 49;
        int rest = ci / 49;
        int otile = rest & 3, b = rest >> 2;
        conv64_body(ksw, x, QKs, ksb, Q, b, otile * 64, ptile * 64, dsm);
    }
}

// ---------------------------------------------------------------------------
// Pipelined dense tf32 GEMM (unchanged from v8).
// MODE 0: +bias | 1: aux*sigmoid(+bias) | 2: BN+leaky | 4: +bias tf32-rounded
// ---------------------------------------------------------------------------
template <int MODE>
__device__ __forceinline__ void mmp_body(
    const float* __restrict__ W, const float* __restrict__ X,
    float* __restrict__ out,
    const float* __restrict__ bias, const float* __restrict__ aux,
    const float* __restrict__ g, const float* __restrict__ bt,
    const float* __restrict__ mn, const float* __restrict__ vr,
    long outB, int b, int o0, int p0, float* sm)
{
    const float* Xb = X + (long)b * CC * PP;
    const int tid = threadIdx.x, lane = tid & 31, w = tid >> 5;
    const int wm = w & 3, wn = w >> 2;
    const int mw = wm * 32, nw = wn * 32;
    const int r = lane >> 2, cA = lane & 3;

    const int arow = tid >> 1, aoff = (tid & 1) * 8;
    const int brow = tid >> 4, boff = (tid & 15) * 4;

    auto issue_slab = [&](int s) {
        if (s < 16) {
            float* Asm = sm + (s & 3) * MM_STAGE_F;
            float* Bsm = Asm + 2560;
            const float* wsrc = W + (long)(o0 + arow) * CC + s * 16 + aoff;
            unsigned ad = (unsigned)__cvta_generic_to_shared(Asm + arow * 20 + aoff);
            asm volatile("cp.async.cg.shared.global [%0], [%1], 16;" :: "r"(ad), "l"(wsrc));
            asm volatile("cp.async.cg.shared.global [%0], [%1], 16;" :: "r"(ad + 16u), "l"(wsrc + 4));
            const float* xsrc = Xb + (long)(s * 16 + brow) * PP + p0 + boff;
            unsigned bd = (unsigned)__cvta_generic_to_shared(Bsm + brow * 72 + boff);
            asm volatile("cp.async.cg.shared.global [%0], [%1], 16;" :: "r"(bd), "l"(xsrc));
        }
        asm volatile("cp.async.commit_group;" ::: "memory");
    };

    issue_slab(0); issue_slab(1); issue_slab(2);

    float acc[2][4][4];
#pragma unroll
    for (int mt = 0; mt < 2; mt++)
#pragma unroll
        for (int nt = 0; nt < 4; nt++)
#pragma unroll
            for (int j = 0; j < 4; j++) acc[mt][nt][j] = 0.f;

    for (int s = 0; s < 16; s++) {
        asm volatile("cp.async.wait_group 2;" ::: "memory");
        __syncthreads();
        issue_slab(s + 3);
        const float* Asm = sm + (s & 3) * MM_STAGE_F;
        const float* Bsm = Asm + 2560;
#pragma unroll
        for (int kc = 0; kc < 2; kc++) {
            unsigned af[2][4];
#pragma unroll
            for (int mt = 0; mt < 2; mt++) {
                int mb = mw + mt * 16 + r;
                af[mt][0] = f2tf(Asm[mb * 20 + kc * 8 + cA]);
                af[mt][1] = f2tf(Asm[(mb + 8) * 20 + kc * 8 + cA]);
                af[mt][2] = f2tf(Asm[mb * 20 + kc * 8 + cA + 4]);
                af[mt][3] = f2tf(Asm[(mb + 8) * 20 + kc * 8 + cA + 4]);
            }
#pragma unroll
            for (int nt = 0; nt < 4; nt++) {
                unsigned b0 = f2tf(Bsm[(kc * 8 + cA) * 72 + nw + nt * 8 + r]);
                unsigned b1 = f2tf(Bsm[(kc * 8 + cA + 4) * 72 + nw + nt * 8 + r]);
                mma8(acc[0][nt], af[0], b0, b1);
                mma8(acc[1][nt], af[1], b0, b1);
            }
        }
    }

#pragma unroll
    for (int mt = 0; mt < 2; mt++) {
        int o_lo = o0 + mw + mt * 16 + r;
        int o_hi = o_lo + 8;
        float bi_lo = 0.f, bi_hi = 0.f, sc_lo = 0.f, sc_hi = 0.f, sb_lo = 0.f, sb_hi = 0.f;
        if (MODE != 2) { bi_lo = bias[o_lo]; bi_hi = bias[o_hi]; }
        if (MODE == 2) {
            sc_lo = g[o_lo] * rsqrtf(vr[o_lo] + EPS); sb_lo = bt[o_lo] - mn[o_lo] * sc_lo;
            sc_hi = g[o_hi] * rsqrtf(vr[o_hi] + EPS); sb_hi = bt[o_hi] - mn[o_hi] * sc_hi;
        }
#pragma unroll
        for (int nt = 0; nt < 4; nt++) {
            int p = p0 + nw + nt * 8 + 2 * cA;
            long oi_lo = (long)b * outB + (long)o_lo * PP + p;
            long oi_hi = (long)b * outB + (long)o_hi * PP + p;
            float2 rl, rh;
            float a0 = acc[mt][nt][0], a1 = acc[mt][nt][1];
            float a2 = acc[mt][nt][2], a3 = acc[mt][nt][3];
            if (MODE == 0) {
                rl.x = a0 + bi_lo; rl.y = a1 + bi_lo;
                rh.x = a2 + bi_hi; rh.y = a3 + bi_hi;
            } else if (MODE == 4) {
                rl.x = f2tff(a0 + bi_lo); rl.y = f2tff(a1 + bi_lo);
                rh.x = f2tff(a2 + bi_hi); rh.y = f2tff(a3 + bi_hi);
            } else if (MODE == 1) {
                long ai_lo = (long)b * CC * PP + (long)o_lo * PP + p;
                long ai_hi = (long)b * CC * PP + (long)o_hi * PP + p;
                float2 vl = *(const float2*)(aux + ai_lo);
                float2 vh = *(const float2*)(aux + ai_hi);
                rl.x = vl.x / (1.f + __expf(-(a0 + bi_lo)));
                rl.y = vl.y / (1.f + __expf(-(a1 + bi_lo)));
                rh.x = vh.x / (1.f + __expf(-(a2 + bi_hi)));
                rh.y = vh.y / (1.f + __expf(-(a3 + bi_hi)));
            } else {
                float t0 = a0 * sc_lo + sb_lo, t1 = a1 * sc_lo + sb_lo;
                float t2 = a2 * sc_hi + sb_hi, t3 = a3 * sc_hi + sb_hi;
                rl.x = t0 > 0.f ? t0 : SLOPE * t0; rl.y = t1 > 0.f ? t1 : SLOPE * t1;
                rh.x = t2 > 0.f ? t2 : SLOPE * t2; rh.y = t3 > 0.f ? t3 : SLOPE * t3;
            }
            *(float2*)(out + oi_lo) = rl;
            *(float2*)(out + oi_hi) = rh;
        }
    }
}

template <int MODE>
__global__ void __launch_bounds__(256)
mmp_k(const float* __restrict__ W, const float* __restrict__ X,
      float* __restrict__ out,
      const float* __restrict__ bias, const float* __restrict__ aux,
      const float* __restrict__ g, const float* __restrict__ bt,
      const float* __restrict__ mn, const float* __restrict__ vr,
      long outB)
{
    extern __shared__ float sm[];
    mmp_body<MODE>(W, X, out, bias, aux, g, bt, mn, vr, outB,
                   blockIdx.z, blockIdx.y * 128, blockIdx.x * 64, sm);
}

// Merged Q/K/V projection (pipelined, MODE 4 tf32-rounded outputs).
__global__ void __launch_bounds__(256)
qkvp_k(const float* __restrict__ qw, const float* __restrict__ qb,
       const float* __restrict__ kw, const float* __restrict__ kb,
       const float* __restrict__ vw, const float* __restrict__ vb,
       const float* __restrict__ X,
       float* __restrict__ Q, float* __restrict__ Kb, float* __restrict__ Vb)
{
    extern __shared__ float sm[];
    const int y = blockIdx.y;
    const int sel = y >> 1;
    const float* W    = sel == 0 ? qw : (sel == 1 ? kw : vw);
    const float* bias = sel == 0 ? qb : (sel == 1 ? kb : vb);
    float* out        = sel == 0 ? Q  : (sel == 1 ? Kb : Vb);
    mmp_body<4>(W, X, out, bias, nullptr, nullptr, nullptr, nullptr, nullptr,
                (long)CC * PP, blockIdx.z, (y & 1) * 128, blockIdx.x * 64, sm);
}

// ---------------------------------------------------------------------------
// Depthwise 3x3 conv + BN1 + leaky ReLU (elementwise).
// ---------------------------------------------------------------------------
__global__ void __launch_bounds__(256)
dw_bn_lrelu_k(const float* __restrict__ in, const float* __restrict__ w9,
              const float* __restrict__ g, const float* __restrict__ bt,
              const float* __restrict__ mn, const float* __restrict__ vv,
              float* __restrict__ out)
{
    long idx = (long)blockIdx.x * 256 + threadIdx.x;
    if (idx >= (long)BB * CC * PP) return;
    int p = (int)(idx % PP);
    int c = (int)((idx / PP) % CC);
    int y = p / WX, x = p - y * WX;
    const float* ip = in + (idx - p);
    const float* wc = w9 + c * 9;
    float s = 0.f;
#pragma unroll
    for (int dy = -1; dy <= 1; dy++) {
        int yy = y + dy;
        if ((unsigned)yy >= WX) continue;
#pragma unroll
        for (int dx = -1; dx <= 1; dx++) {
            int xx = x + dx;
            if ((unsigned)xx >= WX) continue;
            s += wc[(dy + 1) * 3 + (dx + 1)] * ip[yy * WX + xx];
        }
    }
    float sc = g[c] * rsqrtf(vv[c] + EPS);
    float t = (s - mn[c]) * sc + bt[c];
    out[idx] = t > 0.f ? t : SLOPE * t;
}

// ---------------------------------------------------------------------------
extern "C" void kernel_launch(void* const* d_in, const int* in_sizes, int n_in,
                              void* d_out, int out_size)
{
    (void)in_sizes; (void)n_in; (void)out_size;
    const float* x    = (const float*)d_in[0];
    const float* qw   = (const float*)d_in[1];
    const float* qb   = (const float*)d_in[2];
    const float* kw   = (const float*)d_in[3];
    const float* kb   = (const float*)d_in[4];
    const float* vw   = (const float*)d_in[5];
    const float* vb   = (const float*)d_in[6];
    const float* ksw  = (const float*)d_in[7];
    const float* ksb  = (const float*)d_in[8];
    const float* sd1w = (const float*)d_in[9];
    const float* sd1b = (const float*)d_in[10];
    const float* sd2w = (const float*)d_in[11];
    const float* sd2b = (const float*)d_in[12];
    const float* dww  = (const float*)d_in[13];
    const float* bn1g = (const float*)d_in[14];
    const float* bn1b = (const float*)d_in[15];
    const float* bn1m = (const float*)d_in[16];
    const float* bn1v = (const float*)d_in[17];
    const float* pww  = (const float*)d_in[18];
    const float* bn2g = (const float*)d_in[19];
    const float* bn2b = (const float*)d_in[20];
    const float* bn2m = (const float*)d_in[21];
    const float* bn2v = (const float*)d_in[22];
    float* out = (float*)d_out;

    float* buf = nullptr;
    cudaGetSymbolAddress((void**)&buf, g_buf);
    float* Q   = buf + 0 * BUFN;
    float* Kb  = buf + 1 * BUFN;
    float* Vb  = buf + 2 * BUFN;
    float* QKs = buf + 3 * BUFN;
    float* VS  = buf + 4 * BUFN;
    float* Y   = buf + 5 * BUFN;
    float* Y2  = buf + 6 * BUFN;

    cudaFuncSetAttribute(fused_attn_conv_k, cudaFuncAttributeMaxDynamicSharedMemorySize, FUSED_SMEM);
    cudaFuncSetAttribute(qkvp_k,  cudaFuncAttributeMaxDynamicSharedMemorySize, MM_SMEM);
    cudaFuncSetAttribute(mmp_k<0>, cudaFuncAttributeMaxDynamicSharedMemorySize, MM_SMEM);
    cudaFuncSetAttribute(mmp_k<1>, cudaFuncAttributeMaxDynamicSharedMemorySize, MM_SMEM);
    cudaFuncSetAttribute(mmp_k<2>, cudaFuncAttributeMaxDynamicSharedMemorySize, MM_SMEM);

    dim3 gg(PP / 64, CC / 128, BB);   // (49, 2, 2)
    const long bs = (long)CC * PP;

    // merged Q, K, V projections (pipelined, tf32-rounded outputs)
    qkvp_k<<<dim3(PP / 64, 6, BB), 256, MM_SMEM>>>(qw, qb, kw, kb, vw, vb, x, Q, Kb, Vb);

    // fused: flash attention (-> out[:, :256]) overlapped with Ks conv (-> QKs)
    fused_attn_conv_k<<<1176, 128, FUSED_SMEM>>>(Q, Kb, Vb, out, ksw, x, ksb, QKs);

    // gate = sigmoid(sd1(QKs)); VS = V * gate
    mmp_k<1><<<gg, 256, MM_SMEM>>>(sd1w, QKs, VS, sd1b, Vb, nullptr, nullptr, nullptr, nullptr, bs);

    // depthwise 3x3 + BN1 + leaky -> Y
    long total = (long)BB * CC * PP;
    dw_bn_lrelu_k<<<(int)((total + 255) / 256), 256>>>(VS, dww, bn1g, bn1b, bn1m, bn1v, Y);

    // pointwise pww + BN2 + leaky -> Y2
    mmp_k<2><<<gg, 256, MM_SMEM>>>(pww, Y, Y2, nullptr, nullptr, bn2g, bn2b, bn2m, bn2v, bs);

    // sd2 projection -> out channels [256,512)
    mmp_k<0><<<gg, 256, MM_SMEM>>>(sd2w, Y2, out + (long)CC * PP, sd2b,
                                   nullptr, nullptr, nullptr, nullptr, nullptr, (long)2 * CC * PP);
}